// round 1
// baseline (speedup 1.0000x reference)
#include <cuda_runtime.h>
#include <math.h>

#define NN 32768
#define EE 524288
#define HH 128
#define BB 2048
#define LL 7
#define NF 10

// ---------------- device scratch (no allocation allowed) ----------------
__device__ int   g_is64;
__device__ float g_x[NN * HH];
__device__ float g_x2[NN * HH];
__device__ float g_agg[NN * HH];
__device__ float g_head[NN * 30];

// smem layout (floats): Hs[128*129] | As[128*33] | Ws[32*128]
#define HS_E (128 * 129)
#define AS_E (128 * 33)
#define WS_E (32 * 128)
#define SMEM_BYTES ((HS_E + AS_E + WS_E) * 4)

__device__ __forceinline__ int load_idx(const void* p, long long i) {
    if (g_is64) return (int)((const long long*)p)[i];
    return ((const int*)p)[i];
}

// Detect int64 vs int32 edge_index: indices are nonneg < 2^31, so if stored as
// little-endian int64 every odd 32-bit word is 0. For int32 random indices the
// probability of 128 consecutive zeros is ~0.
__global__ void detect_kernel(const int* e) {
    if (threadIdx.x == 0) {
        int is64 = 1;
        for (int i = 1; i < 256; i += 2)
            if (e[i] != 0) { is64 = 0; break; }
        g_is64 = is64;
    }
}

// 32-deep K-chunk microkernel: acc[8][8] += As(128 x 32, pitch ap) * Ws(32 x 128)
__device__ __forceinline__ void mm_chunk(const float* As, int ap, const float* Ws,
                                         int ty, int tx, float acc[8][8]) {
#pragma unroll
    for (int k = 0; k < 32; k++) {
        float a[8], b[8];
#pragma unroll
        for (int i = 0; i < 8; i++) a[i] = As[(ty * 8 + i) * ap + k];
#pragma unroll
        for (int j = 0; j < 8; j++) b[j] = Ws[k * 128 + tx * 8 + j];
#pragma unroll
        for (int i = 0; i < 8; i++)
#pragma unroll
            for (int j = 0; j < 8; j++) acc[i][j] += a[i] * b[j];
    }
}

// ---------------- edge message MLP + scatter-add ----------------
// per block: 128 edges. hidden = relu(cat(x[dst],x[src]) @ W1 + b1)
// out = hidden @ W2 + b2 ; atomicAdd into agg[dst]
__global__ void edge_kernel(const float* __restrict__ x, const void* __restrict__ eidx,
                            const float* __restrict__ W1, const float* __restrict__ b1,
                            const float* __restrict__ W2, const float* __restrict__ b2,
                            float* __restrict__ agg) {
    extern __shared__ float sm[];
    float* Hs = sm;
    float* As = sm + HS_E;
    float* Ws = sm + HS_E + AS_E;
    __shared__ int s_src[128], s_dst[128];

    int tid = threadIdx.x;
    long long e0 = (long long)blockIdx.x * 128;
    for (int i = tid; i < 128; i += 256) {
        s_src[i] = load_idx(eidx, e0 + i);
        s_dst[i] = load_idx(eidx, (long long)EE + e0 + i);
    }
    __syncthreads();

    int tx = tid & 15, ty = tid >> 4;
    float acc[8][8];
#pragma unroll
    for (int i = 0; i < 8; i++)
#pragma unroll
        for (int j = 0; j < 8; j++) acc[i][j] = 0.f;

    for (int kc = 0; kc < 256; kc += 32) {
        for (int t = tid; t < 128 * 32; t += 256) {
            int r = t >> 5, c = t & 31;
            int k = kc + c;
            int node = (k < 128) ? s_dst[r] : s_src[r];
            As[r * 33 + c] = x[(long long)node * HH + (k & 127)];
        }
        for (int t = tid; t < 32 * 128; t += 256) {
            int r = t >> 7, c = t & 127;
            Ws[t] = W1[(kc + r) * HH + c];
        }
        __syncthreads();
        mm_chunk(As, 33, Ws, ty, tx, acc);
        __syncthreads();
    }
#pragma unroll
    for (int i = 0; i < 8; i++)
#pragma unroll
        for (int j = 0; j < 8; j++) {
            float v = acc[i][j] + b1[tx * 8 + j];
            Hs[(ty * 8 + i) * 129 + tx * 8 + j] = v > 0.f ? v : 0.f;
            acc[i][j] = 0.f;
        }
    __syncthreads();
    for (int kc = 0; kc < 128; kc += 32) {
        for (int t = tid; t < 32 * 128; t += 256) {
            int r = t >> 7, c = t & 127;
            Ws[t] = W2[(kc + r) * HH + c];
        }
        __syncthreads();
        mm_chunk(Hs + kc, 129, Ws, ty, tx, acc);
        __syncthreads();
    }
#pragma unroll
    for (int i = 0; i < 8; i++) {
        int d = s_dst[ty * 8 + i];
#pragma unroll
        for (int j = 0; j < 8; j++) {
            atomicAdd(&agg[(long long)d * HH + tx * 8 + j], acc[i][j] + b2[tx * 8 + j]);
        }
    }
}

// ---------------- node update MLP ----------------
// x2 = relu(cat(x, agg) @ W1 + b1) @ W2 + b2
__global__ void upd_kernel(const float* __restrict__ x, const float* __restrict__ agg,
                           const float* __restrict__ W1, const float* __restrict__ b1,
                           const float* __restrict__ W2, const float* __restrict__ b2,
                           float* __restrict__ x2) {
    extern __shared__ float sm[];
    float* Hs = sm;
    float* As = sm + HS_E;
    float* Ws = sm + HS_E + AS_E;

    int tid = threadIdx.x;
    int n0 = blockIdx.x * 128;
    int tx = tid & 15, ty = tid >> 4;
    float acc[8][8];
#pragma unroll
    for (int i = 0; i < 8; i++)
#pragma unroll
        for (int j = 0; j < 8; j++) acc[i][j] = 0.f;

    for (int kc = 0; kc < 256; kc += 32) {
        for (int t = tid; t < 128 * 32; t += 256) {
            int r = t >> 5, c = t & 31;
            int k = kc + c;
            const float* src = (k < 128) ? x : agg;
            As[r * 33 + c] = src[(long long)(n0 + r) * HH + (k & 127)];
        }
        for (int t = tid; t < 32 * 128; t += 256) {
            int r = t >> 7, c = t & 127;
            Ws[t] = W1[(kc + r) * HH + c];
        }
        __syncthreads();
        mm_chunk(As, 33, Ws, ty, tx, acc);
        __syncthreads();
    }
#pragma unroll
    for (int i = 0; i < 8; i++)
#pragma unroll
        for (int j = 0; j < 8; j++) {
            float v = acc[i][j] + b1[tx * 8 + j];
            Hs[(ty * 8 + i) * 129 + tx * 8 + j] = v > 0.f ? v : 0.f;
            acc[i][j] = 0.f;
        }
    __syncthreads();
    for (int kc = 0; kc < 128; kc += 32) {
        for (int t = tid; t < 32 * 128; t += 256) {
            int r = t >> 7, c = t & 127;
            Ws[t] = W2[(kc + r) * HH + c];
        }
        __syncthreads();
        mm_chunk(Hs + kc, 129, Ws, ty, tx, acc);
        __syncthreads();
    }
#pragma unroll
    for (int i = 0; i < 8; i++)
#pragma unroll
        for (int j = 0; j < 8; j++)
            x2[(long long)(n0 + ty * 8 + i) * HH + tx * 8 + j] = acc[i][j] + b2[tx * 8 + j];
}

// ---------------- embedder ----------------
// in: concat(loc, vel) per frame -> (N, 60) ; out: x (N,128) = relu(in@W1+b1)@W2+b2
__global__ void embed_kernel(const float* __restrict__ loc, const float* __restrict__ vel,
                             const float* __restrict__ W1, const float* __restrict__ b1,
                             const float* __restrict__ W2, const float* __restrict__ b2,
                             float* __restrict__ xout) {
    extern __shared__ float sm[];
    float* Hs = sm;
    float* As = sm + HS_E;
    float* Ws = sm + HS_E + AS_E;

    int tid = threadIdx.x;
    int n0 = blockIdx.x * 128;
    int tx = tid & 15, ty = tid >> 4;
    float acc[8][8];
#pragma unroll
    for (int i = 0; i < 8; i++)
#pragma unroll
        for (int j = 0; j < 8; j++) acc[i][j] = 0.f;

    // K1 padded to 64 (true K1 = 60)
    for (int kc = 0; kc < 64; kc += 32) {
        for (int t = tid; t < 128 * 32; t += 256) {
            int r = t >> 5, c = t & 31;
            int k = kc + c;
            float v = 0.f;
            if (k < 60) {
                int f = k / 6, c6 = k % 6;
                int base = (n0 + r) * 30 + f * 3;
                v = (c6 < 3) ? loc[base + c6] : vel[base + c6 - 3];
            }
            As[r * 33 + c] = v;
        }
        for (int t = tid; t < 32 * 128; t += 256) {
            int r = t >> 7, c = t & 127;
            int k = kc + r;
            Ws[t] = (k < 60) ? W1[k * HH + c] : 0.f;
        }
        __syncthreads();
        mm_chunk(As, 33, Ws, ty, tx, acc);
        __syncthreads();
    }
#pragma unroll
    for (int i = 0; i < 8; i++)
#pragma unroll
        for (int j = 0; j < 8; j++) {
            float v = acc[i][j] + b1[tx * 8 + j];
            Hs[(ty * 8 + i) * 129 + tx * 8 + j] = v > 0.f ? v : 0.f;
            acc[i][j] = 0.f;
        }
    __syncthreads();
    for (int kc = 0; kc < 128; kc += 32) {
        for (int t = tid; t < 32 * 128; t += 256) {
            int r = t >> 7, c = t & 127;
            Ws[t] = W2[(kc + r) * HH + c];
        }
        __syncthreads();
        mm_chunk(Hs + kc, 129, Ws, ty, tx, acc);
        __syncthreads();
    }
#pragma unroll
    for (int i = 0; i < 8; i++)
#pragma unroll
        for (int j = 0; j < 8; j++)
            xout[(long long)(n0 + ty * 8 + i) * HH + tx * 8 + j] = acc[i][j] + b2[tx * 8 + j];
}

// ---------------- head ----------------
// hout(N,30) = relu(x @ W1 + b1) @ W2(128,30) + b2
__global__ void head_kernel(const float* __restrict__ x,
                            const float* __restrict__ W1, const float* __restrict__ b1,
                            const float* __restrict__ W2, const float* __restrict__ b2,
                            float* __restrict__ hout) {
    extern __shared__ float sm[];
    float* Hs = sm;
    float* Wh = sm + HS_E;          // 128*30 floats, fits in As region
    float* Ws = sm + HS_E + AS_E;

    int tid = threadIdx.x;
    int n0 = blockIdx.x * 128;
    int tx = tid & 15, ty = tid >> 4;
    float acc[8][8];
#pragma unroll
    for (int i = 0; i < 8; i++)
#pragma unroll
        for (int j = 0; j < 8; j++) acc[i][j] = 0.f;

    for (int kc = 0; kc < 128; kc += 32) {
        for (int t = tid; t < 32 * 128; t += 256) {
            int r = t >> 7, c = t & 127;
            Ws[t] = W1[(kc + r) * HH + c];
        }
        __syncthreads();
        // A tile directly from x, staged through Ws? No: read from global in a temp As-like way.
        // Instead reuse the chunk micro with a staged tile in Wh space is too small; stage in-place:
        __syncthreads();
        // stage A chunk into the tail of smem? Simplest: read x into registers via Hs as staging.
        // We stage A chunk into Hs columns temporarily is unsafe (Hs used later), so do direct:
#pragma unroll
        for (int k = 0; k < 32; k++) {
            float a[8], b[8];
#pragma unroll
            for (int i = 0; i < 8; i++)
                a[i] = x[(long long)(n0 + ty * 8 + i) * HH + kc + k];
#pragma unroll
            for (int j = 0; j < 8; j++) b[j] = Ws[k * 128 + tx * 8 + j];
#pragma unroll
            for (int i = 0; i < 8; i++)
#pragma unroll
                for (int j = 0; j < 8; j++) acc[i][j] += a[i] * b[j];
        }
        __syncthreads();
    }
#pragma unroll
    for (int i = 0; i < 8; i++)
#pragma unroll
        for (int j = 0; j < 8; j++) {
            float v = acc[i][j] + b1[tx * 8 + j];
            Hs[(ty * 8 + i) * 129 + tx * 8 + j] = v > 0.f ? v : 0.f;
        }
    // load W2 (128 x 30)
    for (int t = tid; t < 128 * 30; t += 256) Wh[t] = W2[t];
    __syncthreads();
    for (int t = tid; t < 128 * 30; t += 256) {
        int row = t / 30, c = t % 30;
        float s = b2[c];
        const float* hr = Hs + row * 129;
#pragma unroll 8
        for (int k = 0; k < 128; k++) s += hr[k] * Wh[k * 30 + c];
        hout[(long long)(n0 + row) * 30 + c] = s;
    }
}

// ---------------- loss ----------------
__global__ void loss_kernel(const float* __restrict__ hout, const float* __restrict__ loc,
                            const float* __restrict__ y, float* __restrict__ out) {
    int w = (blockIdx.x * blockDim.x + threadIdx.x) >> 5;
    int lane = threadIdx.x & 31;
    if (w >= BB) return;
    float ade = 0.f, fde = 0.f;
    for (int p = lane; p < 160; p += 32) {
        int node = w * 16 + p / NF;
        int f = p % NF;
        int base = node * 30 + f * 3;
        float dx = hout[base] + loc[base] - y[base];
        float dy = hout[base + 1] + loc[base + 1] - y[base + 1];
        float dz = hout[base + 2] + loc[base + 2] - y[base + 2];
        float d = sqrtf(dx * dx + dy * dy + dz * dz);
        ade += d;
        if (f == NF - 1) fde += d;
    }
#pragma unroll
    for (int o = 16; o; o >>= 1) {
        ade += __shfl_down_sync(0xffffffffu, ade, o);
        fde += __shfl_down_sync(0xffffffffu, fde, o);
    }
    if (lane == 0) {
        out[1 + w] = ade / 160.f;
        out[1 + BB + w] = fde / 16.f;
    }
}

__global__ void final_kernel(float* __restrict__ out) {
    __shared__ float s[256];
    float v = 0.f;
    for (int i = threadIdx.x; i < BB; i += 256) v += out[1 + i];
    s[threadIdx.x] = v;
    __syncthreads();
    for (int o = 128; o; o >>= 1) {
        if (threadIdx.x < o) s[threadIdx.x] += s[threadIdx.x + o];
        __syncthreads();
    }
    if (threadIdx.x == 0) out[0] = s[0] / (float)BB;
}

// ---------------- host ----------------
extern "C" void kernel_launch(void* const* d_in, const int* in_sizes, int n_in,
                              void* d_out, int out_size) {
    // input ordering per setup_inputs(); batch_size may or may not be present
    int o = (n_in > 4 && in_sizes[4] == 1) ? 1 : 0;
    const float* loc = (const float*)d_in[0];
    const float* vel = (const float*)d_in[1];
    const float* y   = (const float*)d_in[2];
    const void*  eix = d_in[3];
    const float* embW1 = (const float*)d_in[4 + o];
    const float* embb1 = (const float*)d_in[5 + o];
    const float* embW2 = (const float*)d_in[6 + o];
    const float* embb2 = (const float*)d_in[7 + o];
    const float* msgW1 = (const float*)d_in[8 + o];
    const float* msgb1 = (const float*)d_in[9 + o];
    const float* msgW2 = (const float*)d_in[10 + o];
    const float* msgb2 = (const float*)d_in[11 + o];
    const float* updW1 = (const float*)d_in[12 + o];
    const float* updb1 = (const float*)d_in[13 + o];
    const float* updW2 = (const float*)d_in[14 + o];
    const float* updb2 = (const float*)d_in[15 + o];
    const float* hW1 = (const float*)d_in[16 + o];
    const float* hb1 = (const float*)d_in[17 + o];
    const float* hW2 = (const float*)d_in[18 + o];
    const float* hb2 = (const float*)d_in[19 + o];
    float* out = (float*)d_out;

    cudaFuncSetAttribute(edge_kernel, cudaFuncAttributeMaxDynamicSharedMemorySize, SMEM_BYTES);
    cudaFuncSetAttribute(upd_kernel, cudaFuncAttributeMaxDynamicSharedMemorySize, SMEM_BYTES);
    cudaFuncSetAttribute(embed_kernel, cudaFuncAttributeMaxDynamicSharedMemorySize, SMEM_BYTES);
    cudaFuncSetAttribute(head_kernel, cudaFuncAttributeMaxDynamicSharedMemorySize, SMEM_BYTES);

    float *xp, *x2p, *aggp, *headp;
    cudaGetSymbolAddress((void**)&xp, g_x);
    cudaGetSymbolAddress((void**)&x2p, g_x2);
    cudaGetSymbolAddress((void**)&aggp, g_agg);
    cudaGetSymbolAddress((void**)&headp, g_head);

    detect_kernel<<<1, 32>>>((const int*)eix);
    embed_kernel<<<NN / 128, 256, SMEM_BYTES>>>(loc, vel, embW1, embb1, embW2, embb2, xp);

    float* xa = xp;
    float* xb = x2p;
    for (int i = 0; i < LL; i++) {
        cudaMemsetAsync(aggp, 0, (size_t)NN * HH * sizeof(float));
        edge_kernel<<<EE / 128, 256, SMEM_BYTES>>>(
            xa, eix,
            msgW1 + (size_t)i * 2 * HH * HH, msgb1 + (size_t)i * HH,
            msgW2 + (size_t)i * HH * HH, msgb2 + (size_t)i * HH, aggp);
        upd_kernel<<<NN / 128, 256, SMEM_BYTES>>>(
            xa, aggp,
            updW1 + (size_t)i * 2 * HH * HH, updb1 + (size_t)i * HH,
            updW2 + (size_t)i * HH * HH, updb2 + (size_t)i * HH, xb);
        float* t = xa; xa = xb; xb = t;
    }
    head_kernel<<<NN / 128, 256, SMEM_BYTES>>>(xa, hW1, hb1, hW2, hb2, headp);
    loss_kernel<<<(BB * 32 + 127) / 128, 128>>>(headp, loc, y, out);
    final_kernel<<<1, 256>>>(out);
}

// round 3
// speedup vs baseline: 3.4595x; 3.4595x over previous
#include <cuda_runtime.h>
#include <cuda_fp16.h>
#include <math.h>
#include <stdint.h>

#define NN 32768
#define EE 524288
#define HH 128
#define BB 2048
#define LL 7
#define NF 10

// ---------------------------------------------------------------------------
// device scratch
// ---------------------------------------------------------------------------
__device__ int    g_is64;
__device__ __half g_xh[NN * HH];
__device__ __half g_xh2[NN * HH];
__device__ float  g_agg[NN * HH];
__device__ float  g_head[NN * 30];
// n-major fp16 weight images: W1t [n=128][k=256] pitch 264 halfs; W2t [128][128] pitch 136
__device__ __half g_mW1i[LL * 128 * 264];
__device__ __half g_mW2i[LL * 128 * 136];
__device__ __half g_uW1i[LL * 128 * 264];
__device__ __half g_uW2i[LL * 128 * 136];

// pitches in halfs
#define PA 264   // K=256 + 8 pad  (row stride 528 B -> 16B bank rotation)
#define PB 136   // K=128 + 8 pad  (272 B)

// smem layout (bytes)
#define SA_OFF   0
#define SW1_OFF  (128 * PA * 2)                  // 67584
#define SH_OFF   (SW1_OFF + 128 * PA * 2)        // 135168
#define SW2_OFF  (SH_OFF + 128 * PB * 2)         // 169984
#define SB1_OFF  (SW2_OFF + 128 * PB * 2)        // 204800
#define SB2_OFF  (SB1_OFF + 512)
#define SDST_OFF (SB2_OFF + 512)
#define DYNB     (SDST_OFF + 512)

__device__ __forceinline__ uint32_t smem_u32(const void* p) {
    uint32_t a;
    asm("{ .reg .u64 t; cvta.to.shared.u64 t, %1; cvt.u32.u64 %0, t; }" : "=r"(a) : "l"(p));
    return a;
}

__device__ __forceinline__ void ldsm_x4(uint32_t r[4], uint32_t addr) {
    asm volatile("ldmatrix.sync.aligned.m8n8.x4.shared.b16 {%0,%1,%2,%3}, [%4];"
                 : "=r"(r[0]), "=r"(r[1]), "=r"(r[2]), "=r"(r[3]) : "r"(addr));
}

__device__ __forceinline__ void mma16816(float c[4], const uint32_t a[4],
                                         uint32_t b0, uint32_t b1) {
    asm volatile(
        "mma.sync.aligned.m16n8k16.row.col.f32.f16.f16.f32 "
        "{%0,%1,%2,%3},{%4,%5,%6,%7},{%8,%9},{%0,%1,%2,%3};"
        : "+f"(c[0]), "+f"(c[1]), "+f"(c[2]), "+f"(c[3])
        : "r"(a[0]), "r"(a[1]), "r"(a[2]), "r"(a[3]), "r"(b0), "r"(b1));
}

__device__ __forceinline__ int load_idx(const void* p, long long i) {
    if (g_is64) return (int)((const long long*)p)[i];
    return ((const int*)p)[i];
}

__global__ void detect_kernel(const int* e) {
    if (threadIdx.x == 0) {
        int is64 = 1;
        for (int i = 1; i < 256; i += 2)
            if (e[i] != 0) { is64 = 0; break; }
        g_is64 = is64;
    }
}

// ---------------------------------------------------------------------------
// weight prep: fp32 [k][n] -> fp16 n-major [n][k] padded
// ---------------------------------------------------------------------------
__global__ void prep_w1(const float* msg, const float* upd) {
    int b = blockIdx.x;           // l*2 + which
    int l = b >> 1, which = b & 1;
    const float* src = (which ? upd : msg) + (size_t)l * 256 * HH;
    __half* dst = (which ? g_uW1i : g_mW1i) + (size_t)l * 128 * PA;
    for (int i = threadIdx.x; i < 128 * 256; i += blockDim.x) {
        int n = i & 127, k = i >> 7;
        dst[n * PA + k] = __float2half(src[k * HH + n]);
    }
}
__global__ void prep_w2(const float* msg, const float* upd) {
    int b = blockIdx.x;
    int l = b >> 1, which = b & 1;
    const float* src = (which ? upd : msg) + (size_t)l * HH * HH;
    __half* dst = (which ? g_uW2i : g_mW2i) + (size_t)l * 128 * PB;
    for (int i = threadIdx.x; i < 128 * 128; i += blockDim.x) {
        int n = i & 127, k = i >> 7;
        dst[n * PB + k] = __float2half(src[k * HH + n]);
    }
}

// ---------------------------------------------------------------------------
// HMMA 2-layer MLP, 128 rows per block, 256 threads (8 warps, warp tile 32x64)
// ---------------------------------------------------------------------------
struct MlpCtx {
    uint32_t sb;
    int lane, wm, wn;
    float acc[2][8][4];
};

__device__ __forceinline__ void gemm_zero(MlpCtx& c) {
#pragma unroll
    for (int mt = 0; mt < 2; mt++)
#pragma unroll
        for (int nt = 0; nt < 8; nt++)
#pragma unroll
            for (int q = 0; q < 4; q++) c.acc[mt][nt][q] = 0.f;
}

// A at aoff (pitch pbytes), B at boff (pitch pbytes), ksteps of 16
__device__ __forceinline__ void gemm_run(MlpCtx& c, uint32_t aoff, uint32_t boff,
                                         uint32_t pbytes, int ksteps) {
    int l = c.lane;
    uint32_t aBase = c.sb + aoff +
        (uint32_t)(c.wm * 32 + (l & 7) + ((l >> 3) & 1) * 8) * pbytes + (l >> 4) * 16;
    uint32_t bBase = c.sb + boff +
        (uint32_t)(c.wn * 64 + (l & 7) + (l >> 4) * 8) * pbytes + ((l >> 3) & 1) * 16;
    for (int ks = 0; ks < ksteps; ks++) {
        uint32_t a0[4], a1[4], bq[4][4];
        ldsm_x4(a0, aBase + ks * 32);
        ldsm_x4(a1, aBase + 16 * pbytes + ks * 32);
#pragma unroll
        for (int p = 0; p < 4; p++) ldsm_x4(bq[p], bBase + p * 16 * pbytes + ks * 32);
#pragma unroll
        for (int p = 0; p < 4; p++) {
            mma16816(c.acc[0][2 * p], a0, bq[p][0], bq[p][1]);
            mma16816(c.acc[0][2 * p + 1], a0, bq[p][2], bq[p][3]);
            mma16816(c.acc[1][2 * p], a1, bq[p][0], bq[p][1]);
            mma16816(c.acc[1][2 * p + 1], a1, bq[p][2], bq[p][3]);
        }
    }
}

// bias + relu -> fp16 H tile (pitch PB)
__device__ __forceinline__ void epi_relu_h(MlpCtx& c, char* sm) {
    int g = c.lane >> 2, t = c.lane & 3;
    const float* sb1 = (const float*)(sm + SB1_OFF);
#pragma unroll
    for (int mt = 0; mt < 2; mt++)
#pragma unroll
        for (int nt = 0; nt < 8; nt++) {
            int row = c.wm * 32 + mt * 16 + g;
            int col = c.wn * 64 + nt * 8 + t * 2;
            float v0 = c.acc[mt][nt][0] + sb1[col];
            float v1 = c.acc[mt][nt][1] + sb1[col + 1];
            float v2 = c.acc[mt][nt][2] + sb1[col];
            float v3 = c.acc[mt][nt][3] + sb1[col + 1];
            v0 = v0 > 0.f ? v0 : 0.f; v1 = v1 > 0.f ? v1 : 0.f;
            v2 = v2 > 0.f ? v2 : 0.f; v3 = v3 > 0.f ? v3 : 0.f;
            *(__half2*)(sm + SH_OFF + row * (PB * 2) + col * 2) = __floats2half2_rn(v0, v1);
            *(__half2*)(sm + SH_OFF + (row + 8) * (PB * 2) + col * 2) = __floats2half2_rn(v2, v3);
        }
}

__global__ void __launch_bounds__(256, 1)
edge_tc(const __half* __restrict__ xh, const void* __restrict__ eidx,
        const __half* __restrict__ W1i, const __half* __restrict__ W2i,
        const float* __restrict__ b1, const float* __restrict__ b2,
        float* __restrict__ agg) {
    extern __shared__ __align__(128) char sm[];
    MlpCtx c;
    c.sb = smem_u32(sm);
    int tid = threadIdx.x;
    c.lane = tid & 31;
    int warp = tid >> 5;
    c.wm = warp >> 1; c.wn = warp & 1;

    if (tid < 128) {
        ((float*)(sm + SB1_OFF))[tid] = b1[tid];
        ((float*)(sm + SB2_OFF))[tid] = b2[tid];
    }

    // gather: 2 threads per row; h=0 -> x[dst] cols 0-127, h=1 -> x[src] cols 128-255
    {
        int r = tid >> 1, h = tid & 1;
        long long e0 = (long long)blockIdx.x * 128 + r;
        int node;
        if (h == 0) {
            node = load_idx(eidx, (long long)EE + e0);
            ((int*)(sm + SDST_OFF))[r] = node;
        } else {
            node = load_idx(eidx, e0);
        }
        const uint4* row = (const uint4*)xh + (size_t)node * 16;
        uint4* dstp = (uint4*)(sm + SA_OFF + r * (PA * 2) + h * 256);
#pragma unroll
        for (int j = 0; j < 16; j++) dstp[j] = __ldg(row + j);
    }
    // weights (images already padded/n-major): linear vector copy
    {
        const uint4* w1 = (const uint4*)W1i;
        uint4* s1 = (uint4*)(sm + SW1_OFF);
        for (int j = tid; j < 128 * PA * 2 / 16; j += 256) s1[j] = __ldg(w1 + j);
        const uint4* w2 = (const uint4*)W2i;
        uint4* s2 = (uint4*)(sm + SW2_OFF);
        for (int j = tid; j < 128 * PB * 2 / 16; j += 256) s2[j] = __ldg(w2 + j);
    }
    __syncthreads();

    gemm_zero(c);
    gemm_run(c, SA_OFF, SW1_OFF, PA * 2, 16);
    epi_relu_h(c, sm);
    __syncthreads();

    gemm_zero(c);
    gemm_run(c, SH_OFF, SW2_OFF, PB * 2, 8);

    // epilogue: bias + atomic scatter into agg[dst]
    {
        int g = c.lane >> 2, t = c.lane & 3;
        const float* sb2 = (const float*)(sm + SB2_OFF);
        const int* sdst = (const int*)(sm + SDST_OFF);
#pragma unroll
        for (int mt = 0; mt < 2; mt++)
#pragma unroll
            for (int nt = 0; nt < 8; nt++) {
                int row = c.wm * 32 + mt * 16 + g;
                int col = c.wn * 64 + nt * 8 + t * 2;
                float bb0 = sb2[col], bb1 = sb2[col + 1];
                int d0 = sdst[row], d1 = sdst[row + 8];
                float* p0 = agg + (size_t)d0 * HH + col;
                float* p1 = agg + (size_t)d1 * HH + col;
                atomicAdd(p0, c.acc[mt][nt][0] + bb0);
                atomicAdd(p0 + 1, c.acc[mt][nt][1] + bb1);
                atomicAdd(p1, c.acc[mt][nt][2] + bb0);
                atomicAdd(p1 + 1, c.acc[mt][nt][3] + bb1);
            }
    }
}

__global__ void __launch_bounds__(256, 1)
upd_tc(const __half* __restrict__ xh, const float* __restrict__ agg,
       const __half* __restrict__ W1i, const __half* __restrict__ W2i,
       const float* __restrict__ b1, const float* __restrict__ b2,
       __half* __restrict__ xout) {
    extern __shared__ __align__(128) char sm[];
    MlpCtx c;
    c.sb = smem_u32(sm);
    int tid = threadIdx.x;
    c.lane = tid & 31;
    int warp = tid >> 5;
    c.wm = warp >> 1; c.wn = warp & 1;

    if (tid < 128) {
        ((float*)(sm + SB1_OFF))[tid] = b1[tid];
        ((float*)(sm + SB2_OFF))[tid] = b2[tid];
    }
    // gather: h=0 -> x row (fp16 copy), h=1 -> agg row (fp32->fp16)
    {
        int r = tid >> 1, h = tid & 1;
        int node = blockIdx.x * 128 + r;
        if (h == 0) {
            const uint4* row = (const uint4*)xh + (size_t)node * 16;
            uint4* dstp = (uint4*)(sm + SA_OFF + r * (PA * 2));
#pragma unroll
            for (int j = 0; j < 16; j++) dstp[j] = __ldg(row + j);
        } else {
            const float4* ar = (const float4*)(agg + (size_t)node * HH);
            uint4* dstp = (uint4*)(sm + SA_OFF + r * (PA * 2) + 256);
#pragma unroll
            for (int j = 0; j < 16; j++) {
                float4 a = __ldg(ar + 2 * j), b = __ldg(ar + 2 * j + 1);
                __half2 h0 = __floats2half2_rn(a.x, a.y), h1 = __floats2half2_rn(a.z, a.w);
                __half2 h2 = __floats2half2_rn(b.x, b.y), h3 = __floats2half2_rn(b.z, b.w);
                uint4 v;
                v.x = *(uint32_t*)&h0; v.y = *(uint32_t*)&h1;
                v.z = *(uint32_t*)&h2; v.w = *(uint32_t*)&h3;
                dstp[j] = v;
            }
        }
    }
    {
        const uint4* w1 = (const uint4*)W1i;
        uint4* s1 = (uint4*)(sm + SW1_OFF);
        for (int j = tid; j < 128 * PA * 2 / 16; j += 256) s1[j] = __ldg(w1 + j);
        const uint4* w2 = (const uint4*)W2i;
        uint4* s2 = (uint4*)(sm + SW2_OFF);
        for (int j = tid; j < 128 * PB * 2 / 16; j += 256) s2[j] = __ldg(w2 + j);
    }
    __syncthreads();

    gemm_zero(c);
    gemm_run(c, SA_OFF, SW1_OFF, PA * 2, 16);
    epi_relu_h(c, sm);
    __syncthreads();

    gemm_zero(c);
    gemm_run(c, SH_OFF, SW2_OFF, PB * 2, 8);

    {
        int g = c.lane >> 2, t = c.lane & 3;
        const float* sb2 = (const float*)(sm + SB2_OFF);
        int n0 = blockIdx.x * 128;
#pragma unroll
        for (int mt = 0; mt < 2; mt++)
#pragma unroll
            for (int nt = 0; nt < 8; nt++) {
                int row = c.wm * 32 + mt * 16 + g;
                int col = c.wn * 64 + nt * 8 + t * 2;
                float bb0 = sb2[col], bb1 = sb2[col + 1];
                __half2 h0 = __floats2half2_rn(c.acc[mt][nt][0] + bb0, c.acc[mt][nt][1] + bb1);
                __half2 h1 = __floats2half2_rn(c.acc[mt][nt][2] + bb0, c.acc[mt][nt][3] + bb1);
                *(__half2*)(xout + (size_t)(n0 + row) * HH + col) = h0;
                *(__half2*)(xout + (size_t)(n0 + row + 8) * HH + col) = h1;
            }
    }
}

// ---------------------------------------------------------------------------
// fp32 embed / head (small fraction)
// ---------------------------------------------------------------------------
#define HS_E (128 * 129)
#define AS_E (128 * 33)
#define WS_E (32 * 128)
#define SMEM_BYTES ((HS_E + AS_E + WS_E) * 4)

__device__ __forceinline__ void mm_chunk(const float* As, int ap, const float* Ws,
                                         int ty, int tx, float acc[8][8]) {
#pragma unroll
    for (int k = 0; k < 32; k++) {
        float a[8], b[8];
#pragma unroll
        for (int i = 0; i < 8; i++) a[i] = As[(ty * 8 + i) * ap + k];
#pragma unroll
        for (int j = 0; j < 8; j++) b[j] = Ws[k * 128 + tx * 8 + j];
#pragma unroll
        for (int i = 0; i < 8; i++)
#pragma unroll
            for (int j = 0; j < 8; j++) acc[i][j] += a[i] * b[j];
    }
}

__global__ void embed_kernel(const float* __restrict__ loc, const float* __restrict__ vel,
                             const float* __restrict__ W1, const float* __restrict__ b1,
                             const float* __restrict__ W2, const float* __restrict__ b2,
                             __half* __restrict__ xout) {
    extern __shared__ float smf[];
    float* Hs = smf;
    float* As = smf + HS_E;
    float* Ws = smf + HS_E + AS_E;
    int tid = threadIdx.x;
    int n0 = blockIdx.x * 128;
    int tx = tid & 15, ty = tid >> 4;
    float acc[8][8];
#pragma unroll
    for (int i = 0; i < 8; i++)
#pragma unroll
        for (int j = 0; j < 8; j++) acc[i][j] = 0.f;

    for (int kc = 0; kc < 64; kc += 32) {
        for (int t = tid; t < 128 * 32; t += 256) {
            int r = t >> 5, cc = t & 31;
            int k = kc + cc;
            float v = 0.f;
            if (k < 60) {
                int f = k / 6, c6 = k % 6;
                int base = (n0 + r) * 30 + f * 3;
                v = (c6 < 3) ? loc[base + c6] : vel[base + c6 - 3];
            }
            As[r * 33 + cc] = v;
        }
        for (int t = tid; t < 32 * 128; t += 256) {
            int r = t >> 7, cc = t & 127;
            int k = kc + r;
            Ws[t] = (k < 60) ? W1[k * HH + cc] : 0.f;
        }
        __syncthreads();
        mm_chunk(As, 33, Ws, ty, tx, acc);
        __syncthreads();
    }
#pragma unroll
    for (int i = 0; i < 8; i++)
#pragma unroll
        for (int j = 0; j < 8; j++) {
            float v = acc[i][j] + b1[tx * 8 + j];
            Hs[(ty * 8 + i) * 129 + tx * 8 + j] = v > 0.f ? v : 0.f;
            acc[i][j] = 0.f;
        }
    __syncthreads();
    for (int kc = 0; kc < 128; kc += 32) {
        for (int t = tid; t < 32 * 128; t += 256) {
            int r = t >> 7, cc = t & 127;
            Ws[t] = W2[(kc + r) * HH + cc];
        }
        __syncthreads();
        mm_chunk(Hs + kc, 129, Ws, ty, tx, acc);
        __syncthreads();
    }
#pragma unroll
    for (int i = 0; i < 8; i++)
#pragma unroll
        for (int j = 0; j < 8; j++)
            xout[(size_t)(n0 + ty * 8 + i) * HH + tx * 8 + j] =
                __float2half(acc[i][j] + b2[tx * 8 + j]);
}

__global__ void head_kernel(const __half* __restrict__ x,
                            const float* __restrict__ W1, const float* __restrict__ b1,
                            const float* __restrict__ W2, const float* __restrict__ b2,
                            float* __restrict__ hout) {
    extern __shared__ float smf[];
    float* Hs = smf;
    float* Wh = smf + HS_E;
    float* Ws = smf + HS_E + AS_E;
    int tid = threadIdx.x;
    int n0 = blockIdx.x * 128;
    int tx = tid & 15, ty = tid >> 4;
    float acc[8][8];
#pragma unroll
    for (int i = 0; i < 8; i++)
#pragma unroll
        for (int j = 0; j < 8; j++) acc[i][j] = 0.f;

    for (int kc = 0; kc < 128; kc += 32) {
        for (int t = tid; t < 32 * 128; t += 256) {
            int r = t >> 7, cc = t & 127;
            Ws[t] = W1[(kc + r) * HH + cc];
        }
        __syncthreads();
#pragma unroll
        for (int k = 0; k < 32; k++) {
            float a[8], b[8];
#pragma unroll
            for (int i = 0; i < 8; i++)
                a[i] = __half2float(x[(size_t)(n0 + ty * 8 + i) * HH + kc + k]);
#pragma unroll
            for (int j = 0; j < 8; j++) b[j] = Ws[k * 128 + tx * 8 + j];
#pragma unroll
            for (int i = 0; i < 8; i++)
#pragma unroll
                for (int j = 0; j < 8; j++) acc[i][j] += a[i] * b[j];
        }
        __syncthreads();
    }
#pragma unroll
    for (int i = 0; i < 8; i++)
#pragma unroll
        for (int j = 0; j < 8; j++) {
            float v = acc[i][j] + b1[tx * 8 + j];
            Hs[(ty * 8 + i) * 129 + tx * 8 + j] = v > 0.f ? v : 0.f;
        }
    for (int t = tid; t < 128 * 30; t += 256) Wh[t] = W2[t];
    __syncthreads();
    for (int t = tid; t < 128 * 30; t += 256) {
        int row = t / 30, cc = t % 30;
        float s = b2[cc];
        const float* hr = Hs + row * 129;
#pragma unroll 8
        for (int k = 0; k < 128; k++) s += hr[k] * Wh[k * 30 + cc];
        hout[(size_t)(n0 + row) * 30 + cc] = s;
    }
}

// ---------------------------------------------------------------------------
// loss
// ---------------------------------------------------------------------------
__global__ void loss_kernel(const float* __restrict__ hout, const float* __restrict__ loc,
                            const float* __restrict__ y, float* __restrict__ out) {
    int w = (blockIdx.x * blockDim.x + threadIdx.x) >> 5;
    int lane = threadIdx.x & 31;
    if (w >= BB) return;
    float ade = 0.f, fde = 0.f;
    for (int p = lane; p < 160; p += 32) {
        int node = w * 16 + p / NF;
        int f = p % NF;
        int base = node * 30 + f * 3;
        float dx = hout[base] + loc[base] - y[base];
        float dy = hout[base + 1] + loc[base + 1] - y[base + 1];
        float dz = hout[base + 2] + loc[base + 2] - y[base + 2];
        float d = sqrtf(dx * dx + dy * dy + dz * dz);
        ade += d;
        if (f == NF - 1) fde += d;
    }
#pragma unroll
    for (int o = 16; o; o >>= 1) {
        ade += __shfl_down_sync(0xffffffffu, ade, o);
        fde += __shfl_down_sync(0xffffffffu, fde, o);
    }
    if (lane == 0) {
        out[1 + w] = ade / 160.f;
        out[1 + BB + w] = fde / 16.f;
    }
}

__global__ void final_kernel(float* __restrict__ out) {
    __shared__ float s[256];
    float v = 0.f;
    for (int i = threadIdx.x; i < BB; i += 256) v += out[1 + i];
    s[threadIdx.x] = v;
    __syncthreads();
    for (int o = 128; o; o >>= 1) {
        if (threadIdx.x < o) s[threadIdx.x] += s[threadIdx.x + o];
        __syncthreads();
    }
    if (threadIdx.x == 0) out[0] = s[0] / (float)BB;
}

// ---------------------------------------------------------------------------
// host
// ---------------------------------------------------------------------------
extern "C" void kernel_launch(void* const* d_in, const int* in_sizes, int n_in,
                              void* d_out, int out_size) {
    int o = (n_in > 4 && in_sizes[4] == 1) ? 1 : 0;
    const float* loc = (const float*)d_in[0];
    const float* vel = (const float*)d_in[1];
    const float* y   = (const float*)d_in[2];
    const void*  eix = d_in[3];
    const float* embW1 = (const float*)d_in[4 + o];
    const float* embb1 = (const float*)d_in[5 + o];
    const float* embW2 = (const float*)d_in[6 + o];
    const float* embb2 = (const float*)d_in[7 + o];
    const float* msgW1 = (const float*)d_in[8 + o];
    const float* msgb1 = (const float*)d_in[9 + o];
    const float* msgW2 = (const float*)d_in[10 + o];
    const float* msgb2 = (const float*)d_in[11 + o];
    const float* updW1 = (const float*)d_in[12 + o];
    const float* updb1 = (const float*)d_in[13 + o];
    const float* updW2 = (const float*)d_in[14 + o];
    const float* updb2 = (const float*)d_in[15 + o];
    const float* hW1 = (const float*)d_in[16 + o];
    const float* hb1 = (const float*)d_in[17 + o];
    const float* hW2 = (const float*)d_in[18 + o];
    const float* hb2 = (const float*)d_in[19 + o];
    float* out = (float*)d_out;

    cudaFuncSetAttribute(edge_tc, cudaFuncAttributeMaxDynamicSharedMemorySize, DYNB);
    cudaFuncSetAttribute(upd_tc, cudaFuncAttributeMaxDynamicSharedMemorySize, DYNB);
    cudaFuncSetAttribute(embed_kernel, cudaFuncAttributeMaxDynamicSharedMemorySize, SMEM_BYTES);
    cudaFuncSetAttribute(head_kernel, cudaFuncAttributeMaxDynamicSharedMemorySize, SMEM_BYTES);

    __half *xhp, *xh2p, *mW1i, *mW2i, *uW1i, *uW2i;
    float *aggp, *headp;
    cudaGetSymbolAddress((void**)&xhp, g_xh);
    cudaGetSymbolAddress((void**)&xh2p, g_xh2);
    cudaGetSymbolAddress((void**)&aggp, g_agg);
    cudaGetSymbolAddress((void**)&headp, g_head);
    cudaGetSymbolAddress((void**)&mW1i, g_mW1i);
    cudaGetSymbolAddress((void**)&mW2i, g_mW2i);
    cudaGetSymbolAddress((void**)&uW1i, g_uW1i);
    cudaGetSymbolAddress((void**)&uW2i, g_uW2i);

    detect_kernel<<<1, 32>>>((const int*)eix);
    prep_w1<<<LL * 2, 256>>>(msgW1, updW1);
    prep_w2<<<LL * 2, 256>>>(msgW2, updW2);
    embed_kernel<<<NN / 128, 256, SMEM_BYTES>>>(loc, vel, embW1, embb1, embW2, embb2, xhp);

    __half* xa = xhp;
    __half* xb = xh2p;
    for (int i = 0; i < LL; i++) {
        cudaMemsetAsync(aggp, 0, (size_t)NN * HH * sizeof(float));
        edge_tc<<<EE / 128, 256, DYNB>>>(
            xa, eix,
            mW1i + (size_t)i * 128 * PA, mW2i + (size_t)i * 128 * PB,
            msgb1 + (size_t)i * HH, msgb2 + (size_t)i * HH, aggp);
        upd_tc<<<NN / 128, 256, DYNB>>>(
            xa, aggp,
            uW1i + (size_t)i * 128 * PA, uW2i + (size_t)i * 128 * PB,
            updb1 + (size_t)i * HH, updb2 + (size_t)i * HH, xb);
        __half* t = xa; xa = xb; xb = t;
    }
    head_kernel<<<NN / 128, 256, SMEM_BYTES>>>(xa, hW1, hb1, hW2, hb2, headp);
    loss_kernel<<<(BB * 32 + 127) / 128, 128>>>(headp, loc, y, out);
    final_kernel<<<1, 256>>>(out);
}

// round 6
// speedup vs baseline: 3.8574x; 1.1150x over previous
#include <cuda_runtime.h>
#include <cuda_fp16.h>
#include <math.h>
#include <stdint.h>

#define NN 32768
#define EE 524288
#define HH 128
#define BB 2048
#define LL 7
#define NF 10
#define TPB 4   // edge tiles (128 edges each) per block

// ---------------------------------------------------------------------------
// device scratch
// ---------------------------------------------------------------------------
__device__ int    g_is64;
__device__ __half g_xh[NN * HH];
__device__ __half g_xh2[NN * HH];
__device__ float  g_agg[NN * HH];
__device__ float  g_head[NN * 30];
// n-major fp16 weight images: W1t [n=128][k=256] pitch 264 halfs; W2t [128][128] pitch 136
__device__ __half g_mW1i[LL * 128 * 264];
__device__ __half g_mW2i[LL * 128 * 136];
__device__ __half g_uW1i[LL * 128 * 264];
__device__ __half g_uW2i[LL * 128 * 136];

// pitches in halfs
#define PA 264   // K=256 + 8 pad  (row stride 528 B -> 16B bank rotation)
#define PB 136   // K=128 + 8 pad  (272 B)

// smem layout (bytes)
#define SA_OFF   0
#define SW1_OFF  (128 * PA * 2)                  // 67584
#define SH_OFF   (SW1_OFF + 128 * PA * 2)        // 135168 (H fp16 / f32 out staging)
#define SW2_OFF  (SH_OFF + 128 * PB * 2)         // 169984
#define SB1_OFF  (SW2_OFF + 128 * PB * 2)        // 204800
#define SB2_OFF  (SB1_OFF + 512)
#define SDST_OFF (SB2_OFF + 512)
#define DYNB     (SDST_OFF + 512)
#define POUT     132   // f32 staging pitch (floats); 528B row = 33*16B, float4-aligned

__device__ __forceinline__ uint32_t smem_u32(const void* p) {
    uint32_t a;
    asm("{ .reg .u64 t; cvta.to.shared.u64 t, %1; cvt.u32.u64 %0, t; }" : "=r"(a) : "l"(p));
    return a;
}

__device__ __forceinline__ void ldsm_x4(uint32_t r[4], uint32_t addr) {
    asm volatile("ldmatrix.sync.aligned.m8n8.x4.shared.b16 {%0,%1,%2,%3}, [%4];"
                 : "=r"(r[0]), "=r"(r[1]), "=r"(r[2]), "=r"(r[3]) : "r"(addr));
}

__device__ __forceinline__ void mma16816(float c[4], const uint32_t a[4],
                                         uint32_t b0, uint32_t b1) {
    asm volatile(
        "mma.sync.aligned.m16n8k16.row.col.f32.f16.f16.f32 "
        "{%0,%1,%2,%3},{%4,%5,%6,%7},{%8,%9},{%0,%1,%2,%3};"
        : "+f"(c[0]), "+f"(c[1]), "+f"(c[2]), "+f"(c[3])
        : "r"(a[0]), "r"(a[1]), "r"(a[2]), "r"(a[3]), "r"(b0), "r"(b1));
}

__device__ __forceinline__ void red_add_v4(float* p, float x, float y, float z, float w) {
    asm volatile("red.global.add.v4.f32 [%0], {%1, %2, %3, %4};"
                 :: "l"(p), "f"(x), "f"(y), "f"(z), "f"(w) : "memory");
}

__device__ __forceinline__ int load_idx(const void* p, long long i) {
    if (g_is64) return (int)((const long long*)p)[i];
    return ((const int*)p)[i];
}

__global__ void detect_kernel(const int* e) {
    if (threadIdx.x == 0) {
        int is64 = 1;
        for (int i = 1; i < 256; i += 2)
            if (e[i] != 0) { is64 = 0; break; }
        g_is64 = is64;
    }
}

// ---------------------------------------------------------------------------
// weight prep: fp32 [k][n] -> fp16 n-major [n][k] padded
// ---------------------------------------------------------------------------
__global__ void prep_w1(const float* msg, const float* upd) {
    int b = blockIdx.x;           // l*2 + which
    int l = b >> 1, which = b & 1;
    const float* src = (which ? upd : msg) + (size_t)l * 256 * HH;
    __half* dst = (which ? g_uW1i : g_mW1i) + (size_t)l * 128 * PA;
    for (int i = threadIdx.x; i < 128 * 256; i += blockDim.x) {
        int n = i & 127, k = i >> 7;
        dst[n * PA + k] = __float2half(src[k * HH + n]);
    }
}
__global__ void prep_w2(const float* msg, const float* upd) {
    int b = blockIdx.x;
    int l = b >> 1, which = b & 1;
    const float* src = (which ? upd : msg) + (size_t)l * HH * HH;
    __half* dst = (which ? g_uW2i : g_mW2i) + (size_t)l * 128 * PB;
    for (int i = threadIdx.x; i < 128 * 128; i += blockDim.x) {
        int n = i & 127, k = i >> 7;
        dst[n * PB + k] = __float2half(src[k * HH + n]);
    }
}

// ---------------------------------------------------------------------------
// HMMA 2-layer MLP, 128 rows per tile, 256 threads (8 warps, warp tile 32x64)
// ---------------------------------------------------------------------------
struct MlpCtx {
    uint32_t sb;
    int lane, wm, wn;
    float acc[2][8][4];
};

__device__ __forceinline__ void gemm_zero(MlpCtx& c) {
#pragma unroll
    for (int mt = 0; mt < 2; mt++)
#pragma unroll
        for (int nt = 0; nt < 8; nt++)
#pragma unroll
            for (int q = 0; q < 4; q++) c.acc[mt][nt][q] = 0.f;
}

__device__ __forceinline__ void gemm_run(MlpCtx& c, uint32_t aoff, uint32_t boff,
                                         uint32_t pbytes, int ksteps) {
    int l = c.lane;
    uint32_t aBase = c.sb + aoff +
        (uint32_t)(c.wm * 32 + (l & 7) + ((l >> 3) & 1) * 8) * pbytes + (l >> 4) * 16;
    uint32_t bBase = c.sb + boff +
        (uint32_t)(c.wn * 64 + (l & 7) + (l >> 4) * 8) * pbytes + ((l >> 3) & 1) * 16;
    for (int ks = 0; ks < ksteps; ks++) {
        uint32_t a0[4], a1[4], bq[4][4];
        ldsm_x4(a0, aBase + ks * 32);
        ldsm_x4(a1, aBase + 16 * pbytes + ks * 32);
#pragma unroll
        for (int p = 0; p < 4; p++) ldsm_x4(bq[p], bBase + p * 16 * pbytes + ks * 32);
#pragma unroll
        for (int p = 0; p < 4; p++) {
            mma16816(c.acc[0][2 * p], a0, bq[p][0], bq[p][1]);
            mma16816(c.acc[0][2 * p + 1], a0, bq[p][2], bq[p][3]);
            mma16816(c.acc[1][2 * p], a1, bq[p][0], bq[p][1]);
            mma16816(c.acc[1][2 * p + 1], a1, bq[p][2], bq[p][3]);
        }
    }
}

// bias + relu -> fp16 H tile (pitch PB)
__device__ __forceinline__ void epi_relu_h(MlpCtx& c, char* sm) {
    int g = c.lane >> 2, t = c.lane & 3;
    const float* sb1 = (const float*)(sm + SB1_OFF);
#pragma unroll
    for (int mt = 0; mt < 2; mt++)
#pragma unroll
        for (int nt = 0; nt < 8; nt++) {
            int row = c.wm * 32 + mt * 16 + g;
            int col = c.wn * 64 + nt * 8 + t * 2;
            float v0 = c.acc[mt][nt][0] + sb1[col];
            float v1 = c.acc[mt][nt][1] + sb1[col + 1];
            float v2 = c.acc[mt][nt][2] + sb1[col];
            float v3 = c.acc[mt][nt][3] + sb1[col + 1];
            v0 = v0 > 0.f ? v0 : 0.f; v1 = v1 > 0.f ? v1 : 0.f;
            v2 = v2 > 0.f ? v2 : 0.f; v3 = v3 > 0.f ? v3 : 0.f;
            *(__half2*)(sm + SH_OFF + row * (PB * 2) + col * 2) = __floats2half2_rn(v0, v1);
            *(__half2*)(sm + SH_OFF + (row + 8) * (PB * 2) + col * 2) = __floats2half2_rn(v2, v3);
        }
}

__global__ void __launch_bounds__(256, 1)
edge_tc(const __half* __restrict__ xh, const void* __restrict__ eidx,
        const __half* __restrict__ W1i, const __half* __restrict__ W2i,
        const float* __restrict__ b1, const float* __restrict__ b2,
        float* __restrict__ agg) {
    extern __shared__ __align__(128) char sm[];
    MlpCtx c;
    c.sb = smem_u32(sm);
    int tid = threadIdx.x;
    c.lane = tid & 31;
    int warp = tid >> 5;
    c.wm = warp >> 1; c.wn = warp & 1;

    if (tid < 128) {
        ((float*)(sm + SB1_OFF))[tid] = b1[tid];
        ((float*)(sm + SB2_OFF))[tid] = b2[tid];
    }
    // weights once per block (amortized over TPB tiles)
    {
        const uint4* w1 = (const uint4*)W1i;
        uint4* s1 = (uint4*)(sm + SW1_OFF);
        for (int j = tid; j < 128 * PA * 2 / 16; j += 256) s1[j] = __ldg(w1 + j);
        const uint4* w2 = (const uint4*)W2i;
        uint4* s2 = (uint4*)(sm + SW2_OFF);
        for (int j = tid; j < 128 * PB * 2 / 16; j += 256) s2[j] = __ldg(w2 + j);
    }
    __syncthreads();

    for (int t = 0; t < TPB; t++) {
        // gather: 2 threads per row; h=0 -> x[dst] cols 0-127, h=1 -> x[src]
        {
            int r = tid >> 1, h = tid & 1;
            long long e0 = ((long long)blockIdx.x * TPB + t) * 128 + r;
            int node;
            if (h == 0) {
                node = load_idx(eidx, (long long)EE + e0);
                ((int*)(sm + SDST_OFF))[r] = node;
            } else {
                node = load_idx(eidx, e0);
            }
            const uint4* row = (const uint4*)xh + (size_t)node * 16;
            uint4* dstp = (uint4*)(sm + SA_OFF + r * (PA * 2) + h * 256);
#pragma unroll
            for (int j = 0; j < 16; j++) dstp[j] = __ldg(row + j);
        }
        __syncthreads();

        gemm_zero(c);
        gemm_run(c, SA_OFF, SW1_OFF, PA * 2, 16);
        epi_relu_h(c, sm);
        __syncthreads();

        gemm_zero(c);
        gemm_run(c, SH_OFF, SW2_OFF, PB * 2, 8);
        __syncthreads();   // all warps done reading H; H region now free

        // staged epilogue: two 64-row passes, f32 in H region, then v4 red
        {
            float* so = (float*)(sm + SH_OFF);
            const float* sb2 = (const float*)(sm + SB2_OFF);
            const int* sdst = (const int*)(sm + SDST_OFF);
            int g = c.lane >> 2, tq = c.lane & 3;
#pragma unroll
            for (int pass = 0; pass < 2; pass++) {
                if ((c.wm >> 1) == pass) {
                    int rbase = (c.wm & 1) * 32;
#pragma unroll
                    for (int mt = 0; mt < 2; mt++)
#pragma unroll
                        for (int nt = 0; nt < 8; nt++) {
                            int row = rbase + mt * 16 + g;
                            int col = c.wn * 64 + nt * 8 + tq * 2;
                            so[row * POUT + col]           = c.acc[mt][nt][0] + sb2[col];
                            so[row * POUT + col + 1]       = c.acc[mt][nt][1] + sb2[col + 1];
                            so[(row + 8) * POUT + col]     = c.acc[mt][nt][2] + sb2[col];
                            so[(row + 8) * POUT + col + 1] = c.acc[mt][nt][3] + sb2[col + 1];
                        }
                }
                __syncthreads();
#pragma unroll
                for (int q = 0; q < 8; q++) {
                    int id = tid + q * 256;            // 0..2047
                    int row = id >> 5, c4 = id & 31;
                    int d = sdst[pass * 64 + row];
                    const float* sp = so + row * POUT + c4 * 4;
                    red_add_v4(agg + (size_t)d * HH + c4 * 4, sp[0], sp[1], sp[2], sp[3]);
                }
                __syncthreads();
            }
        }
    }
}

__global__ void __launch_bounds__(256, 1)
upd_tc(const __half* __restrict__ xh, const float* __restrict__ agg,
       const __half* __restrict__ W1i, const __half* __restrict__ W2i,
       const float* __restrict__ b1, const float* __restrict__ b2,
       __half* __restrict__ xout) {
    extern __shared__ __align__(128) char sm[];
    MlpCtx c;
    c.sb = smem_u32(sm);
    int tid = threadIdx.x;
    c.lane = tid & 31;
    int warp = tid >> 5;
    c.wm = warp >> 1; c.wn = warp & 1;

    if (tid < 128) {
        ((float*)(sm + SB1_OFF))[tid] = b1[tid];
        ((float*)(sm + SB2_OFF))[tid] = b2[tid];
    }
    // gather: h=0 -> x row (fp16 copy), h=1 -> agg row (fp32->fp16)
    {
        int r = tid >> 1, h = tid & 1;
        int node = blockIdx.x * 128 + r;
        if (h == 0) {
            const uint4* row = (const uint4*)xh + (size_t)node * 16;
            uint4* dstp = (uint4*)(sm + SA_OFF + r * (PA * 2));
#pragma unroll
            for (int j = 0; j < 16; j++) dstp[j] = __ldg(row + j);
        } else {
            const float4* ar = (const float4*)(agg + (size_t)node * HH);
            uint4* dstp = (uint4*)(sm + SA_OFF + r * (PA * 2) + 256);
#pragma unroll
            for (int j = 0; j < 16; j++) {
                float4 a = __ldg(ar + 2 * j), b = __ldg(ar + 2 * j + 1);
                __half2 h0 = __floats2half2_rn(a.x, a.y), h1 = __floats2half2_rn(a.z, a.w);
                __half2 h2 = __floats2half2_rn(b.x, b.y), h3 = __floats2half2_rn(b.z, b.w);
                uint4 v;
                v.x = *(uint32_t*)&h0; v.y = *(uint32_t*)&h1;
                v.z = *(uint32_t*)&h2; v.w = *(uint32_t*)&h3;
                dstp[j] = v;
            }
        }
    }
    {
        const uint4* w1 = (const uint4*)W1i;
        uint4* s1 = (uint4*)(sm + SW1_OFF);
        for (int j = tid; j < 128 * PA * 2 / 16; j += 256) s1[j] = __ldg(w1 + j);
        const uint4* w2 = (const uint4*)W2i;
        uint4* s2 = (uint4*)(sm + SW2_OFF);
        for (int j = tid; j < 128 * PB * 2 / 16; j += 256) s2[j] = __ldg(w2 + j);
    }
    __syncthreads();

    gemm_zero(c);
    gemm_run(c, SA_OFF, SW1_OFF, PA * 2, 16);
    epi_relu_h(c, sm);
    __syncthreads();

    gemm_zero(c);
    gemm_run(c, SH_OFF, SW2_OFF, PB * 2, 8);

    {
        int g = c.lane >> 2, t = c.lane & 3;
        const float* sb2 = (const float*)(sm + SB2_OFF);
        int n0 = blockIdx.x * 128;
#pragma unroll
        for (int mt = 0; mt < 2; mt++)
#pragma unroll
            for (int nt = 0; nt < 8; nt++) {
                int row = c.wm * 32 + mt * 16 + g;
                int col = c.wn * 64 + nt * 8 + t * 2;
                float bb0 = sb2[col], bb1 = sb2[col + 1];
                __half2 h0 = __floats2half2_rn(c.acc[mt][nt][0] + bb0, c.acc[mt][nt][1] + bb1);
                __half2 h1 = __floats2half2_rn(c.acc[mt][nt][2] + bb0, c.acc[mt][nt][3] + bb1);
                *(__half2*)(xout + (size_t)(n0 + row) * HH + col) = h0;
                *(__half2*)(xout + (size_t)(n0 + row + 8) * HH + col) = h1;
            }
    }
}

// ---------------------------------------------------------------------------
// fp32 embed / head (small fraction)
// ---------------------------------------------------------------------------
#define HS_E (128 * 129)
#define AS_E (128 * 33)
#define WS_E (32 * 128)
#define SMEM_BYTES ((HS_E + AS_E + WS_E) * 4)

__device__ __forceinline__ void mm_chunk(const float* As, int ap, const float* Ws,
                                         int ty, int tx, float acc[8][8]) {
#pragma unroll
    for (int k = 0; k < 32; k++) {
        float a[8], b[8];
#pragma unroll
        for (int i = 0; i < 8; i++) a[i] = As[(ty * 8 + i) * ap + k];
#pragma unroll
        for (int j = 0; j < 8; j++) b[j] = Ws[k * 128 + tx * 8 + j];
#pragma unroll
        for (int i = 0; i < 8; i++)
#pragma unroll
            for (int j = 0; j < 8; j++) acc[i][j] += a[i] * b[j];
    }
}

__global__ void embed_kernel(const float* __restrict__ loc, const float* __restrict__ vel,
                             const float* __restrict__ W1, const float* __restrict__ b1,
                             const float* __restrict__ W2, const float* __restrict__ b2,
                             __half* __restrict__ xout) {
    extern __shared__ float smf[];
    float* Hs = smf;
    float* As = smf + HS_E;
    float* Ws = smf + HS_E + AS_E;
    int tid = threadIdx.x;
    int n0 = blockIdx.x * 128;
    int tx = tid & 15, ty = tid >> 4;
    float acc[8][8];
#pragma unroll
    for (int i = 0; i < 8; i++)
#pragma unroll
        for (int j = 0; j < 8; j++) acc[i][j] = 0.f;

    for (int kc = 0; kc < 64; kc += 32) {
        for (int t = tid; t < 128 * 32; t += 256) {
            int r = t >> 5, cc = t & 31;
            int k = kc + cc;
            float v = 0.f;
            if (k < 60) {
                int f = k / 6, c6 = k % 6;
                int base = (n0 + r) * 30 + f * 3;
                v = (c6 < 3) ? loc[base + c6] : vel[base + c6 - 3];
            }
            As[r * 33 + cc] = v;
        }
        for (int t = tid; t < 32 * 128; t += 256) {
            int r = t >> 7, cc = t & 127;
            int k = kc + r;
            Ws[t] = (k < 60) ? W1[k * HH + cc] : 0.f;
        }
        __syncthreads();
        mm_chunk(As, 33, Ws, ty, tx, acc);
        __syncthreads();
    }
#pragma unroll
    for (int i = 0; i < 8; i++)
#pragma unroll
        for (int j = 0; j < 8; j++) {
            float v = acc[i][j] + b1[tx * 8 + j];
            Hs[(ty * 8 + i) * 129 + tx * 8 + j] = v > 0.f ? v : 0.f;
            acc[i][j] = 0.f;
        }
    __syncthreads();
    for (int kc = 0; kc < 128; kc += 32) {
        for (int t = tid; t < 32 * 128; t += 256) {
            int r = t >> 7, cc = t & 127;
            Ws[t] = W2[(kc + r) * HH + cc];
        }
        __syncthreads();
        mm_chunk(Hs + kc, 129, Ws, ty, tx, acc);
        __syncthreads();
    }
#pragma unroll
    for (int i = 0; i < 8; i++)
#pragma unroll
        for (int j = 0; j < 8; j++)
            xout[(size_t)(n0 + ty * 8 + i) * HH + tx * 8 + j] =
                __float2half(acc[i][j] + b2[tx * 8 + j]);
}

__global__ void head_kernel(const __half* __restrict__ x,
                            const float* __restrict__ W1, const float* __restrict__ b1,
                            const float* __restrict__ W2, const float* __restrict__ b2,
                            float* __restrict__ hout) {
    extern __shared__ float smf[];
    float* Hs = smf;
    float* Wh = smf + HS_E;
    float* Ws = smf + HS_E + AS_E;
    int tid = threadIdx.x;
    int n0 = blockIdx.x * 128;
    int tx = tid & 15, ty = tid >> 4;
    float acc[8][8];
#pragma unroll
    for (int i = 0; i < 8; i++)
#pragma unroll
        for (int j = 0; j < 8; j++) acc[i][j] = 0.f;

    for (int kc = 0; kc < 128; kc += 32) {
        for (int t = tid; t < 32 * 128; t += 256) {
            int r = t >> 7, cc = t & 127;
            Ws[t] = W1[(kc + r) * HH + cc];
        }
        __syncthreads();
#pragma unroll
        for (int k = 0; k < 32; k++) {
            float a[8], b[8];
#pragma unroll
            for (int i = 0; i < 8; i++)
                a[i] = __half2float(x[(size_t)(n0 + ty * 8 + i) * HH + kc + k]);
#pragma unroll
            for (int j = 0; j < 8; j++) b[j] = Ws[k * 128 + tx * 8 + j];
#pragma unroll
            for (int i = 0; i < 8; i++)
#pragma unroll
                for (int j = 0; j < 8; j++) acc[i][j] += a[i] * b[j];
        }
        __syncthreads();
    }
#pragma unroll
    for (int i = 0; i < 8; i++)
#pragma unroll
        for (int j = 0; j < 8; j++) {
            float v = acc[i][j] + b1[tx * 8 + j];
            Hs[(ty * 8 + i) * 129 + tx * 8 + j] = v > 0.f ? v : 0.f;
        }
    for (int t = tid; t < 128 * 30; t += 256) Wh[t] = W2[t];
    __syncthreads();
    for (int t = tid; t < 128 * 30; t += 256) {
        int row = t / 30, cc = t % 30;
        float s = b2[cc];
        const float* hr = Hs + row * 129;
#pragma unroll 8
        for (int k = 0; k < 128; k++) s += hr[k] * Wh[k * 30 + cc];
        hout[(size_t)(n0 + row) * 30 + cc] = s;
    }
}

// ---------------------------------------------------------------------------
// loss
// ---------------------------------------------------------------------------
__global__ void loss_kernel(const float* __restrict__ hout, const float* __restrict__ loc,
                            const float* __restrict__ y, float* __restrict__ out) {
    int w = (blockIdx.x * blockDim.x + threadIdx.x) >> 5;
    int lane = threadIdx.x & 31;
    if (w >= BB) return;
    float ade = 0.f, fde = 0.f;
    for (int p = lane; p < 160; p += 32) {
        int node = w * 16 + p / NF;
        int f = p % NF;
        int base = node * 30 + f * 3;
        float dx = hout[base] + loc[base] - y[base];
        float dy = hout[base + 1] + loc[base + 1] - y[base + 1];
        float dz = hout[base + 2] + loc[base + 2] - y[base + 2];
        float d = sqrtf(dx * dx + dy * dy + dz * dz);
        ade += d;
        if (f == NF - 1) fde += d;
    }
#pragma unroll
    for (int o = 16; o; o >>= 1) {
        ade += __shfl_down_sync(0xffffffffu, ade, o);
        fde += __shfl_down_sync(0xffffffffu, fde, o);
    }
    if (lane == 0) {
        out[1 + w] = ade / 160.f;
        out[1 + BB + w] = fde / 16.f;
    }
}

__global__ void final_kernel(float* __restrict__ out) {
    __shared__ float s[256];
    float v = 0.f;
    for (int i = threadIdx.x; i < BB; i += 256) v += out[1 + i];
    s[threadIdx.x] = v;
    __syncthreads();
    for (int o = 128; o; o >>= 1) {
        if (threadIdx.x < o) s[threadIdx.x] += s[threadIdx.x + o];
        __syncthreads();
    }
    if (threadIdx.x == 0) out[0] = s[0] / (float)BB;
}

// ---------------------------------------------------------------------------
// host
// ---------------------------------------------------------------------------
extern "C" void kernel_launch(void* const* d_in, const int* in_sizes, int n_in,
                              void* d_out, int out_size) {
    int o = (n_in > 4 && in_sizes[4] == 1) ? 1 : 0;
    const float* loc = (const float*)d_in[0];
    const float* vel = (const float*)d_in[1];
    const float* y   = (const float*)d_in[2];
    const void*  eix = d_in[3];
    const float* embW1 = (const float*)d_in[4 + o];
    const float* embb1 = (const float*)d_in[5 + o];
    const float* embW2 = (const float*)d_in[6 + o];
    const float* embb2 = (const float*)d_in[7 + o];
    const float* msgW1 = (const float*)d_in[8 + o];
    const float* msgb1 = (const float*)d_in[9 + o];
    const float* msgW2 = (const float*)d_in[10 + o];
    const float* msgb2 = (const float*)d_in[11 + o];
    const float* updW1 = (const float*)d_in[12 + o];
    const float* updb1 = (const float*)d_in[13 + o];
    const float* updW2 = (const float*)d_in[14 + o];
    const float* updb2 = (const float*)d_in[15 + o];
    const float* hW1 = (const float*)d_in[16 + o];
    const float* hb1 = (const float*)d_in[17 + o];
    const float* hW2 = (const float*)d_in[18 + o];
    const float* hb2 = (const float*)d_in[19 + o];
    float* out = (float*)d_out;

    cudaFuncSetAttribute(edge_tc, cudaFuncAttributeMaxDynamicSharedMemorySize, DYNB);
    cudaFuncSetAttribute(upd_tc, cudaFuncAttributeMaxDynamicSharedMemorySize, DYNB);
    cudaFuncSetAttribute(embed_kernel, cudaFuncAttributeMaxDynamicSharedMemorySize, SMEM_BYTES);
    cudaFuncSetAttribute(head_kernel, cudaFuncAttributeMaxDynamicSharedMemorySize, SMEM_BYTES);

    __half *xhp, *xh2p, *mW1i, *mW2i, *uW1i, *uW2i;
    float *aggp, *headp;
    cudaGetSymbolAddress((void**)&xhp, g_xh);
    cudaGetSymbolAddress((void**)&xh2p, g_xh2);
    cudaGetSymbolAddress((void**)&aggp, g_agg);
    cudaGetSymbolAddress((void**)&headp, g_head);
    cudaGetSymbolAddress((void**)&mW1i, g_mW1i);
    cudaGetSymbolAddress((void**)&mW2i, g_mW2i);
    cudaGetSymbolAddress((void**)&uW1i, g_uW1i);
    cudaGetSymbolAddress((void**)&uW2i, g_uW2i);

    detect_kernel<<<1, 32>>>((const int*)eix);
    prep_w1<<<LL * 2, 256>>>(msgW1, updW1);
    prep_w2<<<LL * 2, 256>>>(msgW2, updW2);
    embed_kernel<<<NN / 128, 256, SMEM_BYTES>>>(loc, vel, embW1, embb1, embW2, embb2, xhp);

    __half* xa = xhp;
    __half* xb = xh2p;
    for (int i = 0; i < LL; i++) {
        cudaMemsetAsync(aggp, 0, (size_t)NN * HH * sizeof(float));
        edge_tc<<<EE / 128 / TPB, 256, DYNB>>>(
            xa, eix,
            mW1i + (size_t)i * 128 * PA, mW2i + (size_t)i * 128 * PB,
            msgb1 + (size_t)i * HH, msgb2 + (size_t)i * HH, aggp);
        upd_tc<<<NN / 128, 256, DYNB>>>(
            xa, aggp,
            uW1i + (size_t)i * 128 * PA, uW2i + (size_t)i * 128 * PB,
            updb1 + (size_t)i * HH, updb2 + (size_t)i * HH, xb);
        __half* t = xa; xa = xb; xb = t;
    }
    head_kernel<<<NN / 128, 256, SMEM_BYTES>>>(xa, hW1, hb1, hW2, hb2, headp);
    loss_kernel<<<(BB * 32 + 127) / 128, 128>>>(headp, loc, y, out);
    final_kernel<<<1, 256>>>(out);
}

// round 7
// speedup vs baseline: 5.3794x; 1.3946x over previous
#include <cuda_runtime.h>
#include <cuda_fp16.h>
#include <math.h>
#include <stdint.h>

#define NN 32768
#define EE 524288
#define HH 128
#define BB 2048
#define LL 7
#define NF 10
#define TPB 2   // edge tiles (128 edges each) per block

// ---------------------------------------------------------------------------
// device scratch
// ---------------------------------------------------------------------------
__device__ int    g_is64;
__device__ __half g_xh[NN * HH];
__device__ __half g_xh2[NN * HH];
__device__ float  g_agg[NN * HH];
__device__ float  g_head[NN * 30];
// fragment-order fp16 weight images (uint4 for 16B alignment)
// layout per matrix: [ks][wn(2)][p(4)][lane(32)] x 16B ; W1: 16 ks -> 4096 uint4
__device__ uint4 g_mW1f[LL * 4096];
__device__ uint4 g_mW2f[LL * 2048];
__device__ uint4 g_uW1f[LL * 4096];
__device__ uint4 g_uW2f[LL * 2048];
__device__ uint4 g_eW1f[1024];         // K=64 (4 ks)
__device__ uint4 g_eW2f[2048];         // K=128 (8 ks)

// pitches in halfs
#define PA 264   // K=256 + 8 pad  (row stride 528 B -> 16B bank rotation)
#define PB 136   // K=128 + 8 pad  (272 B)
#define PE 72    // K=64  + 8 pad  (144 B)

// edge/upd smem layout (bytes)
#define SA_OFF   0
#define SH_OFF   (128 * PA * 2)                  // 67584
#define SB1_OFF  (SH_OFF + 128 * PB * 2)         // 102400
#define SB2_OFF  (SB1_OFF + 512)
#define SDST_OFF (SB2_OFF + 512)
#define DYNB     (SDST_OFF + 512)                // 103936 -> 2 CTAs/SM
#define POUT     132   // f32 staging pitch (floats)

// embed smem layout
#define EA_OFF   0
#define EH_OFF   (128 * PE * 2)                  // 18432
#define EB1_OFF  (EH_OFF + 128 * PB * 2)         // 53248
#define EB2_OFF  (EB1_OFF + 512)
#define DYNB_EM  (EB2_OFF + 512)                 // 54272

__device__ __forceinline__ uint32_t smem_u32(const void* p) {
    uint32_t a;
    asm("{ .reg .u64 t; cvta.to.shared.u64 t, %1; cvt.u32.u64 %0, t; }" : "=r"(a) : "l"(p));
    return a;
}

__device__ __forceinline__ void ldsm_x4(uint32_t r[4], uint32_t addr) {
    asm volatile("ldmatrix.sync.aligned.m8n8.x4.shared.b16 {%0,%1,%2,%3}, [%4];"
                 : "=r"(r[0]), "=r"(r[1]), "=r"(r[2]), "=r"(r[3]) : "r"(addr));
}

__device__ __forceinline__ void mma16816(float c[4], const uint32_t a[4],
                                         uint32_t b0, uint32_t b1) {
    asm volatile(
        "mma.sync.aligned.m16n8k16.row.col.f32.f16.f16.f32 "
        "{%0,%1,%2,%3},{%4,%5,%6,%7},{%8,%9},{%0,%1,%2,%3};"
        : "+f"(c[0]), "+f"(c[1]), "+f"(c[2]), "+f"(c[3])
        : "r"(a[0]), "r"(a[1]), "r"(a[2]), "r"(a[3]), "r"(b0), "r"(b1));
}

__device__ __forceinline__ void red_add_v4(float* p, float x, float y, float z, float w) {
    asm volatile("red.global.add.v4.f32 [%0], {%1, %2, %3, %4};"
                 :: "l"(p), "f"(x), "f"(y), "f"(z), "f"(w) : "memory");
}

__device__ __forceinline__ int load_idx(const void* p, long long i) {
    if (g_is64) return (int)((const long long*)p)[i];
    return ((const int*)p)[i];
}

__global__ void detect_kernel(const int* e) {
    if (threadIdx.x == 0) {
        int is64 = 1;
        for (int i = 1; i < 256; i += 2)
            if (e[i] != 0) { is64 = 0; break; }
        g_is64 = is64;
    }
}

// ---------------------------------------------------------------------------
// weight prep: fp32 [k][n=128] -> fragment-order fp16 image.
// Per PTX m16n8k16.row.col B-frag mapping:
//   b0: k=(l%4)*2+{0,1}, b1: k+8 ; n = l/4 (and +8 for second n-group)
// element e = (((ks*2+wn)*4+p)*32+lane)*8 + h
//   k = ks*16 + (l&3)*2 + (h&1) + ((h>>1)&1)*8
//   n = wn*64 + p*16 + (l>>2) + (h>>2)*8
// ---------------------------------------------------------------------------
__global__ void prep_fragk(const float* __restrict__ src, __half* __restrict__ dst,
                           int ksteps, int Ktrue, int srcStride, int dstStride) {
    int l = blockIdx.x;
    src += (size_t)l * srcStride;
    dst += (size_t)l * dstStride;
    int total = ksteps * 2048;   // ksteps*16*128 halfs
    for (int e = threadIdx.x; e < total; e += blockDim.x) {
        int h = e & 7, lane = (e >> 3) & 31, p = (e >> 8) & 3, wn = (e >> 10) & 1, ks = e >> 11;
        int k = ks * 16 + (lane & 3) * 2 + (h & 1) + ((h >> 1) & 1) * 8;
        int n = wn * 64 + p * 16 + (lane >> 2) + (h >> 2) * 8;
        dst[e] = (k < Ktrue) ? __float2half(src[k * 128 + n]) : __half(0.f);
    }
}

// ---------------------------------------------------------------------------
// HMMA 2-layer MLP, 128 rows per tile, 256 threads (8 warps, warp tile 32x64)
// B operand loaded as fragments directly from global (L1-cached)
// ---------------------------------------------------------------------------
struct MlpCtx {
    uint32_t sb;
    int lane, wm, wn;
    float acc[2][8][4];
};

__device__ __forceinline__ void gemm_zero(MlpCtx& c) {
#pragma unroll
    for (int mt = 0; mt < 2; mt++)
#pragma unroll
        for (int nt = 0; nt < 8; nt++)
#pragma unroll
            for (int q = 0; q < 4; q++) c.acc[mt][nt][q] = 0.f;
}

__device__ __forceinline__ void gemm_run(MlpCtx& c, uint32_t aoff, uint32_t pbytes,
                                         const uint4* __restrict__ wf, int ksteps) {
    int l = c.lane;
    uint32_t aBase = c.sb + aoff +
        (uint32_t)(c.wm * 32 + (l & 7) + ((l >> 3) & 1) * 8) * pbytes + (l >> 4) * 16;
    const uint4* wb = wf + c.wn * 128 + l;   // wn stride = 4*32 uint4
#pragma unroll
    for (int ks = 0; ks < 16; ks++) {
        if (ks >= ksteps) break;
        uint32_t a0[4], a1[4];
        uint4 q[4];
#pragma unroll
        for (int p = 0; p < 4; p++) q[p] = __ldg(wb + ks * 256 + p * 32);
        ldsm_x4(a0, aBase + ks * 32);
        ldsm_x4(a1, aBase + 16 * pbytes + ks * 32);
#pragma unroll
        for (int p = 0; p < 4; p++) {
            mma16816(c.acc[0][2 * p],     a0, q[p].x, q[p].y);
            mma16816(c.acc[0][2 * p + 1], a0, q[p].z, q[p].w);
            mma16816(c.acc[1][2 * p],     a1, q[p].x, q[p].y);
            mma16816(c.acc[1][2 * p + 1], a1, q[p].z, q[p].w);
        }
    }
}

// bias + relu -> fp16 H tile (pitch PB) at shOff
__device__ __forceinline__ void epi_relu_h(MlpCtx& c, char* sm, int shOff, int b1Off) {
    int g = c.lane >> 2, t = c.lane & 3;
    const float* sb1 = (const float*)(sm + b1Off);
#pragma unroll
    for (int mt = 0; mt < 2; mt++)
#pragma unroll
        for (int nt = 0; nt < 8; nt++) {
            int row = c.wm * 32 + mt * 16 + g;
            int col = c.wn * 64 + nt * 8 + t * 2;
            float v0 = c.acc[mt][nt][0] + sb1[col];
            float v1 = c.acc[mt][nt][1] + sb1[col + 1];
            float v2 = c.acc[mt][nt][2] + sb1[col];
            float v3 = c.acc[mt][nt][3] + sb1[col + 1];
            v0 = v0 > 0.f ? v0 : 0.f; v1 = v1 > 0.f ? v1 : 0.f;
            v2 = v2 > 0.f ? v2 : 0.f; v3 = v3 > 0.f ? v3 : 0.f;
            *(__half2*)(sm + shOff + row * (PB * 2) + col * 2) = __floats2half2_rn(v0, v1);
            *(__half2*)(sm + shOff + (row + 8) * (PB * 2) + col * 2) = __floats2half2_rn(v2, v3);
        }
}

// fp16 writeout of GEMM2 result (bias added), rows n0..n0+127
__device__ __forceinline__ void epi_write_x(MlpCtx& c, char* sm, int b2Off,
                                            __half* __restrict__ xout, int n0) {
    int g = c.lane >> 2, t = c.lane & 3;
    const float* sb2 = (const float*)(sm + b2Off);
#pragma unroll
    for (int mt = 0; mt < 2; mt++)
#pragma unroll
        for (int nt = 0; nt < 8; nt++) {
            int row = c.wm * 32 + mt * 16 + g;
            int col = c.wn * 64 + nt * 8 + t * 2;
            float bb0 = sb2[col], bb1 = sb2[col + 1];
            __half2 h0 = __floats2half2_rn(c.acc[mt][nt][0] + bb0, c.acc[mt][nt][1] + bb1);
            __half2 h1 = __floats2half2_rn(c.acc[mt][nt][2] + bb0, c.acc[mt][nt][3] + bb1);
            *(__half2*)(xout + (size_t)(n0 + row) * HH + col) = h0;
            *(__half2*)(xout + (size_t)(n0 + row + 8) * HH + col) = h1;
        }
}

__global__ void __launch_bounds__(256, 2)
edge_tc(const __half* __restrict__ xh, const void* __restrict__ eidx,
        const uint4* __restrict__ wf1, const uint4* __restrict__ wf2,
        const float* __restrict__ b1, const float* __restrict__ b2,
        float* __restrict__ agg) {
    extern __shared__ __align__(128) char sm[];
    MlpCtx c;
    c.sb = smem_u32(sm);
    int tid = threadIdx.x;
    c.lane = tid & 31;
    int warp = tid >> 5;
    c.wm = warp >> 1; c.wn = warp & 1;

    if (tid < 128) {
        ((float*)(sm + SB1_OFF))[tid] = b1[tid];
        ((float*)(sm + SB2_OFF))[tid] = b2[tid];
    }

    for (int t = 0; t < TPB; t++) {
        // gather: 2 threads per row; h=0 -> x[dst] cols 0-127, h=1 -> x[src]
        {
            int r = tid >> 1, h = tid & 1;
            long long e0 = ((long long)blockIdx.x * TPB + t) * 128 + r;
            int node;
            if (h == 0) {
                node = load_idx(eidx, (long long)EE + e0);
                ((int*)(sm + SDST_OFF))[r] = node;
            } else {
                node = load_idx(eidx, e0);
            }
            const uint4* row = (const uint4*)xh + (size_t)node * 16;
            uint4* dstp = (uint4*)(sm + SA_OFF + r * (PA * 2) + h * 256);
#pragma unroll
            for (int j = 0; j < 16; j++) dstp[j] = __ldg(row + j);
        }
        __syncthreads();

        gemm_zero(c);
        gemm_run(c, SA_OFF, PA * 2, wf1, 16);
        epi_relu_h(c, sm, SH_OFF, SB1_OFF);
        __syncthreads();

        gemm_zero(c);
        gemm_run(c, SH_OFF, PB * 2, wf2, 8);
        __syncthreads();   // all warps done reading H; H region now free

        // staged epilogue: two 64-row passes, f32 in H region, then v4 red
        {
            float* so = (float*)(sm + SH_OFF);
            const float* sb2 = (const float*)(sm + SB2_OFF);
            const int* sdst = (const int*)(sm + SDST_OFF);
            int g = c.lane >> 2, tq = c.lane & 3;
#pragma unroll
            for (int pass = 0; pass < 2; pass++) {
                if ((c.wm >> 1) == pass) {
                    int rbase = (c.wm & 1) * 32;
#pragma unroll
                    for (int mt = 0; mt < 2; mt++)
#pragma unroll
                        for (int nt = 0; nt < 8; nt++) {
                            int row = rbase + mt * 16 + g;
                            int col = c.wn * 64 + nt * 8 + tq * 2;
                            so[row * POUT + col]           = c.acc[mt][nt][0] + sb2[col];
                            so[row * POUT + col + 1]       = c.acc[mt][nt][1] + sb2[col + 1];
                            so[(row + 8) * POUT + col]     = c.acc[mt][nt][2] + sb2[col];
                            so[(row + 8) * POUT + col + 1] = c.acc[mt][nt][3] + sb2[col + 1];
                        }
                }
                __syncthreads();
#pragma unroll
                for (int q = 0; q < 8; q++) {
                    int id = tid + q * 256;            // 0..2047
                    int row = id >> 5, c4 = id & 31;
                    int d = sdst[pass * 64 + row];
                    const float* sp = so + row * POUT + c4 * 4;
                    red_add_v4(agg + (size_t)d * HH + c4 * 4, sp[0], sp[1], sp[2], sp[3]);
                }
                __syncthreads();
            }
        }
    }
}

__global__ void __launch_bounds__(256, 2)
upd_tc(const __half* __restrict__ xh, const float* __restrict__ agg,
       const uint4* __restrict__ wf1, const uint4* __restrict__ wf2,
       const float* __restrict__ b1, const float* __restrict__ b2,
       __half* __restrict__ xout) {
    extern __shared__ __align__(128) char sm[];
    MlpCtx c;
    c.sb = smem_u32(sm);
    int tid = threadIdx.x;
    c.lane = tid & 31;
    int warp = tid >> 5;
    c.wm = warp >> 1; c.wn = warp & 1;

    if (tid < 128) {
        ((float*)(sm + SB1_OFF))[tid] = b1[tid];
        ((float*)(sm + SB2_OFF))[tid] = b2[tid];
    }
    // gather: h=0 -> x row (fp16 copy), h=1 -> agg row (fp32->fp16)
    {
        int r = tid >> 1, h = tid & 1;
        int node = blockIdx.x * 128 + r;
        if (h == 0) {
            const uint4* row = (const uint4*)xh + (size_t)node * 16;
            uint4* dstp = (uint4*)(sm + SA_OFF + r * (PA * 2));
#pragma unroll
            for (int j = 0; j < 16; j++) dstp[j] = __ldg(row + j);
        } else {
            const float4* ar = (const float4*)(agg + (size_t)node * HH);
            uint4* dstp = (uint4*)(sm + SA_OFF + r * (PA * 2) + 256);
#pragma unroll
            for (int j = 0; j < 16; j++) {
                float4 a = __ldg(ar + 2 * j), b = __ldg(ar + 2 * j + 1);
                __half2 h0 = __floats2half2_rn(a.x, a.y), h1 = __floats2half2_rn(a.z, a.w);
                __half2 h2 = __floats2half2_rn(b.x, b.y), h3 = __floats2half2_rn(b.z, b.w);
                uint4 v;
                v.x = *(uint32_t*)&h0; v.y = *(uint32_t*)&h1;
                v.z = *(uint32_t*)&h2; v.w = *(uint32_t*)&h3;
                dstp[j] = v;
            }
        }
    }
    __syncthreads();

    gemm_zero(c);
    gemm_run(c, SA_OFF, PA * 2, wf1, 16);
    epi_relu_h(c, sm, SH_OFF, SB1_OFF);
    __syncthreads();

    gemm_zero(c);
    gemm_run(c, SH_OFF, PB * 2, wf2, 8);
    epi_write_x(c, sm, SB2_OFF, xout, blockIdx.x * 128);
}

// ---------------------------------------------------------------------------
// embed via HMMA: x = relu(in60 @ W1 + b1) @ W2 + b2   (in padded to K=64)
// ---------------------------------------------------------------------------
__global__ void __launch_bounds__(256, 2)
embed_tc(const float* __restrict__ loc, const float* __restrict__ vel,
         const uint4* __restrict__ wf1, const uint4* __restrict__ wf2,
         const float* __restrict__ b1, const float* __restrict__ b2,
         __half* __restrict__ xout) {
    extern __shared__ __align__(128) char sm[];
    MlpCtx c;
    c.sb = smem_u32(sm);
    int tid = threadIdx.x;
    c.lane = tid & 31;
    int warp = tid >> 5;
    c.wm = warp >> 1; c.wn = warp & 1;
    int n0 = blockIdx.x * 128;

    if (tid < 128) {
        ((float*)(sm + EB1_OFF))[tid] = b1[tid];
        ((float*)(sm + EB2_OFF))[tid] = b2[tid];
    }
    if (tid < 128) {
        int r = tid;
        const float* lrow = loc + (size_t)(n0 + r) * 30;
        const float* vrow = vel + (size_t)(n0 + r) * 30;
        __half* drow = (__half*)(sm + EA_OFF + r * (PE * 2));
#pragma unroll
        for (int k = 0; k < 64; k++) {
            float v = 0.f;
            if (k < 60) {
                int f = k / 6, c6 = k % 6;
                v = (c6 < 3) ? lrow[f * 3 + c6] : vrow[f * 3 + c6 - 3];
            }
            drow[k] = __float2half(v);
        }
    }
    __syncthreads();

    gemm_zero(c);
    gemm_run(c, EA_OFF, PE * 2, wf1, 4);
    epi_relu_h(c, sm, EH_OFF, EB1_OFF);
    __syncthreads();

    gemm_zero(c);
    gemm_run(c, EH_OFF, PB * 2, wf2, 8);
    epi_write_x(c, sm, EB2_OFF, xout, n0);
}

// ---------------------------------------------------------------------------
// fp32 head
// ---------------------------------------------------------------------------
#define HS_E (128 * 129)
#define AS_E (128 * 33)
#define WS_E (32 * 128)
#define SMEM_BYTES ((HS_E + AS_E + WS_E) * 4)

__global__ void head_kernel(const __half* __restrict__ x,
                            const float* __restrict__ W1, const float* __restrict__ b1,
                            const float* __restrict__ W2, const float* __restrict__ b2,
                            float* __restrict__ hout) {
    extern __shared__ float smf[];
    float* Hs = smf;
    float* Wh = smf + HS_E;
    float* Ws = smf + HS_E + AS_E;
    int tid = threadIdx.x;
    int n0 = blockIdx.x * 128;
    int tx = tid & 15, ty = tid >> 4;
    float acc[8][8];
#pragma unroll
    for (int i = 0; i < 8; i++)
#pragma unroll
        for (int j = 0; j < 8; j++) acc[i][j] = 0.f;

    for (int kc = 0; kc < 128; kc += 32) {
        for (int t = tid; t < 32 * 128; t += 256) {
            int r = t >> 7, cc = t & 127;
            Ws[t] = W1[(kc + r) * HH + cc];
        }
        __syncthreads();
#pragma unroll
        for (int k = 0; k < 32; k++) {
            float a[8], b[8];
#pragma unroll
            for (int i = 0; i < 8; i++)
                a[i] = __half2float(x[(size_t)(n0 + ty * 8 + i) * HH + kc + k]);
#pragma unroll
            for (int j = 0; j < 8; j++) b[j] = Ws[k * 128 + tx * 8 + j];
#pragma unroll
            for (int i = 0; i < 8; i++)
#pragma unroll
                for (int j = 0; j < 8; j++) acc[i][j] += a[i] * b[j];
        }
        __syncthreads();
    }
#pragma unroll
    for (int i = 0; i < 8; i++)
#pragma unroll
        for (int j = 0; j < 8; j++) {
            float v = acc[i][j] + b1[tx * 8 + j];
            Hs[(ty * 8 + i) * 129 + tx * 8 + j] = v > 0.f ? v : 0.f;
        }
    for (int t = tid; t < 128 * 30; t += 256) Wh[t] = W2[t];
    __syncthreads();
    for (int t = tid; t < 128 * 30; t += 256) {
        int row = t / 30, cc = t % 30;
        float s = b2[cc];
        const float* hr = Hs + row * 129;
#pragma unroll 8
        for (int k = 0; k < 128; k++) s += hr[k] * Wh[k * 30 + cc];
        hout[(size_t)(n0 + row) * 30 + cc] = s;
    }
}

// ---------------------------------------------------------------------------
// loss
// ---------------------------------------------------------------------------
__global__ void loss_kernel(const float* __restrict__ hout, const float* __restrict__ loc,
                            const float* __restrict__ y, float* __restrict__ out) {
    int w = (blockIdx.x * blockDim.x + threadIdx.x) >> 5;
    int lane = threadIdx.x & 31;
    if (w >= BB) return;
    float ade = 0.f, fde = 0.f;
    for (int p = lane; p < 160; p += 32) {
        int node = w * 16 + p / NF;
        int f = p % NF;
        int base = node * 30 + f * 3;
        float dx = hout[base] + loc[base] - y[base];
        float dy = hout[base + 1] + loc[base + 1] - y[base + 1];
        float dz = hout[base + 2] + loc[base + 2] - y[base + 2];
        float d = sqrtf(dx * dx + dy * dy + dz * dz);
        ade += d;
        if (f == NF - 1) fde += d;
    }
#pragma unroll
    for (int o = 16; o; o >>= 1) {
        ade += __shfl_down_sync(0xffffffffu, ade, o);
        fde += __shfl_down_sync(0xffffffffu, fde, o);
    }
    if (lane == 0) {
        out[1 + w] = ade / 160.f;
        out[1 + BB + w] = fde / 16.f;
    }
}

__global__ void final_kernel(float* __restrict__ out) {
    __shared__ float s[256];
    float v = 0.f;
    for (int i = threadIdx.x; i < BB; i += 256) v += out[1 + i];
    s[threadIdx.x] = v;
    __syncthreads();
    for (int o = 128; o; o >>= 1) {
        if (threadIdx.x < o) s[threadIdx.x] += s[threadIdx.x + o];
        __syncthreads();
    }
    if (threadIdx.x == 0) out[0] = s[0] / (float)BB;
}

// ---------------------------------------------------------------------------
// host
// ---------------------------------------------------------------------------
extern "C" void kernel_launch(void* const* d_in, const int* in_sizes, int n_in,
                              void* d_out, int out_size) {
    int o = (n_in > 4 && in_sizes[4] == 1) ? 1 : 0;
    const float* loc = (const float*)d_in[0];
    const float* vel = (const float*)d_in[1];
    const float* y   = (const float*)d_in[2];
    const void*  eix = d_in[3];
    const float* embW1 = (const float*)d_in[4 + o];
    const float* embb1 = (const float*)d_in[5 + o];
    const float* embW2 = (const float*)d_in[6 + o];
    const float* embb2 = (const float*)d_in[7 + o];
    const float* msgW1 = (const float*)d_in[8 + o];
    const float* msgb1 = (const float*)d_in[9 + o];
    const float* msgW2 = (const float*)d_in[10 + o];
    const float* msgb2 = (const float*)d_in[11 + o];
    const float* updW1 = (const float*)d_in[12 + o];
    const float* updb1 = (const float*)d_in[13 + o];
    const float* updW2 = (const float*)d_in[14 + o];
    const float* updb2 = (const float*)d_in[15 + o];
    const float* hW1 = (const float*)d_in[16 + o];
    const float* hb1 = (const float*)d_in[17 + o];
    const float* hW2 = (const float*)d_in[18 + o];
    const float* hb2 = (const float*)d_in[19 + o];
    float* out = (float*)d_out;

    cudaFuncSetAttribute(edge_tc, cudaFuncAttributeMaxDynamicSharedMemorySize, DYNB);
    cudaFuncSetAttribute(upd_tc, cudaFuncAttributeMaxDynamicSharedMemorySize, DYNB);
    cudaFuncSetAttribute(embed_tc, cudaFuncAttributeMaxDynamicSharedMemorySize, DYNB_EM);
    cudaFuncSetAttribute(head_kernel, cudaFuncAttributeMaxDynamicSharedMemorySize, SMEM_BYTES);

    __half *xhp, *xh2p;
    float *aggp, *headp;
    uint4 *mW1f, *mW2f, *uW1f, *uW2f, *eW1f, *eW2f;
    cudaGetSymbolAddress((void**)&xhp, g_xh);
    cudaGetSymbolAddress((void**)&xh2p, g_xh2);
    cudaGetSymbolAddress((void**)&aggp, g_agg);
    cudaGetSymbolAddress((void**)&headp, g_head);
    cudaGetSymbolAddress((void**)&mW1f, g_mW1f);
    cudaGetSymbolAddress((void**)&mW2f, g_mW2f);
    cudaGetSymbolAddress((void**)&uW1f, g_uW1f);
    cudaGetSymbolAddress((void**)&uW2f, g_uW2f);
    cudaGetSymbolAddress((void**)&eW1f, g_eW1f);
    cudaGetSymbolAddress((void**)&eW2f, g_eW2f);

    detect_kernel<<<1, 32>>>((const int*)eix);
    prep_fragk<<<LL, 256>>>(msgW1, (__half*)mW1f, 16, 256, 256 * 128, 32768);
    prep_fragk<<<LL, 256>>>(updW1, (__half*)uW1f, 16, 256, 256 * 128, 32768);
    prep_fragk<<<LL, 256>>>(msgW2, (__half*)mW2f, 8, 128, 128 * 128, 16384);
    prep_fragk<<<LL, 256>>>(updW2, (__half*)uW2f, 8, 128, 128 * 128, 16384);
    prep_fragk<<<1, 256>>>(embW1, (__half*)eW1f, 4, 60, 0, 0);
    prep_fragk<<<1, 256>>>(embW2, (__half*)eW2f, 8, 128, 0, 0);

    embed_tc<<<NN / 128, 256, DYNB_EM>>>(loc, vel, eW1f, eW2f, embb1, embb2, xhp);

    __half* xa = xhp;
    __half* xb = xh2p;
    for (int i = 0; i < LL; i++) {
        cudaMemsetAsync(aggp, 0, (size_t)NN * HH * sizeof(float));
        edge_tc<<<EE / 128 / TPB, 256, DYNB>>>(
            xa, eix,
            mW1f + (size_t)i * 4096, mW2f + (size_t)i * 2048,
            msgb1 + (size_t)i * HH, msgb2 + (size_t)i * HH, aggp);
        upd_tc<<<NN / 128, 256, DYNB>>>(
            xa, aggp,
            uW1f + (size_t)i * 4096, uW2f + (size_t)i * 2048,
            updb1 + (size_t)i * HH, updb2 + (size_t)i * HH, xb);
        __half* t = xa; xa = xb; xb = t;
    }
    head_kernel<<<NN / 128, 256, SMEM_BYTES>>>(xa, hW1, hb1, hW2, hb2, headp);
    loss_kernel<<<(BB * 32 + 127) / 128, 128>>>(headp, loc, y, out);
    final_kernel<<<1, 256>>>(out);
}

// round 9
// speedup vs baseline: 7.1531x; 1.3297x over previous
#include <cuda_runtime.h>
#include <cuda_fp16.h>
#include <math.h>
#include <stdint.h>

#define NN 32768
#define EE 524288
#define HH 128
#define BB 2048
#define LL 7
#define NF 10

// ---------------------------------------------------------------------------
// device scratch
// ---------------------------------------------------------------------------
__device__ int    g_is64;
__device__ __half g_xh[NN * HH];
__device__ __half g_xh2[NN * HH];
__device__ __half g_pd[NN * HH];       // x @ W1_top  (indexed by dst)
__device__ __half g_ps[NN * HH];       // x @ W1_bot  (indexed by src)
__device__ float  g_agg[NN * HH];
__device__ float  g_head[NN * 30];
// fragment-order fp16 weight images (uint4 = one lane's 16B B-fragment)
__device__ uint4 g_mW1f[LL * 4096];
__device__ uint4 g_mW2f[LL * 2048];
__device__ uint4 g_uW1f[LL * 4096];
__device__ uint4 g_uW2f[LL * 2048];
__device__ uint4 g_eW1f[1024];         // K=64 (4 ks)
__device__ uint4 g_eW2f[2048];         // K=128 (8 ks)

// pitches in halfs
#define PA 264   // K=256 + 8 pad
#define PB 136   // K=128 + 8 pad  (272 B)
#define PE 72    // K=64  + 8 pad

// ---- edge kernel smem (bytes): H tile only + ctrl; staging overlays H ----
#define ESH_OFF  0
#define ESB2_OFF (128 * PB * 2)                  // 34816
#define ESD_OFF  (ESB2_OFF + 512)
#define DYNB_E   (ESD_OFF + 512)                 // 35840
#define POUT     132                             // f32 staging pitch (floats), 64 rows

// ---- upd kernel smem ----
#define SA_OFF   0
#define SH_OFF   (128 * PA * 2)                  // 67584
#define SB1_OFF  (SH_OFF + 128 * PB * 2)         // 102400
#define SB2_OFF  (SB1_OFF + 512)
#define DYNB_U   (SB2_OFF + 512)

// ---- pre kernel smem ----
#define DYNB_P   (128 * PB * 2)                  // 34816

// ---- embed smem ----
#define EA_OFF   0
#define EH_OFF   (128 * PE * 2)                  // 18432
#define EB1_OFF  (EH_OFF + 128 * PB * 2)         // 53248
#define EB2_OFF  (EB1_OFF + 512)
#define DYNB_EM  (EB2_OFF + 512)

__device__ __forceinline__ uint32_t smem_u32(const void* p) {
    uint32_t a;
    asm("{ .reg .u64 t; cvta.to.shared.u64 t, %1; cvt.u32.u64 %0, t; }" : "=r"(a) : "l"(p));
    return a;
}

__device__ __forceinline__ void ldsm_x4(uint32_t r[4], uint32_t addr) {
    asm volatile("ldmatrix.sync.aligned.m8n8.x4.shared.b16 {%0,%1,%2,%3}, [%4];"
                 : "=r"(r[0]), "=r"(r[1]), "=r"(r[2]), "=r"(r[3]) : "r"(addr));
}

__device__ __forceinline__ void mma16816(float c[4], const uint32_t a[4],
                                         uint32_t b0, uint32_t b1) {
    asm volatile(
        "mma.sync.aligned.m16n8k16.row.col.f32.f16.f16.f32 "
        "{%0,%1,%2,%3},{%4,%5,%6,%7},{%8,%9},{%0,%1,%2,%3};"
        : "+f"(c[0]), "+f"(c[1]), "+f"(c[2]), "+f"(c[3])
        : "r"(a[0]), "r"(a[1]), "r"(a[2]), "r"(a[3]), "r"(b0), "r"(b1));
}

__device__ __forceinline__ void red_add_v4(float* p, float x, float y, float z, float w) {
    asm volatile("red.global.add.v4.f32 [%0], {%1, %2, %3, %4};"
                 :: "l"(p), "f"(x), "f"(y), "f"(z), "f"(w) : "memory");
}

__device__ __forceinline__ int load_idx(const void* p, long long i) {
    if (g_is64) return (int)((const long long*)p)[i];
    return ((const int*)p)[i];
}

__global__ void detect_kernel(const int* e) {
    if (threadIdx.x == 0) {
        int is64 = 1;
        for (int i = 1; i < 256; i += 2)
            if (e[i] != 0) { is64 = 0; break; }
        g_is64 = is64;
    }
}

// ---------------------------------------------------------------------------
// weight prep: fp32 [k][n=128] -> fragment-order fp16 image
// ---------------------------------------------------------------------------
__global__ void prep_fragk(const float* __restrict__ src, __half* __restrict__ dst,
                           int ksteps, int Ktrue, int srcStride, int dstStride) {
    int l = blockIdx.x;
    src += (size_t)l * srcStride;
    dst += (size_t)l * dstStride;
    int total = ksteps * 2048;
    for (int e = threadIdx.x; e < total; e += blockDim.x) {
        int h = e & 7, lane = (e >> 3) & 31, p = (e >> 8) & 3, wn = (e >> 10) & 1, ks = e >> 11;
        int k = ks * 16 + (lane & 3) * 2 + (h & 1) + ((h >> 1) & 1) * 8;
        int n = wn * 64 + p * 16 + (lane >> 2) + (h >> 2) * 8;
        dst[e] = (k < Ktrue) ? __float2half(src[k * 128 + n]) : __half(0.f);
    }
}

// ---------------------------------------------------------------------------
// HMMA core: 128 rows per tile, 256 threads (8 warps, warp tile 32x64)
// ---------------------------------------------------------------------------
struct MlpCtx {
    uint32_t sb;
    int lane, wm, wn;
    float acc[2][8][4];
};

__device__ __forceinline__ void gemm_zero(MlpCtx& c) {
#pragma unroll
    for (int mt = 0; mt < 2; mt++)
#pragma unroll
        for (int nt = 0; nt < 8; nt++)
#pragma unroll
            for (int q = 0; q < 4; q++) c.acc[mt][nt][q] = 0.f;
}

__device__ __forceinline__ void gemm_run(MlpCtx& c, uint32_t aoff, uint32_t pbytes,
                                         const uint4* __restrict__ wf, int ksteps) {
    int l = c.lane;
    uint32_t aBase = c.sb + aoff +
        (uint32_t)(c.wm * 32 + (l & 7) + ((l >> 3) & 1) * 8) * pbytes + (l >> 4) * 16;
    const uint4* wb = wf + c.wn * 128 + l;
#pragma unroll
    for (int ks = 0; ks < 16; ks++) {
        if (ks >= ksteps) break;
        uint32_t a0[4], a1[4];
        uint4 q[4];
#pragma unroll
        for (int p = 0; p < 4; p++) q[p] = __ldg(wb + ks * 256 + p * 32);
        ldsm_x4(a0, aBase + ks * 32);
        ldsm_x4(a1, aBase + 16 * pbytes + ks * 32);
#pragma unroll
        for (int p = 0; p < 4; p++) {
            mma16816(c.acc[0][2 * p],     a0, q[p].x, q[p].y);
            mma16816(c.acc[0][2 * p + 1], a0, q[p].z, q[p].w);
            mma16816(c.acc[1][2 * p],     a1, q[p].x, q[p].y);
            mma16816(c.acc[1][2 * p + 1], a1, q[p].z, q[p].w);
        }
    }
}

__device__ __forceinline__ void epi_relu_h(MlpCtx& c, char* sm, int shOff, int b1Off) {
    int g = c.lane >> 2, t = c.lane & 3;
    const float* sb1 = (const float*)(sm + b1Off);
#pragma unroll
    for (int mt = 0; mt < 2; mt++)
#pragma unroll
        for (int nt = 0; nt < 8; nt++) {
            int row = c.wm * 32 + mt * 16 + g;
            int col = c.wn * 64 + nt * 8 + t * 2;
            float v0 = c.acc[mt][nt][0] + sb1[col];
            float v1 = c.acc[mt][nt][1] + sb1[col + 1];
            float v2 = c.acc[mt][nt][2] + sb1[col];
            float v3 = c.acc[mt][nt][3] + sb1[col + 1];
            v0 = v0 > 0.f ? v0 : 0.f; v1 = v1 > 0.f ? v1 : 0.f;
            v2 = v2 > 0.f ? v2 : 0.f; v3 = v3 > 0.f ? v3 : 0.f;
            *(__half2*)(sm + shOff + row * (PB * 2) + col * 2) = __floats2half2_rn(v0, v1);
            *(__half2*)(sm + shOff + (row + 8) * (PB * 2) + col * 2) = __floats2half2_rn(v2, v3);
        }
}

__device__ __forceinline__ void epi_write_x(MlpCtx& c, char* sm, int b2Off,
                                            __half* __restrict__ xout, int n0) {
    int g = c.lane >> 2, t = c.lane & 3;
    const float* sb2 = (const float*)(sm + b2Off);
#pragma unroll
    for (int mt = 0; mt < 2; mt++)
#pragma unroll
        for (int nt = 0; nt < 8; nt++) {
            int row = c.wm * 32 + mt * 16 + g;
            int col = c.wn * 64 + nt * 8 + t * 2;
            float bb0 = sb2[col], bb1 = sb2[col + 1];
            __half2 h0 = __floats2half2_rn(c.acc[mt][nt][0] + bb0, c.acc[mt][nt][1] + bb1);
            __half2 h1 = __floats2half2_rn(c.acc[mt][nt][2] + bb0, c.acc[mt][nt][3] + bb1);
            *(__half2*)(xout + (size_t)(n0 + row) * HH + col) = h0;
            *(__half2*)(xout + (size_t)(n0 + row + 8) * HH + col) = h1;
        }
}

// ---------------------------------------------------------------------------
// pre kernel: P = x @ W1half  (no bias), fp16 out.  blockIdx.y selects half.
// ---------------------------------------------------------------------------
__global__ void __launch_bounds__(256, 2)
pre_tc(const __half* __restrict__ xh, const uint4* __restrict__ wf1,
       __half* __restrict__ pd, __half* __restrict__ ps) {
    extern __shared__ __align__(128) char sm[];
    MlpCtx c;
    c.sb = smem_u32(sm);
    int tid = threadIdx.x;
    c.lane = tid & 31;
    int warp = tid >> 5;
    c.wm = warp >> 1; c.wn = warp & 1;
    int n0 = blockIdx.x * 128;
    const uint4* wf = wf1 + blockIdx.y * 2048;    // top / bottom half of W1
    __half* pout = blockIdx.y ? ps : pd;

    // stage x rows (2 threads/row)
    {
        int r = tid >> 1, h = tid & 1;
        const uint4* row = (const uint4*)xh + (size_t)(n0 + r) * 16 + h * 8;
        uint4* dstp = (uint4*)(sm + r * (PB * 2)) + h * 8;
#pragma unroll
        for (int j = 0; j < 8; j++) dstp[j] = __ldg(row + j);
    }
    __syncthreads();

    gemm_zero(c);
    gemm_run(c, 0, PB * 2, wf, 8);

    // raw fp16 writeout (no bias)
    {
        int g = c.lane >> 2, t = c.lane & 3;
#pragma unroll
        for (int mt = 0; mt < 2; mt++)
#pragma unroll
            for (int nt = 0; nt < 8; nt++) {
                int row = c.wm * 32 + mt * 16 + g;
                int col = c.wn * 64 + nt * 8 + t * 2;
                __half2 h0 = __floats2half2_rn(c.acc[mt][nt][0], c.acc[mt][nt][1]);
                __half2 h1 = __floats2half2_rn(c.acc[mt][nt][2], c.acc[mt][nt][3]);
                *(__half2*)(pout + (size_t)(n0 + row) * HH + col) = h0;
                *(__half2*)(pout + (size_t)(n0 + row + 8) * HH + col) = h1;
            }
    }
}

// ---------------------------------------------------------------------------
// edge kernel: H = relu(pd[dst] + ps[src] + b1); out = H @ W2 + b2 -> scatter
// ---------------------------------------------------------------------------
__global__ void __launch_bounds__(256, 2)
edge_tc(const __half* __restrict__ pd, const __half* __restrict__ ps,
        const void* __restrict__ eidx, const uint4* __restrict__ wf2,
        const float* __restrict__ b1, const float* __restrict__ b2,
        float* __restrict__ agg) {
    extern __shared__ __align__(128) char sm[];
    MlpCtx c;
    c.sb = smem_u32(sm);
    int tid = threadIdx.x;
    c.lane = tid & 31;
    int warp = tid >> 5;
    c.wm = warp >> 1; c.wn = warp & 1;

    if (tid < 128) ((float*)(sm + ESB2_OFF))[tid] = b2[tid];

    // build H: 2 threads/row, each handles 64 cols
    {
        int r = tid >> 1, h = tid & 1;
        long long e0 = (long long)blockIdx.x * 128 + r;
        int dstn = load_idx(eidx, (long long)EE + e0);
        int srcn = load_idx(eidx, e0);
        if (h == 0) ((int*)(sm + ESD_OFF))[r] = dstn;
        const uint4* prow = (const uint4*)(pd + (size_t)dstn * HH) + h * 8;
        const uint4* srow = (const uint4*)(ps + (size_t)srcn * HH) + h * 8;
        uint4* hrow = (uint4*)(sm + ESH_OFF + r * (PB * 2)) + h * 8;
#pragma unroll
        for (int j = 0; j < 8; j++) {
            uint4 pv = __ldg(prow + j);
            uint4 sv = __ldg(srow + j);
            const __half2* pp = (const __half2*)&pv;
            const __half2* ss = (const __half2*)&sv;
            uint4 o;
            __half2* oo = (__half2*)&o;
#pragma unroll
            for (int q = 0; q < 4; q++) {
                float2 a = __half22float2(pp[q]);
                float2 b = __half22float2(ss[q]);
                int col = h * 64 + j * 8 + q * 2;
                float v0 = a.x + b.x + __ldg(b1 + col);
                float v1 = a.y + b.y + __ldg(b1 + col + 1);
                v0 = fmaxf(v0, 0.f);
                v1 = fmaxf(v1, 0.f);
                oo[q] = __floats2half2_rn(v0, v1);
            }
            hrow[j] = o;
        }
    }
    __syncthreads();

    gemm_zero(c);
    gemm_run(c, ESH_OFF, PB * 2, wf2, 8);
    __syncthreads();   // H no longer needed; region becomes f32 staging

    // staged epilogue: two 64-row passes, f32 staging in H region, v4 red
    {
        float* so = (float*)(sm + ESH_OFF);
        const float* sb2 = (const float*)(sm + ESB2_OFF);
        const int* sdst = (const int*)(sm + ESD_OFF);
        int g = c.lane >> 2, tq = c.lane & 3;
#pragma unroll
        for (int pass = 0; pass < 2; pass++) {
            if ((c.wm >> 1) == pass) {
                int rbase = (c.wm & 1) * 32;
#pragma unroll
                for (int mt = 0; mt < 2; mt++)
#pragma unroll
                    for (int nt = 0; nt < 8; nt++) {
                        int row = rbase + mt * 16 + g;
                        int col = c.wn * 64 + nt * 8 + tq * 2;
                        so[row * POUT + col]           = c.acc[mt][nt][0] + sb2[col];
                        so[row * POUT + col + 1]       = c.acc[mt][nt][1] + sb2[col + 1];
                        so[(row + 8) * POUT + col]     = c.acc[mt][nt][2] + sb2[col];
                        so[(row + 8) * POUT + col + 1] = c.acc[mt][nt][3] + sb2[col + 1];
                    }
            }
            __syncthreads();
#pragma unroll
            for (int q = 0; q < 8; q++) {
                int id = tid + q * 256;            // 0..2047
                int row = id >> 5, c4 = id & 31;
                int d = sdst[pass * 64 + row];
                const float* sp = so + row * POUT + c4 * 4;
                red_add_v4(agg + (size_t)d * HH + c4 * 4, sp[0], sp[1], sp[2], sp[3]);
            }
            __syncthreads();
        }
    }
}

// ---------------------------------------------------------------------------
// upd kernel (unchanged structure)
// ---------------------------------------------------------------------------
__global__ void __launch_bounds__(256, 2)
upd_tc(const __half* __restrict__ xh, const float* __restrict__ agg,
       const uint4* __restrict__ wf1, const uint4* __restrict__ wf2,
       const float* __restrict__ b1, const float* __restrict__ b2,
       __half* __restrict__ xout) {
    extern __shared__ __align__(128) char sm[];
    MlpCtx c;
    c.sb = smem_u32(sm);
    int tid = threadIdx.x;
    c.lane = tid & 31;
    int warp = tid >> 5;
    c.wm = warp >> 1; c.wn = warp & 1;

    if (tid < 128) {
        ((float*)(sm + SB1_OFF))[tid] = b1[tid];
        ((float*)(sm + SB2_OFF))[tid] = b2[tid];
    }
    {
        int r = tid >> 1, h = tid & 1;
        int node = blockIdx.x * 128 + r;
        if (h == 0) {
            const uint4* row = (const uint4*)xh + (size_t)node * 16;
            uint4* dstp = (uint4*)(sm + SA_OFF + r * (PA * 2));
#pragma unroll
            for (int j = 0; j < 16; j++) dstp[j] = __ldg(row + j);
        } else {
            const float4* ar = (const float4*)(agg + (size_t)node * HH);
            uint4* dstp = (uint4*)(sm + SA_OFF + r * (PA * 2) + 256);
#pragma unroll
            for (int j = 0; j < 16; j++) {
                float4 a = __ldg(ar + 2 * j), b = __ldg(ar + 2 * j + 1);
                __half2 h0 = __floats2half2_rn(a.x, a.y), h1 = __floats2half2_rn(a.z, a.w);
                __half2 h2 = __floats2half2_rn(b.x, b.y), h3 = __floats2half2_rn(b.z, b.w);
                uint4 v;
                v.x = *(uint32_t*)&h0; v.y = *(uint32_t*)&h1;
                v.z = *(uint32_t*)&h2; v.w = *(uint32_t*)&h3;
                dstp[j] = v;
            }
        }
    }
    __syncthreads();

    gemm_zero(c);
    gemm_run(c, SA_OFF, PA * 2, wf1, 16);
    epi_relu_h(c, sm, SH_OFF, SB1_OFF);
    __syncthreads();

    gemm_zero(c);
    gemm_run(c, SH_OFF, PB * 2, wf2, 8);
    epi_write_x(c, sm, SB2_OFF, xout, blockIdx.x * 128);
}

// ---------------------------------------------------------------------------
// embed via HMMA
// ---------------------------------------------------------------------------
__global__ void __launch_bounds__(256, 2)
embed_tc(const float* __restrict__ loc, const float* __restrict__ vel,
         const uint4* __restrict__ wf1, const uint4* __restrict__ wf2,
         const float* __restrict__ b1, const float* __restrict__ b2,
         __half* __restrict__ xout) {
    extern __shared__ __align__(128) char sm[];
    MlpCtx c;
    c.sb = smem_u32(sm);
    int tid = threadIdx.x;
    c.lane = tid & 31;
    int warp = tid >> 5;
    c.wm = warp >> 1; c.wn = warp & 1;
    int n0 = blockIdx.x * 128;

    if (tid < 128) {
        ((float*)(sm + EB1_OFF))[tid] = b1[tid];
        ((float*)(sm + EB2_OFF))[tid] = b2[tid];
    }
    if (tid < 128) {
        int r = tid;
        const float* lrow = loc + (size_t)(n0 + r) * 30;
        const float* vrow = vel + (size_t)(n0 + r) * 30;
        __half* drow = (__half*)(sm + EA_OFF + r * (PE * 2));
#pragma unroll
        for (int k = 0; k < 64; k++) {
            float v = 0.f;
            if (k < 60) {
                int f = k / 6, c6 = k % 6;
                v = (c6 < 3) ? lrow[f * 3 + c6] : vrow[f * 3 + c6 - 3];
            }
            drow[k] = __float2half(v);
        }
    }
    __syncthreads();

    gemm_zero(c);
    gemm_run(c, EA_OFF, PE * 2, wf1, 4);
    epi_relu_h(c, sm, EH_OFF, EB1_OFF);
    __syncthreads();

    gemm_zero(c);
    gemm_run(c, EH_OFF, PB * 2, wf2, 8);
    epi_write_x(c, sm, EB2_OFF, xout, n0);
}

// ---------------------------------------------------------------------------
// fp32 head
// ---------------------------------------------------------------------------
#define HS_E (128 * 129)
#define AS_E (128 * 33)
#define WS_E (32 * 128)
#define SMEM_BYTES ((HS_E + AS_E + WS_E) * 4)

__global__ void head_kernel(const __half* __restrict__ x,
                            const float* __restrict__ W1, const float* __restrict__ b1,
                            const float* __restrict__ W2, const float* __restrict__ b2,
                            float* __restrict__ hout) {
    extern __shared__ float smf[];
    float* Hs = smf;
    float* Wh = smf + HS_E;
    float* Ws = smf + HS_E + AS_E;
    int tid = threadIdx.x;
    int n0 = blockIdx.x * 128;
    int tx = tid & 15, ty = tid >> 4;
    float acc[8][8];
#pragma unroll
    for (int i = 0; i < 8; i++)
#pragma unroll
        for (int j = 0; j < 8; j++) acc[i][j] = 0.f;

    for (int kc = 0; kc < 128; kc += 32) {
        for (int t = tid; t < 32 * 128; t += 256) {
            int r = t >> 7, cc = t & 127;
            Ws[t] = W1[(kc + r) * HH + cc];
        }
        __syncthreads();
#pragma unroll
        for (int k = 0; k < 32; k++) {
            float a[8], b[8];
#pragma unroll
            for (int i = 0; i < 8; i++)
                a[i] = __half2float(x[(size_t)(n0 + ty * 8 + i) * HH + kc + k]);
#pragma unroll
            for (int j = 0; j < 8; j++) b[j] = Ws[k * 128 + tx * 8 + j];
#pragma unroll
            for (int i = 0; i < 8; i++)
#pragma unroll
                for (int j = 0; j < 8; j++) acc[i][j] += a[i] * b[j];
        }
        __syncthreads();
    }
#pragma unroll
    for (int i = 0; i < 8; i++)
#pragma unroll
        for (int j = 0; j < 8; j++) {
            float v = acc[i][j] + b1[tx * 8 + j];
            Hs[(ty * 8 + i) * 129 + tx * 8 + j] = v > 0.f ? v : 0.f;
        }
    for (int t = tid; t < 128 * 30; t += 256) Wh[t] = W2[t];
    __syncthreads();
    for (int t = tid; t < 128 * 30; t += 256) {
        int row = t / 30, cc = t % 30;
        float s = b2[cc];
        const float* hr = Hs + row * 129;
#pragma unroll 8
        for (int k = 0; k < 128; k++) s += hr[k] * Wh[k * 30 + cc];
        hout[(size_t)(n0 + row) * 30 + cc] = s;
    }
}

// ---------------------------------------------------------------------------
// loss
// ---------------------------------------------------------------------------
__global__ void loss_kernel(const float* __restrict__ hout, const float* __restrict__ loc,
                            const float* __restrict__ y, float* __restrict__ out) {
    int w = (blockIdx.x * blockDim.x + threadIdx.x) >> 5;
    int lane = threadIdx.x & 31;
    if (w >= BB) return;
    float ade = 0.f, fde = 0.f;
    for (int p = lane; p < 160; p += 32) {
        int node = w * 16 + p / NF;
        int f = p % NF;
        int base = node * 30 + f * 3;
        float dx = hout[base] + loc[base] - y[base];
        float dy = hout[base + 1] + loc[base + 1] - y[base + 1];
        float dz = hout[base + 2] + loc[base + 2] - y[base + 2];
        float d = sqrtf(dx * dx + dy * dy + dz * dz);
        ade += d;
        if (f == NF - 1) fde += d;
    }
#pragma unroll
    for (int o = 16; o; o >>= 1) {
        ade += __shfl_down_sync(0xffffffffu, ade, o);
        fde += __shfl_down_sync(0xffffffffu, fde, o);
    }
    if (lane == 0) {
        out[1 + w] = ade / 160.f;
        out[1 + BB + w] = fde / 16.f;
    }
}

__global__ void final_kernel(float* __restrict__ out) {
    __shared__ float s[256];
    float v = 0.f;
    for (int i = threadIdx.x; i < BB; i += 256) v += out[1 + i];
    s[threadIdx.x] = v;
    __syncthreads();
    for (int o = 128; o; o >>= 1) {
        if (threadIdx.x < o) s[threadIdx.x] += s[threadIdx.x + o];
        __syncthreads();
    }
    if (threadIdx.x == 0) out[0] = s[0] / (float)BB;
}

// ---------------------------------------------------------------------------
// host
// ---------------------------------------------------------------------------
extern "C" void kernel_launch(void* const* d_in, const int* in_sizes, int n_in,
                              void* d_out, int out_size) {
    int o = (n_in > 4 && in_sizes[4] == 1) ? 1 : 0;
    const float* loc = (const float*)d_in[0];
    const float* vel = (const float*)d_in[1];
    const float* y   = (const float*)d_in[2];
    const void*  eix = d_in[3];
    const float* embW1 = (const float*)d_in[4 + o];
    const float* embb1 = (const float*)d_in[5 + o];
    const float* embW2 = (const float*)d_in[6 + o];
    const float* embb2 = (const float*)d_in[7 + o];
    const float* msgW1 = (const float*)d_in[8 + o];
    const float* msgb1 = (const float*)d_in[9 + o];
    const float* msgW2 = (const float*)d_in[10 + o];
    const float* msgb2 = (const float*)d_in[11 + o];
    const float* updW1 = (const float*)d_in[12 + o];
    const float* updb1 = (const float*)d_in[13 + o];
    const float* updW2 = (const float*)d_in[14 + o];
    const float* updb2 = (const float*)d_in[15 + o];
    const float* hW1 = (const float*)d_in[16 + o];
    const float* hb1 = (const float*)d_in[17 + o];
    const float* hW2 = (const float*)d_in[18 + o];
    const float* hb2 = (const float*)d_in[19 + o];
    float* out = (float*)d_out;

    cudaFuncSetAttribute(edge_tc, cudaFuncAttributeMaxDynamicSharedMemorySize, DYNB_E);
    cudaFuncSetAttribute(upd_tc, cudaFuncAttributeMaxDynamicSharedMemorySize, DYNB_U);
    cudaFuncSetAttribute(pre_tc, cudaFuncAttributeMaxDynamicSharedMemorySize, DYNB_P);
    cudaFuncSetAttribute(embed_tc, cudaFuncAttributeMaxDynamicSharedMemorySize, DYNB_EM);
    cudaFuncSetAttribute(head_kernel, cudaFuncAttributeMaxDynamicSharedMemorySize, SMEM_BYTES);

    __half *xhp, *xh2p, *pdp, *psp;
    float *aggp, *headp;
    uint4 *mW1f, *mW2f, *uW1f, *uW2f, *eW1f, *eW2f;
    cudaGetSymbolAddress((void**)&xhp, g_xh);
    cudaGetSymbolAddress((void**)&xh2p, g_xh2);
    cudaGetSymbolAddress((void**)&pdp, g_pd);
    cudaGetSymbolAddress((void**)&psp, g_ps);
    cudaGetSymbolAddress((void**)&aggp, g_agg);
    cudaGetSymbolAddress((void**)&headp, g_head);
    cudaGetSymbolAddress((void**)&mW1f, g_mW1f);
    cudaGetSymbolAddress((void**)&mW2f, g_mW2f);
    cudaGetSymbolAddress((void**)&uW1f, g_uW1f);
    cudaGetSymbolAddress((void**)&uW2f, g_uW2f);
    cudaGetSymbolAddress((void**)&eW1f, g_eW1f);
    cudaGetSymbolAddress((void**)&eW2f, g_eW2f);

    detect_kernel<<<1, 32>>>((const int*)eix);
    prep_fragk<<<LL, 256>>>(msgW1, (__half*)mW1f, 16, 256, 256 * 128, 32768);
    prep_fragk<<<LL, 256>>>(updW1, (__half*)uW1f, 16, 256, 256 * 128, 32768);
    prep_fragk<<<LL, 256>>>(msgW2, (__half*)mW2f, 8, 128, 128 * 128, 16384);
    prep_fragk<<<LL, 256>>>(updW2, (__half*)uW2f, 8, 128, 128 * 128, 16384);
    prep_fragk<<<1, 256>>>(embW1, (__half*)eW1f, 4, 60, 0, 0);
    prep_fragk<<<1, 256>>>(embW2, (__half*)eW2f, 8, 128, 0, 0);

    embed_tc<<<NN / 128, 256, DYNB_EM>>>(loc, vel, eW1f, eW2f, embb1, embb2, xhp);

    __half* xa = xhp;
    __half* xb = xh2p;
    for (int i = 0; i < LL; i++) {
        cudaMemsetAsync(aggp, 0, (size_t)NN * HH * sizeof(float));
        pre_tc<<<dim3(NN / 128, 2), 256, DYNB_P>>>(xa, mW1f + (size_t)i * 4096, pdp, psp);
        edge_tc<<<EE / 128, 256, DYNB_E>>>(
            pdp, psp, eix, mW2f + (size_t)i * 2048,
            msgb1 + (size_t)i * HH, msgb2 + (size_t)i * HH, aggp);
        upd_tc<<<NN / 128, 256, DYNB_U>>>(
            xa, aggp,
            uW1f + (size_t)i * 4096, uW2f + (size_t)i * 2048,
            updb1 + (size_t)i * HH, updb2 + (size_t)i * HH, xb);
        __half* t = xa; xa = xb; xb = t;
    }
    head_kernel<<<NN / 128, 256, SMEM_BYTES>>>(xa, hW1, hb1, hW2, hb2, headp);
    loss_kernel<<<(BB * 32 + 127) / 128, 128>>>(headp, loc, y, out);
    final_kernel<<<1, 256>>>(out);
}

// round 10
// speedup vs baseline: 7.3893x; 1.0330x over previous
#include <cuda_runtime.h>
#include <cuda_fp16.h>
#include <math.h>
#include <stdint.h>

#define NN 32768
#define EE 524288
#define HH 128
#define BB 2048
#define LL 7
#define NF 10

// ---------------------------------------------------------------------------
// device scratch
// ---------------------------------------------------------------------------
__device__ int    g_is64;
__device__ __half g_xh[NN * HH];
__device__ __half g_xh2[NN * HH];
__device__ __half g_pd[NN * HH];       // x @ W1_top  (indexed by dst)
__device__ __half g_ps[NN * HH];       // x @ W1_bot  (indexed by src)
__device__ float  g_agg[NN * HH];
__device__ float  g_head[NN * 30];
// fragment-order fp16 weight images (uint4 = one lane's 16B B-fragment)
__device__ uint4 g_mW1f[LL * 4096];
__device__ uint4 g_mW2f[LL * 2048];
__device__ uint4 g_uW1f[LL * 4096];
__device__ uint4 g_uW2f[LL * 2048];
__device__ uint4 g_eW1f[1024];         // K=64 (4 ks)
__device__ uint4 g_eW2f[2048];         // K=128 (8 ks)
__device__ uint4 g_hW1f[2048];         // head W1, K=128
__device__ uint4 g_hW2f[2048];         // head W2, K=128, N=30 (padded)

// pitches in halfs
#define PA 264   // K=256 + 8 pad
#define PB 136   // K=128 + 8 pad  (272 B)
#define PE 72    // K=64  + 8 pad

// ---- edge kernel smem (bytes) ----
#define ESH_OFF  0
#define ESB1_OFF (128 * PB * 2)                  // 34816
#define ESB2_OFF (ESB1_OFF + 512)
#define ESD_OFF  (ESB2_OFF + 512)
#define DYNB_E   (ESD_OFF + 512)                 // 36352
#define POUT     132                             // f32 staging pitch (floats)

// ---- upd kernel smem ----
#define SA_OFF   0
#define SH_OFF   (128 * PA * 2)                  // 67584
#define SB1_OFF  (SH_OFF + 128 * PB * 2)         // 102400
#define SB2_OFF  (SB1_OFF + 512)
#define DYNB_U   (SB2_OFF + 512)

// ---- embed smem ----
#define EA_OFF   0
#define EH_OFF   (128 * PE * 2)                  // 18432
#define EB1_OFF  (EH_OFF + 128 * PB * 2)         // 53248
#define EB2_OFF  (EB1_OFF + 512)
#define DYNB_EM  (EB2_OFF + 512)

// ---- head smem ----
#define HA_OFF   0
#define HHS_OFF  (128 * PB * 2)                  // 34816
#define HB1_OFF  (HHS_OFF + 128 * PB * 2)        // 69632
#define HB2_OFF  (HB1_OFF + 512)
#define DYNB_H   (HB2_OFF + 512)

__device__ __forceinline__ uint32_t smem_u32(const void* p) {
    uint32_t a;
    asm("{ .reg .u64 t; cvta.to.shared.u64 t, %1; cvt.u32.u64 %0, t; }" : "=r"(a) : "l"(p));
    return a;
}

__device__ __forceinline__ void ldsm_x4(uint32_t r[4], uint32_t addr) {
    asm volatile("ldmatrix.sync.aligned.m8n8.x4.shared.b16 {%0,%1,%2,%3}, [%4];"
                 : "=r"(r[0]), "=r"(r[1]), "=r"(r[2]), "=r"(r[3]) : "r"(addr));
}

__device__ __forceinline__ void mma16816(float c[4], const uint32_t a[4],
                                         uint32_t b0, uint32_t b1) {
    asm volatile(
        "mma.sync.aligned.m16n8k16.row.col.f32.f16.f16.f32 "
        "{%0,%1,%2,%3},{%4,%5,%6,%7},{%8,%9},{%0,%1,%2,%3};"
        : "+f"(c[0]), "+f"(c[1]), "+f"(c[2]), "+f"(c[3])
        : "r"(a[0]), "r"(a[1]), "r"(a[2]), "r"(a[3]), "r"(b0), "r"(b1));
}

__device__ __forceinline__ void red_add_v4(float* p, float x, float y, float z, float w) {
    asm volatile("red.global.add.v4.f32 [%0], {%1, %2, %3, %4};"
                 :: "l"(p), "f"(x), "f"(y), "f"(z), "f"(w) : "memory");
}

__device__ __forceinline__ int load_idx(const void* p, long long i) {
    if (g_is64) return (int)((const long long*)p)[i];
    return ((const int*)p)[i];
}

__global__ void detect_kernel(const int* e) {
    if (threadIdx.x == 0) {
        int is64 = 1;
        for (int i = 1; i < 256; i += 2)
            if (e[i] != 0) { is64 = 0; break; }
        g_is64 = is64;
    }
}

// ---------------------------------------------------------------------------
// weight prep: fp32 [k][n] -> fragment-order fp16 image
// ---------------------------------------------------------------------------
__global__ void prep_fragk(const float* __restrict__ src, __half* __restrict__ dst,
                           int ksteps, int Ktrue, int Ntrue, int srcWidth,
                           int srcStride, int dstStride) {
    int l = blockIdx.x;
    src += (size_t)l * srcStride;
    dst += (size_t)l * dstStride;
    int total = ksteps * 2048;
    for (int e = threadIdx.x; e < total; e += blockDim.x) {
        int h = e & 7, lane = (e >> 3) & 31, p = (e >> 8) & 3, wn = (e >> 10) & 1, ks = e >> 11;
        int k = ks * 16 + (lane & 3) * 2 + (h & 1) + ((h >> 1) & 1) * 8;
        int n = wn * 64 + p * 16 + (lane >> 2) + (h >> 2) * 8;
        dst[e] = (k < Ktrue && n < Ntrue) ? __float2half(src[k * srcWidth + n]) : __half(0.f);
    }
}

// ---------------------------------------------------------------------------
// HMMA core: 128 rows per tile, 256 threads (8 warps, warp tile 32x64)
// ---------------------------------------------------------------------------
struct MlpCtx {
    uint32_t sb;
    int lane, wm, wn;
    float acc[2][8][4];
};

__device__ __forceinline__ void gemm_zero(MlpCtx& c) {
#pragma unroll
    for (int mt = 0; mt < 2; mt++)
#pragma unroll
        for (int nt = 0; nt < 8; nt++)
#pragma unroll
            for (int q = 0; q < 4; q++) c.acc[mt][nt][q] = 0.f;
}

__device__ __forceinline__ void gemm_run(MlpCtx& c, uint32_t aoff, uint32_t pbytes,
                                         const uint4* __restrict__ wf, int ksteps) {
    int l = c.lane;
    uint32_t aBase = c.sb + aoff +
        (uint32_t)(c.wm * 32 + (l & 7) + ((l >> 3) & 1) * 8) * pbytes + (l >> 4) * 16;
    const uint4* wb = wf + c.wn * 128 + l;
#pragma unroll
    for (int ks = 0; ks < 16; ks++) {
        if (ks >= ksteps) break;
        uint32_t a0[4], a1[4];
        uint4 q[4];
#pragma unroll
        for (int p = 0; p < 4; p++) q[p] = __ldg(wb + ks * 256 + p * 32);
        ldsm_x4(a0, aBase + ks * 32);
        ldsm_x4(a1, aBase + 16 * pbytes + ks * 32);
#pragma unroll
        for (int p = 0; p < 4; p++) {
            mma16816(c.acc[0][2 * p],     a0, q[p].x, q[p].y);
            mma16816(c.acc[0][2 * p + 1], a0, q[p].z, q[p].w);
            mma16816(c.acc[1][2 * p],     a1, q[p].x, q[p].y);
            mma16816(c.acc[1][2 * p + 1], a1, q[p].z, q[p].w);
        }
    }
}

__device__ __forceinline__ void epi_relu_h(MlpCtx& c, char* sm, int shOff, int b1Off) {
    int g = c.lane >> 2, t = c.lane & 3;
    const float* sb1 = (const float*)(sm + b1Off);
#pragma unroll
    for (int mt = 0; mt < 2; mt++)
#pragma unroll
        for (int nt = 0; nt < 8; nt++) {
            int row = c.wm * 32 + mt * 16 + g;
            int col = c.wn * 64 + nt * 8 + t * 2;
            float v0 = c.acc[mt][nt][0] + sb1[col];
            float v1 = c.acc[mt][nt][1] + sb1[col + 1];
            float v2 = c.acc[mt][nt][2] + sb1[col];
            float v3 = c.acc[mt][nt][3] + sb1[col + 1];
            v0 = v0 > 0.f ? v0 : 0.f; v1 = v1 > 0.f ? v1 : 0.f;
            v2 = v2 > 0.f ? v2 : 0.f; v3 = v3 > 0.f ? v3 : 0.f;
            *(__half2*)(sm + shOff + row * (PB * 2) + col * 2) = __floats2half2_rn(v0, v1);
            *(__half2*)(sm + shOff + (row + 8) * (PB * 2) + col * 2) = __floats2half2_rn(v2, v3);
        }
}

// write x (bias added) to global AND stage fp16 tile (PB pitch) at stageOff
__device__ __forceinline__ void epi_write_x_stage(MlpCtx& c, char* sm, int b2Off,
                                                  __half* __restrict__ xout, int n0,
                                                  int stageOff, bool doStage) {
    int g = c.lane >> 2, t = c.lane & 3;
    const float* sb2 = (const float*)(sm + b2Off);
#pragma unroll
    for (int mt = 0; mt < 2; mt++)
#pragma unroll
        for (int nt = 0; nt < 8; nt++) {
            int row = c.wm * 32 + mt * 16 + g;
            int col = c.wn * 64 + nt * 8 + t * 2;
            float bb0 = sb2[col], bb1 = sb2[col + 1];
            __half2 h0 = __floats2half2_rn(c.acc[mt][nt][0] + bb0, c.acc[mt][nt][1] + bb1);
            __half2 h1 = __floats2half2_rn(c.acc[mt][nt][2] + bb0, c.acc[mt][nt][3] + bb1);
            *(__half2*)(xout + (size_t)(n0 + row) * HH + col) = h0;
            *(__half2*)(xout + (size_t)(n0 + row + 8) * HH + col) = h1;
            if (doStage) {
                *(__half2*)(sm + stageOff + row * (PB * 2) + col * 2) = h0;
                *(__half2*)(sm + stageOff + (row + 8) * (PB * 2) + col * 2) = h1;
            }
        }
}

// raw fp16 writeout (no bias) -> pd/ps
__device__ __forceinline__ void epi_write_raw(MlpCtx& c, __half* __restrict__ pout, int n0) {
    int g = c.lane >> 2, t = c.lane & 3;
#pragma unroll
    for (int mt = 0; mt < 2; mt++)
#pragma unroll
        for (int nt = 0; nt < 8; nt++) {
            int row = c.wm * 32 + mt * 16 + g;
            int col = c.wn * 64 + nt * 8 + t * 2;
            __half2 h0 = __floats2half2_rn(c.acc[mt][nt][0], c.acc[mt][nt][1]);
            __half2 h1 = __floats2half2_rn(c.acc[mt][nt][2], c.acc[mt][nt][3]);
            *(__half2*)(pout + (size_t)(n0 + row) * HH + col) = h0;
            *(__half2*)(pout + (size_t)(n0 + row + 8) * HH + col) = h1;
        }
}

// compute pd/ps for next layer from fp16 x tile staged at aoff (PB pitch)
__device__ __forceinline__ void pre_from_stage(MlpCtx& c, uint32_t aoff,
                                               const uint4* __restrict__ nW1f,
                                               __half* __restrict__ pd,
                                               __half* __restrict__ ps, int n0) {
    gemm_zero(c);
    gemm_run(c, aoff, PB * 2, nW1f, 8);
    epi_write_raw(c, pd, n0);
    gemm_zero(c);
    gemm_run(c, aoff, PB * 2, nW1f + 2048, 8);
    epi_write_raw(c, ps, n0);
}

// ---------------------------------------------------------------------------
// edge kernel: H = relu(pd[dst] + ps[src] + b1); out = H @ W2 + b2 -> scatter
// ---------------------------------------------------------------------------
__global__ void __launch_bounds__(256, 2)
edge_tc(const __half* __restrict__ pd, const __half* __restrict__ ps,
        const void* __restrict__ eidx, const uint4* __restrict__ wf2,
        const float* __restrict__ b1, const float* __restrict__ b2,
        float* __restrict__ agg) {
    extern __shared__ __align__(128) char sm[];
    MlpCtx c;
    c.sb = smem_u32(sm);
    int tid = threadIdx.x;
    c.lane = tid & 31;
    int warp = tid >> 5;
    c.wm = warp >> 1; c.wn = warp & 1;

    if (tid < 128) {
        ((float*)(sm + ESB1_OFF))[tid] = b1[tid];
        ((float*)(sm + ESB2_OFF))[tid] = b2[tid];
    }
    __syncthreads();

    // build H: 2 threads/row, each handles 64 cols
    {
        int r = tid >> 1, h = tid & 1;
        const float* sb1 = (const float*)(sm + ESB1_OFF);
        long long e0 = (long long)blockIdx.x * 128 + r;
        int dstn = load_idx(eidx, (long long)EE + e0);
        int srcn = load_idx(eidx, e0);
        if (h == 0) ((int*)(sm + ESD_OFF))[r] = dstn;
        const uint4* prow = (const uint4*)(pd + (size_t)dstn * HH) + h * 8;
        const uint4* srow = (const uint4*)(ps + (size_t)srcn * HH) + h * 8;
        uint4* hrow = (uint4*)(sm + ESH_OFF + r * (PB * 2)) + h * 8;
#pragma unroll
        for (int j = 0; j < 8; j++) {
            uint4 pv = __ldg(prow + j);
            uint4 sv = __ldg(srow + j);
            const __half2* pp = (const __half2*)&pv;
            const __half2* ss = (const __half2*)&sv;
            uint4 o;
            __half2* oo = (__half2*)&o;
#pragma unroll
            for (int q = 0; q < 4; q++) {
                float2 a = __half22float2(pp[q]);
                float2 b = __half22float2(ss[q]);
                int col = h * 64 + j * 8 + q * 2;
                float v0 = fmaxf(a.x + b.x + sb1[col], 0.f);
                float v1 = fmaxf(a.y + b.y + sb1[col + 1], 0.f);
                oo[q] = __floats2half2_rn(v0, v1);
            }
            hrow[j] = o;
        }
    }
    __syncthreads();

    gemm_zero(c);
    gemm_run(c, ESH_OFF, PB * 2, wf2, 8);
    __syncthreads();   // H no longer needed; region becomes f32 staging

    // staged epilogue: two 64-row passes, f32 staging in H region, v4 red
    {
        float* so = (float*)(sm + ESH_OFF);
        const float* sb2 = (const float*)(sm + ESB2_OFF);
        const int* sdst = (const int*)(sm + ESD_OFF);
        int g = c.lane >> 2, tq = c.lane & 3;
#pragma unroll
        for (int pass = 0; pass < 2; pass++) {
            if ((c.wm >> 1) == pass) {
                int rbase = (c.wm & 1) * 32;
#pragma unroll
                for (int mt = 0; mt < 2; mt++)
#pragma unroll
                    for (int nt = 0; nt < 8; nt++) {
                        int row = rbase + mt * 16 + g;
                        int col = c.wn * 64 + nt * 8 + tq * 2;
                        so[row * POUT + col]           = c.acc[mt][nt][0] + sb2[col];
                        so[row * POUT + col + 1]       = c.acc[mt][nt][1] + sb2[col + 1];
                        so[(row + 8) * POUT + col]     = c.acc[mt][nt][2] + sb2[col];
                        so[(row + 8) * POUT + col + 1] = c.acc[mt][nt][3] + sb2[col + 1];
                    }
            }
            __syncthreads();
#pragma unroll
            for (int q = 0; q < 8; q++) {
                int id = tid + q * 256;
                int row = id >> 5, c4 = id & 31;
                int d = sdst[pass * 64 + row];
                const float* sp = so + row * POUT + c4 * 4;
                red_add_v4(agg + (size_t)d * HH + c4 * 4, sp[0], sp[1], sp[2], sp[3]);
            }
            __syncthreads();
        }
    }
}

// ---------------------------------------------------------------------------
// upd kernel + fused next-layer pre
// ---------------------------------------------------------------------------
__global__ void __launch_bounds__(256, 2)
upd_tc(const __half* __restrict__ xh, const float* __restrict__ agg,
       const uint4* __restrict__ wf1, const uint4* __restrict__ wf2,
       const float* __restrict__ b1, const float* __restrict__ b2,
       __half* __restrict__ xout,
       const uint4* __restrict__ nW1f, __half* __restrict__ pd,
       __half* __restrict__ ps, int do_pre) {
    extern __shared__ __align__(128) char sm[];
    MlpCtx c;
    c.sb = smem_u32(sm);
    int tid = threadIdx.x;
    c.lane = tid & 31;
    int warp = tid >> 5;
    c.wm = warp >> 1; c.wn = warp & 1;
    int n0 = blockIdx.x * 128;

    if (tid < 128) {
        ((float*)(sm + SB1_OFF))[tid] = b1[tid];
        ((float*)(sm + SB2_OFF))[tid] = b2[tid];
    }
    {
        int r = tid >> 1, h = tid & 1;
        int node = n0 + r;
        if (h == 0) {
            const uint4* row = (const uint4*)xh + (size_t)node * 16;
            uint4* dstp = (uint4*)(sm + SA_OFF + r * (PA * 2));
#pragma unroll
            for (int j = 0; j < 16; j++) dstp[j] = __ldg(row + j);
        } else {
            const float4* ar = (const float4*)(agg + (size_t)node * HH);
            uint4* dstp = (uint4*)(sm + SA_OFF + r * (PA * 2) + 256);
#pragma unroll
            for (int j = 0; j < 16; j++) {
                float4 a = __ldg(ar + 2 * j), b = __ldg(ar + 2 * j + 1);
                __half2 h0 = __floats2half2_rn(a.x, a.y), h1 = __floats2half2_rn(a.z, a.w);
                __half2 h2 = __floats2half2_rn(b.x, b.y), h3 = __floats2half2_rn(b.z, b.w);
                uint4 v;
                v.x = *(uint32_t*)&h0; v.y = *(uint32_t*)&h1;
                v.z = *(uint32_t*)&h2; v.w = *(uint32_t*)&h3;
                dstp[j] = v;
            }
        }
    }
    __syncthreads();

    gemm_zero(c);
    gemm_run(c, SA_OFF, PA * 2, wf1, 16);
    epi_relu_h(c, sm, SH_OFF, SB1_OFF);
    __syncthreads();   // SA free after this point (GEMM1 done), H ready

    gemm_zero(c);
    gemm_run(c, SH_OFF, PB * 2, wf2, 8);
    // write x2 to global; stage into SA region (PB pitch) if pre is fused
    epi_write_x_stage(c, sm, SB2_OFF, xout, n0, SA_OFF, do_pre != 0);

    if (do_pre) {
        __syncthreads();
        pre_from_stage(c, SA_OFF, nW1f, pd, ps, n0);
    }
}

// ---------------------------------------------------------------------------
// embed via HMMA + fused layer-0 pre
// ---------------------------------------------------------------------------
__global__ void __launch_bounds__(256, 2)
embed_tc(const float* __restrict__ loc, const float* __restrict__ vel,
         const uint4* __restrict__ wf1, const uint4* __restrict__ wf2,
         const float* __restrict__ b1, const float* __restrict__ b2,
         __half* __restrict__ xout,
         const uint4* __restrict__ nW1f, __half* __restrict__ pd,
         __half* __restrict__ ps) {
    extern __shared__ __align__(128) char sm[];
    MlpCtx c;
    c.sb = smem_u32(sm);
    int tid = threadIdx.x;
    c.lane = tid & 31;
    int warp = tid >> 5;
    c.wm = warp >> 1; c.wn = warp & 1;
    int n0 = blockIdx.x * 128;

    if (tid < 128) {
        ((float*)(sm + EB1_OFF))[tid] = b1[tid];
        ((float*)(sm + EB2_OFF))[tid] = b2[tid];
    }
    if (tid < 128) {
        int r = tid;
        const float* lrow = loc + (size_t)(n0 + r) * 30;
        const float* vrow = vel + (size_t)(n0 + r) * 30;
        __half* drow = (__half*)(sm + EA_OFF + r * (PE * 2));
#pragma unroll
        for (int k = 0; k < 64; k++) {
            float v = 0.f;
            if (k < 60) {
                int f = k / 6, c6 = k % 6;
                v = (c6 < 3) ? lrow[f * 3 + c6] : vrow[f * 3 + c6 - 3];
            }
            drow[k] = __float2half(v);
        }
    }
    __syncthreads();

    gemm_zero(c);
    gemm_run(c, EA_OFF, PE * 2, wf1, 4);
    epi_relu_h(c, sm, EH_OFF, EB1_OFF);
    __syncthreads();

    gemm_zero(c);
    gemm_run(c, EH_OFF, PB * 2, wf2, 8);
    __syncthreads();   // all warps done reading EH; overwrite with x tile
    epi_write_x_stage(c, sm, EB2_OFF, xout, n0, EH_OFF, true);
    __syncthreads();
    pre_from_stage(c, EH_OFF, nW1f, pd, ps, n0);
}

// ---------------------------------------------------------------------------
// head via HMMA: hout(N,30) = relu(x@W1+b1) @ W2pad + b2
// ---------------------------------------------------------------------------
__global__ void __launch_bounds__(256, 2)
head_tc(const __half* __restrict__ xh,
        const uint4* __restrict__ wf1, const uint4* __restrict__ wf2,
        const float* __restrict__ b1, const float* __restrict__ b2,
        float* __restrict__ hout) {
    extern __shared__ __align__(128) char sm[];
    MlpCtx c;
    c.sb = smem_u32(sm);
    int tid = threadIdx.x;
    c.lane = tid & 31;
    int warp = tid >> 5;
    c.wm = warp >> 1; c.wn = warp & 1;
    int n0 = blockIdx.x * 128;

    if (tid < 128) ((float*)(sm + HB1_OFF))[tid] = b1[tid];
    if (tid < 30)  ((float*)(sm + HB2_OFF))[tid] = b2[tid];
    // stage x rows (2 threads/row)
    {
        int r = tid >> 1, h = tid & 1;
        const uint4* row = (const uint4*)xh + (size_t)(n0 + r) * 16 + h * 8;
        uint4* dstp = (uint4*)(sm + HA_OFF + r * (PB * 2)) + h * 8;
#pragma unroll
        for (int j = 0; j < 8; j++) dstp[j] = __ldg(row + j);
    }
    __syncthreads();

    gemm_zero(c);
    gemm_run(c, HA_OFF, PB * 2, wf1, 8);
    epi_relu_h(c, sm, HHS_OFF, HB1_OFF);
    __syncthreads();

    gemm_zero(c);
    gemm_run(c, HHS_OFF, PB * 2, wf2, 8);

    // write cols < 30
    {
        int g = c.lane >> 2, t = c.lane & 3;
        const float* sb2 = (const float*)(sm + HB2_OFF);
        if (c.wn == 0) {
#pragma unroll
            for (int mt = 0; mt < 2; mt++)
#pragma unroll
                for (int nt = 0; nt < 4; nt++) {
                    int row = c.wm * 32 + mt * 16 + g;
                    int col = nt * 8 + t * 2;
                    if (col < 30) {
                        hout[(size_t)(n0 + row) * 30 + col] = c.acc[mt][nt][0] + sb2[col];
                        hout[(size_t)(n0 + row + 8) * 30 + col] = c.acc[mt][nt][2] + sb2[col];
                    }
                    if (col + 1 < 30) {
                        hout[(size_t)(n0 + row) * 30 + col + 1] = c.acc[mt][nt][1] + sb2[col + 1];
                        hout[(size_t)(n0 + row + 8) * 30 + col + 1] = c.acc[mt][nt][3] + sb2[col + 1];
                    }
                }
        }
    }
}

// ---------------------------------------------------------------------------
// loss
// ---------------------------------------------------------------------------
__global__ void loss_kernel(const float* __restrict__ hout, const float* __restrict__ loc,
                            const float* __restrict__ y, float* __restrict__ out) {
    int w = (blockIdx.x * blockDim.x + threadIdx.x) >> 5;
    int lane = threadIdx.x & 31;
    if (w >= BB) return;
    float ade = 0.f, fde = 0.f;
    for (int p = lane; p < 160; p += 32) {
        int node = w * 16 + p / NF;
        int f = p % NF;
        int base = node * 30 + f * 3;
        float dx = hout[base] + loc[base] - y[base];
        float dy = hout[base + 1] + loc[base + 1] - y[base + 1];
        float dz = hout[base + 2] + loc[base + 2] - y[base + 2];
        float d = sqrtf(dx * dx + dy * dy + dz * dz);
        ade += d;
        if (f == NF - 1) fde += d;
    }
#pragma unroll
    for (int o = 16; o; o >>= 1) {
        ade += __shfl_down_sync(0xffffffffu, ade, o);
        fde += __shfl_down_sync(0xffffffffu, fde, o);
    }
    if (lane == 0) {
        out[1 + w] = ade / 160.f;
        out[1 + BB + w] = fde / 16.f;
    }
}

__global__ void final_kernel(float* __restrict__ out) {
    __shared__ float s[256];
    float v = 0.f;
    for (int i = threadIdx.x; i < BB; i += 256) v += out[1 + i];
    s[threadIdx.x] = v;
    __syncthreads();
    for (int o = 128; o; o >>= 1) {
        if (threadIdx.x < o) s[threadIdx.x] += s[threadIdx.x + o];
        __syncthreads();
    }
    if (threadIdx.x == 0) out[0] = s[0] / (float)BB;
}

// ---------------------------------------------------------------------------
// host
// ---------------------------------------------------------------------------
extern "C" void kernel_launch(void* const* d_in, const int* in_sizes, int n_in,
                              void* d_out, int out_size) {
    int o = (n_in > 4 && in_sizes[4] == 1) ? 1 : 0;
    const float* loc = (const float*)d_in[0];
    const float* vel = (const float*)d_in[1];
    const float* y   = (const float*)d_in[2];
    const void*  eix = d_in[3];
    const float* embW1 = (const float*)d_in[4 + o];
    const float* embb1 = (const float*)d_in[5 + o];
    const float* embW2 = (const float*)d_in[6 + o];
    const float* embb2 = (const float*)d_in[7 + o];
    const float* msgW1 = (const float*)d_in[8 + o];
    const float* msgb1 = (const float*)d_in[9 + o];
    const float* msgW2 = (const float*)d_in[10 + o];
    const float* msgb2 = (const float*)d_in[11 + o];
    const float* updW1 = (const float*)d_in[12 + o];
    const float* updb1 = (const float*)d_in[13 + o];
    const float* updW2 = (const float*)d_in[14 + o];
    const float* updb2 = (const float*)d_in[15 + o];
    const float* hW1 = (const float*)d_in[16 + o];
    const float* hb1 = (const float*)d_in[17 + o];
    const float* hW2 = (const float*)d_in[18 + o];
    const float* hb2 = (const float*)d_in[19 + o];
    float* out = (float*)d_out;

    cudaFuncSetAttribute(edge_tc, cudaFuncAttributeMaxDynamicSharedMemorySize, DYNB_E);
    cudaFuncSetAttribute(upd_tc, cudaFuncAttributeMaxDynamicSharedMemorySize, DYNB_U);
    cudaFuncSetAttribute(embed_tc, cudaFuncAttributeMaxDynamicSharedMemorySize, DYNB_EM);
    cudaFuncSetAttribute(head_tc, cudaFuncAttributeMaxDynamicSharedMemorySize, DYNB_H);

    __half *xhp, *xh2p, *pdp, *psp;
    float *aggp, *headp;
    uint4 *mW1f, *mW2f, *uW1f, *uW2f, *eW1f, *eW2f, *hW1f, *hW2f;
    cudaGetSymbolAddress((void**)&xhp, g_xh);
    cudaGetSymbolAddress((void**)&xh2p, g_xh2);
    cudaGetSymbolAddress((void**)&pdp, g_pd);
    cudaGetSymbolAddress((void**)&psp, g_ps);
    cudaGetSymbolAddress((void**)&aggp, g_agg);
    cudaGetSymbolAddress((void**)&headp, g_head);
    cudaGetSymbolAddress((void**)&mW1f, g_mW1f);
    cudaGetSymbolAddress((void**)&mW2f, g_mW2f);
    cudaGetSymbolAddress((void**)&uW1f, g_uW1f);
    cudaGetSymbolAddress((void**)&uW2f, g_uW2f);
    cudaGetSymbolAddress((void**)&eW1f, g_eW1f);
    cudaGetSymbolAddress((void**)&eW2f, g_eW2f);
    cudaGetSymbolAddress((void**)&hW1f, g_hW1f);
    cudaGetSymbolAddress((void**)&hW2f, g_hW2f);

    detect_kernel<<<1, 32>>>((const int*)eix);
    prep_fragk<<<LL, 256>>>(msgW1, (__half*)mW1f, 16, 256, 128, 128, 256 * 128, 32768);
    prep_fragk<<<LL, 256>>>(updW1, (__half*)uW1f, 16, 256, 128, 128, 256 * 128, 32768);
    prep_fragk<<<LL, 256>>>(msgW2, (__half*)mW2f, 8, 128, 128, 128, 128 * 128, 16384);
    prep_fragk<<<LL, 256>>>(updW2, (__half*)uW2f, 8, 128, 128, 128, 128 * 128, 16384);
    prep_fragk<<<1, 256>>>(embW1, (__half*)eW1f, 4, 60, 128, 128, 0, 0);
    prep_fragk<<<1, 256>>>(embW2, (__half*)eW2f, 8, 128, 128, 128, 0, 0);
    prep_fragk<<<1, 256>>>(hW1, (__half*)hW1f, 8, 128, 128, 128, 0, 0);
    prep_fragk<<<1, 256>>>(hW2, (__half*)hW2f, 8, 128, 30, 30, 0, 0);

    embed_tc<<<NN / 128, 256, DYNB_EM>>>(loc, vel, eW1f, eW2f, embb1, embb2, xhp,
                                         mW1f, pdp, psp);

    __half* xa = xhp;
    __half* xb = xh2p;
    for (int i = 0; i < LL; i++) {
        cudaMemsetAsync(aggp, 0, (size_t)NN * HH * sizeof(float));
        edge_tc<<<EE / 128, 256, DYNB_E>>>(
            pdp, psp, eix, mW2f + (size_t)i * 2048,
            msgb1 + (size_t)i * HH, msgb2 + (size_t)i * HH, aggp);
        upd_tc<<<NN / 128, 256, DYNB_U>>>(
            xa, aggp,
            uW1f + (size_t)i * 4096, uW2f + (size_t)i * 2048,
            updb1 + (size_t)i * HH, updb2 + (size_t)i * HH, xb,
            mW1f + (size_t)(i + 1 < LL ? i + 1 : 0) * 4096, pdp, psp,
            i + 1 < LL ? 1 : 0);
        __half* t = xa; xa = xb; xb = t;
    }
    head_tc<<<NN / 128, 256, DYNB_H>>>(xa, hW1f, hW2f, hb1, hb2, headp);
    loss_kernel<<<(BB * 32 + 127) / 128, 128>>>(headp, loc, y, out);
    final_kernel<<<1, 256>>>(out);
}

// round 11
// speedup vs baseline: 8.8446x; 1.1969x over previous
#include <cuda_runtime.h>
#include <cuda_fp16.h>
#include <math.h>
#include <stdint.h>

#define NN 32768
#define EE 524288
#define HH 128
#define BB 2048
#define LL 7
#define NF 10

// ---------------------------------------------------------------------------
// device scratch
// ---------------------------------------------------------------------------
__device__ int    g_is64;
__device__ __half g_xh[NN * HH];
__device__ __half g_xh2[NN * HH];
__device__ __half g_pd[NN * HH];       // x @ W1_top  (indexed by dst)
__device__ __half g_ps[NN * HH];       // x @ W1_bot  (indexed by src)
__device__ float  g_agg[NN * HH];      // scatter target: sum of H (pre-mW2)
__device__ float  g_degf[NN];          // in-degree (float)
__device__ float  g_head[NN * 30];
// fragment-order fp16 weight images (uint4 = one lane's 16B B-fragment)
__device__ uint4 g_mW1f[LL * 4096];
__device__ uint4 g_mW2f[LL * 2048];
__device__ uint4 g_uW1f[LL * 4096];
__device__ uint4 g_uW2f[LL * 2048];
__device__ uint4 g_eW1f[1024];         // K=64 (4 ks)
__device__ uint4 g_eW2f[2048];         // K=128 (8 ks)
__device__ uint4 g_hW1f[2048];         // head W1, K=128
__device__ uint4 g_hW2f[2048];         // head W2, K=128, N=30 (padded)

// pitches in halfs
#define PA 264   // K=256 + 8 pad
#define PB 136   // K=128 + 8 pad  (272 B)
#define PE 72    // K=64  + 8 pad

// ---- upd kernel smem ----
#define SA_OFF   0
#define SH_OFF   (128 * PA * 2)                  // 67584 (T/H tile, PB pitch)
#define SB1_OFF  (SH_OFF + 128 * PB * 2)         // 102400
#define SB2_OFF  (SB1_OFF + 512)
#define SB3_OFF  (SB2_OFF + 512)                 // msg b2
#define SDG_OFF  (SB3_OFF + 512)                 // deg[128]
#define DYNB_U   (SDG_OFF + 512)

// ---- embed smem ----
#define EA_OFF   0
#define EH_OFF   (128 * PE * 2)                  // 18432
#define EB1_OFF  (EH_OFF + 128 * PB * 2)         // 53248
#define EB2_OFF  (EB1_OFF + 512)
#define DYNB_EM  (EB2_OFF + 512)

// ---- head smem ----
#define HA_OFF   0
#define HHS_OFF  (128 * PB * 2)                  // 34816
#define HB1_OFF  (HHS_OFF + 128 * PB * 2)        // 69632
#define HB2_OFF  (HB1_OFF + 512)
#define DYNB_H   (HB2_OFF + 512)

__device__ __forceinline__ uint32_t smem_u32(const void* p) {
    uint32_t a;
    asm("{ .reg .u64 t; cvta.to.shared.u64 t, %1; cvt.u32.u64 %0, t; }" : "=r"(a) : "l"(p));
    return a;
}

__device__ __forceinline__ void ldsm_x4(uint32_t r[4], uint32_t addr) {
    asm volatile("ldmatrix.sync.aligned.m8n8.x4.shared.b16 {%0,%1,%2,%3}, [%4];"
                 : "=r"(r[0]), "=r"(r[1]), "=r"(r[2]), "=r"(r[3]) : "r"(addr));
}

__device__ __forceinline__ void mma16816(float c[4], const uint32_t a[4],
                                         uint32_t b0, uint32_t b1) {
    asm volatile(
        "mma.sync.aligned.m16n8k16.row.col.f32.f16.f16.f32 "
        "{%0,%1,%2,%3},{%4,%5,%6,%7},{%8,%9},{%0,%1,%2,%3};"
        : "+f"(c[0]), "+f"(c[1]), "+f"(c[2]), "+f"(c[3])
        : "r"(a[0]), "r"(a[1]), "r"(a[2]), "r"(a[3]), "r"(b0), "r"(b1));
}

__device__ __forceinline__ void red_add_v4(float* p, float x, float y, float z, float w) {
    asm volatile("red.global.add.v4.f32 [%0], {%1, %2, %3, %4};"
                 :: "l"(p), "f"(x), "f"(y), "f"(z), "f"(w) : "memory");
}

__device__ __forceinline__ int load_idx(const void* p, long long i) {
    if (g_is64) return (int)((const long long*)p)[i];
    return ((const int*)p)[i];
}

__global__ void detect_kernel(const int* e) {
    if (threadIdx.x == 0) {
        int is64 = 1;
        for (int i = 1; i < 256; i += 2)
            if (e[i] != 0) { is64 = 0; break; }
        g_is64 = is64;
    }
}

__global__ void deg_kernel(const void* __restrict__ eidx) {
    int i = blockIdx.x * blockDim.x + threadIdx.x;
    if (i < EE) atomicAdd(&g_degf[load_idx(eidx, (long long)EE + i)], 1.0f);
}

// ---------------------------------------------------------------------------
// weight prep: fp32 [k][n] -> fragment-order fp16 image
// ---------------------------------------------------------------------------
__global__ void prep_fragk(const float* __restrict__ src, __half* __restrict__ dst,
                           int ksteps, int Ktrue, int Ntrue, int srcWidth,
                           int srcStride, int dstStride) {
    int l = blockIdx.x;
    src += (size_t)l * srcStride;
    dst += (size_t)l * dstStride;
    int total = ksteps * 2048;
    for (int e = threadIdx.x; e < total; e += blockDim.x) {
        int h = e & 7, lane = (e >> 3) & 31, p = (e >> 8) & 3, wn = (e >> 10) & 1, ks = e >> 11;
        int k = ks * 16 + (lane & 3) * 2 + (h & 1) + ((h >> 1) & 1) * 8;
        int n = wn * 64 + p * 16 + (lane >> 2) + (h >> 2) * 8;
        dst[e] = (k < Ktrue && n < Ntrue) ? __float2half(src[k * srcWidth + n]) : __half(0.f);
    }
}

// ---------------------------------------------------------------------------
// HMMA core: 128 rows per tile, 256 threads (8 warps, warp tile 32x64)
// ---------------------------------------------------------------------------
struct MlpCtx {
    uint32_t sb;
    int lane, wm, wn;
    float acc[2][8][4];
};

__device__ __forceinline__ void gemm_zero(MlpCtx& c) {
#pragma unroll
    for (int mt = 0; mt < 2; mt++)
#pragma unroll
        for (int nt = 0; nt < 8; nt++)
#pragma unroll
            for (int q = 0; q < 4; q++) c.acc[mt][nt][q] = 0.f;
}

__device__ __forceinline__ void gemm_run(MlpCtx& c, uint32_t aoff, uint32_t pbytes,
                                         const uint4* __restrict__ wf, int ksteps) {
    int l = c.lane;
    uint32_t aBase = c.sb + aoff +
        (uint32_t)(c.wm * 32 + (l & 7) + ((l >> 3) & 1) * 8) * pbytes + (l >> 4) * 16;
    const uint4* wb = wf + c.wn * 128 + l;
#pragma unroll
    for (int ks = 0; ks < 16; ks++) {
        if (ks >= ksteps) break;
        uint32_t a0[4], a1[4];
        uint4 q[4];
#pragma unroll
        for (int p = 0; p < 4; p++) q[p] = __ldg(wb + ks * 256 + p * 32);
        ldsm_x4(a0, aBase + ks * 32);
        ldsm_x4(a1, aBase + 16 * pbytes + ks * 32);
#pragma unroll
        for (int p = 0; p < 4; p++) {
            mma16816(c.acc[0][2 * p],     a0, q[p].x, q[p].y);
            mma16816(c.acc[0][2 * p + 1], a0, q[p].z, q[p].w);
            mma16816(c.acc[1][2 * p],     a1, q[p].x, q[p].y);
            mma16816(c.acc[1][2 * p + 1], a1, q[p].z, q[p].w);
        }
    }
}

__device__ __forceinline__ void epi_relu_h(MlpCtx& c, char* sm, int shOff, int b1Off) {
    int g = c.lane >> 2, t = c.lane & 3;
    const float* sb1 = (const float*)(sm + b1Off);
#pragma unroll
    for (int mt = 0; mt < 2; mt++)
#pragma unroll
        for (int nt = 0; nt < 8; nt++) {
            int row = c.wm * 32 + mt * 16 + g;
            int col = c.wn * 64 + nt * 8 + t * 2;
            float v0 = c.acc[mt][nt][0] + sb1[col];
            float v1 = c.acc[mt][nt][1] + sb1[col + 1];
            float v2 = c.acc[mt][nt][2] + sb1[col];
            float v3 = c.acc[mt][nt][3] + sb1[col + 1];
            v0 = v0 > 0.f ? v0 : 0.f; v1 = v1 > 0.f ? v1 : 0.f;
            v2 = v2 > 0.f ? v2 : 0.f; v3 = v3 > 0.f ? v3 : 0.f;
            *(__half2*)(sm + shOff + row * (PB * 2) + col * 2) = __floats2half2_rn(v0, v1);
            *(__half2*)(sm + shOff + (row + 8) * (PB * 2) + col * 2) = __floats2half2_rn(v2, v3);
        }
}

// write x (bias added) to global AND stage fp16 tile (PB pitch) at stageOff
__device__ __forceinline__ void epi_write_x_stage(MlpCtx& c, char* sm, int b2Off,
                                                  __half* __restrict__ xout, int n0,
                                                  int stageOff, bool doStage) {
    int g = c.lane >> 2, t = c.lane & 3;
    const float* sb2 = (const float*)(sm + b2Off);
#pragma unroll
    for (int mt = 0; mt < 2; mt++)
#pragma unroll
        for (int nt = 0; nt < 8; nt++) {
            int row = c.wm * 32 + mt * 16 + g;
            int col = c.wn * 64 + nt * 8 + t * 2;
            float bb0 = sb2[col], bb1 = sb2[col + 1];
            __half2 h0 = __floats2half2_rn(c.acc[mt][nt][0] + bb0, c.acc[mt][nt][1] + bb1);
            __half2 h1 = __floats2half2_rn(c.acc[mt][nt][2] + bb0, c.acc[mt][nt][3] + bb1);
            *(__half2*)(xout + (size_t)(n0 + row) * HH + col) = h0;
            *(__half2*)(xout + (size_t)(n0 + row + 8) * HH + col) = h1;
            if (doStage) {
                *(__half2*)(sm + stageOff + row * (PB * 2) + col * 2) = h0;
                *(__half2*)(sm + stageOff + (row + 8) * (PB * 2) + col * 2) = h1;
            }
        }
}

// raw fp16 writeout (no bias) -> pd/ps
__device__ __forceinline__ void epi_write_raw(MlpCtx& c, __half* __restrict__ pout, int n0) {
    int g = c.lane >> 2, t = c.lane & 3;
#pragma unroll
    for (int mt = 0; mt < 2; mt++)
#pragma unroll
        for (int nt = 0; nt < 8; nt++) {
            int row = c.wm * 32 + mt * 16 + g;
            int col = c.wn * 64 + nt * 8 + t * 2;
            __half2 h0 = __floats2half2_rn(c.acc[mt][nt][0], c.acc[mt][nt][1]);
            __half2 h1 = __floats2half2_rn(c.acc[mt][nt][2], c.acc[mt][nt][3]);
            *(__half2*)(pout + (size_t)(n0 + row) * HH + col) = h0;
            *(__half2*)(pout + (size_t)(n0 + row + 8) * HH + col) = h1;
        }
}

// compute pd/ps for next layer from fp16 x tile staged at aoff (PB pitch)
__device__ __forceinline__ void pre_from_stage(MlpCtx& c, uint32_t aoff,
                                               const uint4* __restrict__ nW1f,
                                               __half* __restrict__ pd,
                                               __half* __restrict__ ps, int n0) {
    gemm_zero(c);
    gemm_run(c, aoff, PB * 2, nW1f, 8);
    epi_write_raw(c, pd, n0);
    gemm_zero(c);
    gemm_run(c, aoff, PB * 2, nW1f + 2048, 8);
    epi_write_raw(c, ps, n0);
}

// ---------------------------------------------------------------------------
// edge scatter kernel (no MMA): H = relu(pd[dst]+ps[src]+b1); aggH[dst] += H
// ---------------------------------------------------------------------------
__global__ void __launch_bounds__(256)
edge_sc(const __half* __restrict__ pd, const __half* __restrict__ ps,
        const void* __restrict__ eidx, const float* __restrict__ b1,
        float* __restrict__ aggH) {
    __shared__ float sb1[128];
    int tid = threadIdx.x;
    if (tid < 128) sb1[tid] = b1[tid];
    __syncthreads();

    int r = tid >> 1, h = tid & 1;
    long long e0 = (long long)blockIdx.x * 128 + r;
    int dstn = load_idx(eidx, (long long)EE + e0);
    int srcn = load_idx(eidx, e0);
    const uint4* prow = (const uint4*)(pd + (size_t)dstn * HH) + h * 8;
    const uint4* srow = (const uint4*)(ps + (size_t)srcn * HH) + h * 8;
    float* arow = aggH + (size_t)dstn * HH + h * 64;
    const float* bb = sb1 + h * 64;
#pragma unroll
    for (int j = 0; j < 8; j++) {
        uint4 pv = __ldg(prow + j);
        uint4 sv = __ldg(srow + j);
        const __half2* pp = (const __half2*)&pv;
        const __half2* ss = (const __half2*)&sv;
        float v[8];
#pragma unroll
        for (int q = 0; q < 4; q++) {
            float2 a = __half22float2(pp[q]);
            float2 b = __half22float2(ss[q]);
            v[2 * q]     = fmaxf(a.x + b.x + bb[j * 8 + 2 * q], 0.f);
            v[2 * q + 1] = fmaxf(a.y + b.y + bb[j * 8 + 2 * q + 1], 0.f);
        }
        red_add_v4(arow + j * 8,     v[0], v[1], v[2], v[3]);
        red_add_v4(arow + j * 8 + 4, v[4], v[5], v[6], v[7]);
    }
}

// ---------------------------------------------------------------------------
// upd kernel: agg = aggH@mW2 + deg*mb2 ; x2 = mlp(cat(x,agg)) ; fused pre
// ---------------------------------------------------------------------------
__global__ void __launch_bounds__(256, 2)
upd_tc(const __half* __restrict__ xh, const float* __restrict__ aggH,
       const uint4* __restrict__ mW2f, const float* __restrict__ mb2,
       const float* __restrict__ degf,
       const uint4* __restrict__ wf1, const uint4* __restrict__ wf2,
       const float* __restrict__ b1, const float* __restrict__ b2,
       __half* __restrict__ xout,
       const uint4* __restrict__ nW1f, __half* __restrict__ pd,
       __half* __restrict__ ps, int do_pre) {
    extern __shared__ __align__(128) char sm[];
    MlpCtx c;
    c.sb = smem_u32(sm);
    int tid = threadIdx.x;
    c.lane = tid & 31;
    int warp = tid >> 5;
    c.wm = warp >> 1; c.wn = warp & 1;
    int n0 = blockIdx.x * 128;

    if (tid < 128) {
        ((float*)(sm + SB1_OFF))[tid] = b1[tid];
        ((float*)(sm + SB2_OFF))[tid] = b2[tid];
        ((float*)(sm + SB3_OFF))[tid] = mb2[tid];
        ((float*)(sm + SDG_OFF))[tid] = degf[n0 + tid];
    }
    // gather: h=0 -> x row into SA chunks 0-1; h=1 -> aggH row (f32->f16) into T (SH)
    {
        int r = tid >> 1, h = tid & 1;
        int node = n0 + r;
        if (h == 0) {
            const uint4* row = (const uint4*)xh + (size_t)node * 16;
            uint4* dstp = (uint4*)(sm + SA_OFF + r * (PA * 2));
#pragma unroll
            for (int j = 0; j < 16; j++) dstp[j] = __ldg(row + j);
        } else {
            const float4* ar = (const float4*)(aggH + (size_t)node * HH);
            uint4* dstp = (uint4*)(sm + SH_OFF + r * (PB * 2));
#pragma unroll
            for (int j = 0; j < 16; j++) {
                float4 a = __ldg(ar + 2 * j), b = __ldg(ar + 2 * j + 1);
                __half2 h0 = __floats2half2_rn(a.x, a.y), h1 = __floats2half2_rn(a.z, a.w);
                __half2 h2 = __floats2half2_rn(b.x, b.y), h3 = __floats2half2_rn(b.z, b.w);
                uint4 v;
                v.x = *(uint32_t*)&h0; v.y = *(uint32_t*)&h1;
                v.z = *(uint32_t*)&h2; v.w = *(uint32_t*)&h3;
                dstp[j] = v;
            }
        }
    }
    __syncthreads();

    // GEMM_A: agg = T @ mW2 + deg*mb2 -> fp16 into SA chunks 2-3
    gemm_zero(c);
    gemm_run(c, SH_OFF, PB * 2, mW2f, 8);
    {
        int g = c.lane >> 2, t = c.lane & 3;
        const float* sb3 = (const float*)(sm + SB3_OFF);
        const float* sdg = (const float*)(sm + SDG_OFF);
#pragma unroll
        for (int mt = 0; mt < 2; mt++)
#pragma unroll
            for (int nt = 0; nt < 8; nt++) {
                int row = c.wm * 32 + mt * 16 + g;
                int col = c.wn * 64 + nt * 8 + t * 2;
                float d0 = sdg[row], d1 = sdg[row + 8];
                float bb0 = sb3[col], bb1 = sb3[col + 1];
                __half2 h0 = __floats2half2_rn(c.acc[mt][nt][0] + d0 * bb0,
                                               c.acc[mt][nt][1] + d0 * bb1);
                __half2 h1 = __floats2half2_rn(c.acc[mt][nt][2] + d1 * bb0,
                                               c.acc[mt][nt][3] + d1 * bb1);
                *(__half2*)(sm + SA_OFF + row * (PA * 2) + 256 + col * 2) = h0;
                *(__half2*)(sm + SA_OFF + (row + 8) * (PA * 2) + 256 + col * 2) = h1;
            }
    }
    __syncthreads();

    gemm_zero(c);
    gemm_run(c, SA_OFF, PA * 2, wf1, 16);
    epi_relu_h(c, sm, SH_OFF, SB1_OFF);
    __syncthreads();

    gemm_zero(c);
    gemm_run(c, SH_OFF, PB * 2, wf2, 8);
    epi_write_x_stage(c, sm, SB2_OFF, xout, n0, SA_OFF, do_pre != 0);

    if (do_pre) {
        __syncthreads();
        pre_from_stage(c, SA_OFF, nW1f, pd, ps, n0);
    }
}

// ---------------------------------------------------------------------------
// embed via HMMA + fused layer-0 pre
// ---------------------------------------------------------------------------
__global__ void __launch_bounds__(256, 2)
embed_tc(const float* __restrict__ loc, const float* __restrict__ vel,
         const uint4* __restrict__ wf1, const uint4* __restrict__ wf2,
         const float* __restrict__ b1, const float* __restrict__ b2,
         __half* __restrict__ xout,
         const uint4* __restrict__ nW1f, __half* __restrict__ pd,
         __half* __restrict__ ps) {
    extern __shared__ __align__(128) char sm[];
    MlpCtx c;
    c.sb = smem_u32(sm);
    int tid = threadIdx.x;
    c.lane = tid & 31;
    int warp = tid >> 5;
    c.wm = warp >> 1; c.wn = warp & 1;
    int n0 = blockIdx.x * 128;

    if (tid < 128) {
        ((float*)(sm + EB1_OFF))[tid] = b1[tid];
        ((float*)(sm + EB2_OFF))[tid] = b2[tid];
    }
    if (tid < 128) {
        int r = tid;
        const float* lrow = loc + (size_t)(n0 + r) * 30;
        const float* vrow = vel + (size_t)(n0 + r) * 30;
        __half* drow = (__half*)(sm + EA_OFF + r * (PE * 2));
#pragma unroll
        for (int k = 0; k < 64; k++) {
            float v = 0.f;
            if (k < 60) {
                int f = k / 6, c6 = k % 6;
                v = (c6 < 3) ? lrow[f * 3 + c6] : vrow[f * 3 + c6 - 3];
            }
            drow[k] = __float2half(v);
        }
    }
    __syncthreads();

    gemm_zero(c);
    gemm_run(c, EA_OFF, PE * 2, wf1, 4);
    epi_relu_h(c, sm, EH_OFF, EB1_OFF);
    __syncthreads();

    gemm_zero(c);
    gemm_run(c, EH_OFF, PB * 2, wf2, 8);
    __syncthreads();
    epi_write_x_stage(c, sm, EB2_OFF, xout, n0, EH_OFF, true);
    __syncthreads();
    pre_from_stage(c, EH_OFF, nW1f, pd, ps, n0);
}

// ---------------------------------------------------------------------------
// head via HMMA
// ---------------------------------------------------------------------------
__global__ void __launch_bounds__(256, 2)
head_tc(const __half* __restrict__ xh,
        const uint4* __restrict__ wf1, const uint4* __restrict__ wf2,
        const float* __restrict__ b1, const float* __restrict__ b2,
        float* __restrict__ hout) {
    extern __shared__ __align__(128) char sm[];
    MlpCtx c;
    c.sb = smem_u32(sm);
    int tid = threadIdx.x;
    c.lane = tid & 31;
    int warp = tid >> 5;
    c.wm = warp >> 1; c.wn = warp & 1;
    int n0 = blockIdx.x * 128;

    if (tid < 128) ((float*)(sm + HB1_OFF))[tid] = b1[tid];
    if (tid < 30)  ((float*)(sm + HB2_OFF))[tid] = b2[tid];
    {
        int r = tid >> 1, h = tid & 1;
        const uint4* row = (const uint4*)xh + (size_t)(n0 + r) * 16 + h * 8;
        uint4* dstp = (uint4*)(sm + HA_OFF + r * (PB * 2)) + h * 8;
#pragma unroll
        for (int j = 0; j < 8; j++) dstp[j] = __ldg(row + j);
    }
    __syncthreads();

    gemm_zero(c);
    gemm_run(c, HA_OFF, PB * 2, wf1, 8);
    epi_relu_h(c, sm, HHS_OFF, HB1_OFF);
    __syncthreads();

    gemm_zero(c);
    gemm_run(c, HHS_OFF, PB * 2, wf2, 8);
    {
        int g = c.lane >> 2, t = c.lane & 3;
        const float* sb2 = (const float*)(sm + HB2_OFF);
        if (c.wn == 0) {
#pragma unroll
            for (int mt = 0; mt < 2; mt++)
#pragma unroll
                for (int nt = 0; nt < 4; nt++) {
                    int row = c.wm * 32 + mt * 16 + g;
                    int col = nt * 8 + t * 2;
                    if (col < 30) {
                        hout[(size_t)(n0 + row) * 30 + col] = c.acc[mt][nt][0] + sb2[col];
                        hout[(size_t)(n0 + row + 8) * 30 + col] = c.acc[mt][nt][2] + sb2[col];
                    }
                    if (col + 1 < 30) {
                        hout[(size_t)(n0 + row) * 30 + col + 1] = c.acc[mt][nt][1] + sb2[col + 1];
                        hout[(size_t)(n0 + row + 8) * 30 + col + 1] = c.acc[mt][nt][3] + sb2[col + 1];
                    }
                }
        }
    }
}

// ---------------------------------------------------------------------------
// loss
// ---------------------------------------------------------------------------
__global__ void loss_kernel(const float* __restrict__ hout, const float* __restrict__ loc,
                            const float* __restrict__ y, float* __restrict__ out) {
    int w = (blockIdx.x * blockDim.x + threadIdx.x) >> 5;
    int lane = threadIdx.x & 31;
    if (w >= BB) return;
    float ade = 0.f, fde = 0.f;
    for (int p = lane; p < 160; p += 32) {
        int node = w * 16 + p / NF;
        int f = p % NF;
        int base = node * 30 + f * 3;
        float dx = hout[base] + loc[base] - y[base];
        float dy = hout[base + 1] + loc[base + 1] - y[base + 1];
        float dz = hout[base + 2] + loc[base + 2] - y[base + 2];
        float d = sqrtf(dx * dx + dy * dy + dz * dz);
        ade += d;
        if (f == NF - 1) fde += d;
    }
#pragma unroll
    for (int o = 16; o; o >>= 1) {
        ade += __shfl_down_sync(0xffffffffu, ade, o);
        fde += __shfl_down_sync(0xffffffffu, fde, o);
    }
    if (lane == 0) {
        out[1 + w] = ade / 160.f;
        out[1 + BB + w] = fde / 16.f;
    }
}

__global__ void final_kernel(float* __restrict__ out) {
    __shared__ float s[256];
    float v = 0.f;
    for (int i = threadIdx.x; i < BB; i += 256) v += out[1 + i];
    s[threadIdx.x] = v;
    __syncthreads();
    for (int o = 128; o; o >>= 1) {
        if (threadIdx.x < o) s[threadIdx.x] += s[threadIdx.x + o];
        __syncthreads();
    }
    if (threadIdx.x == 0) out[0] = s[0] / (float)BB;
}

// ---------------------------------------------------------------------------
// host
// ---------------------------------------------------------------------------
extern "C" void kernel_launch(void* const* d_in, const int* in_sizes, int n_in,
                              void* d_out, int out_size) {
    int o = (n_in > 4 && in_sizes[4] == 1) ? 1 : 0;
    const float* loc = (const float*)d_in[0];
    const float* vel = (const float*)d_in[1];
    const float* y   = (const float*)d_in[2];
    const void*  eix = d_in[3];
    const float* embW1 = (const float*)d_in[4 + o];
    const float* embb1 = (const float*)d_in[5 + o];
    const float* embW2 = (const float*)d_in[6 + o];
    const float* embb2 = (const float*)d_in[7 + o];
    const float* msgW1 = (const float*)d_in[8 + o];
    const float* msgb1 = (const float*)d_in[9 + o];
    const float* msgW2 = (const float*)d_in[10 + o];
    const float* msgb2 = (const float*)d_in[11 + o];
    const float* updW1 = (const float*)d_in[12 + o];
    const float* updb1 = (const float*)d_in[13 + o];
    const float* updW2 = (const float*)d_in[14 + o];
    const float* updb2 = (const float*)d_in[15 + o];
    const float* hW1 = (const float*)d_in[16 + o];
    const float* hb1 = (const float*)d_in[17 + o];
    const float* hW2 = (const float*)d_in[18 + o];
    const float* hb2 = (const float*)d_in[19 + o];
    float* out = (float*)d_out;

    cudaFuncSetAttribute(upd_tc, cudaFuncAttributeMaxDynamicSharedMemorySize, DYNB_U);
    cudaFuncSetAttribute(embed_tc, cudaFuncAttributeMaxDynamicSharedMemorySize, DYNB_EM);
    cudaFuncSetAttribute(head_tc, cudaFuncAttributeMaxDynamicSharedMemorySize, DYNB_H);

    __half *xhp, *xh2p, *pdp, *psp;
    float *aggp, *headp, *degp;
    uint4 *mW1f, *mW2f, *uW1f, *uW2f, *eW1f, *eW2f, *hW1f, *hW2f;
    cudaGetSymbolAddress((void**)&xhp, g_xh);
    cudaGetSymbolAddress((void**)&xh2p, g_xh2);
    cudaGetSymbolAddress((void**)&pdp, g_pd);
    cudaGetSymbolAddress((void**)&psp, g_ps);
    cudaGetSymbolAddress((void**)&aggp, g_agg);
    cudaGetSymbolAddress((void**)&degp, g_degf);
    cudaGetSymbolAddress((void**)&headp, g_head);
    cudaGetSymbolAddress((void**)&mW1f, g_mW1f);
    cudaGetSymbolAddress((void**)&mW2f, g_mW2f);
    cudaGetSymbolAddress((void**)&uW1f, g_uW1f);
    cudaGetSymbolAddress((void**)&uW2f, g_uW2f);
    cudaGetSymbolAddress((void**)&eW1f, g_eW1f);
    cudaGetSymbolAddress((void**)&eW2f, g_eW2f);
    cudaGetSymbolAddress((void**)&hW1f, g_hW1f);
    cudaGetSymbolAddress((void**)&hW2f, g_hW2f);

    detect_kernel<<<1, 32>>>((const int*)eix);
    cudaMemsetAsync(degp, 0, NN * sizeof(float));
    deg_kernel<<<EE / 256, 256>>>(eix);
    prep_fragk<<<LL, 256>>>(msgW1, (__half*)mW1f, 16, 256, 128, 128, 256 * 128, 32768);
    prep_fragk<<<LL, 256>>>(updW1, (__half*)uW1f, 16, 256, 128, 128, 256 * 128, 32768);
    prep_fragk<<<LL, 256>>>(msgW2, (__half*)mW2f, 8, 128, 128, 128, 128 * 128, 16384);
    prep_fragk<<<LL, 256>>>(updW2, (__half*)uW2f, 8, 128, 128, 128, 128 * 128, 16384);
    prep_fragk<<<1, 256>>>(embW1, (__half*)eW1f, 4, 60, 128, 128, 0, 0);
    prep_fragk<<<1, 256>>>(embW2, (__half*)eW2f, 8, 128, 128, 128, 0, 0);
    prep_fragk<<<1, 256>>>(hW1, (__half*)hW1f, 8, 128, 128, 128, 0, 0);
    prep_fragk<<<1, 256>>>(hW2, (__half*)hW2f, 8, 128, 30, 30, 0, 0);

    embed_tc<<<NN / 128, 256, DYNB_EM>>>(loc, vel, eW1f, eW2f, embb1, embb2, xhp,
                                         mW1f, pdp, psp);

    __half* xa = xhp;
    __half* xb = xh2p;
    for (int i = 0; i < LL; i++) {
        cudaMemsetAsync(aggp, 0, (size_t)NN * HH * sizeof(float));
        edge_sc<<<EE / 128, 256>>>(pdp, psp, eix, msgb1 + (size_t)i * HH, aggp);
        upd_tc<<<NN / 128, 256, DYNB_U>>>(
            xa, aggp,
            mW2f + (size_t)i * 2048, msgb2 + (size_t)i * HH, degp,
            uW1f + (size_t)i * 4096, uW2f + (size_t)i * 2048,
            updb1 + (size_t)i * HH, updb2 + (size_t)i * HH, xb,
            mW1f + (size_t)(i + 1 < LL ? i + 1 : 0) * 4096, pdp, psp,
            i + 1 < LL ? 1 : 0);
        __half* t = xa; xa = xb; xb = t;
    }
    head_tc<<<NN / 128, 256, DYNB_H>>>(xa, hW1f, hW2f, hb1, hb2, headp);
    loss_kernel<<<(BB * 32 + 127) / 128, 128>>>(headp, loc, y, out);
    final_kernel<<<1, 256>>>(out);
}

// round 12
// speedup vs baseline: 12.6799x; 1.4336x over previous
#include <cuda_runtime.h>
#include <cuda_fp16.h>
#include <math.h>
#include <stdint.h>

#define NN 32768
#define EE 524288
#define HH 128
#define BB 2048
#define LL 7
#define NF 10

// ---------------------------------------------------------------------------
// device scratch
// ---------------------------------------------------------------------------
__device__ int    g_is64;
__device__ __half g_xh[NN * HH];
__device__ __half g_xh2[NN * HH];
__device__ __half g_pd[NN * HH];       // x @ W1_top + b1 (indexed by dst)
__device__ __half g_ps[NN * HH];       // x @ W1_bot      (indexed by src)
__device__ __half g_aggh[NN * HH];     // fp16 scatter target: sum of H
__device__ float  g_degf[NN];          // in-degree (float)
__device__ float  g_head[NN * 30];
__device__ int    g_srcA[EE];
__device__ int    g_dstA[EE];
// fragment-order fp16 weight images (uint4 = one lane's 16B B-fragment)
__device__ uint4 g_mW1f[LL * 4096];
__device__ uint4 g_mW2f[LL * 2048];
__device__ uint4 g_uW1f[LL * 4096];
__device__ uint4 g_uW2f[LL * 2048];
__device__ uint4 g_eW1f[1024];         // K=64 (4 ks)
__device__ uint4 g_eW2f[2048];         // K=128 (8 ks)
__device__ uint4 g_hW1f[2048];         // head W1, K=128
__device__ uint4 g_hW2f[2048];         // head W2, K=128, N=30 (padded)

// pitches in halfs
#define PA 264   // K=256 + 8 pad
#define PB 136   // K=128 + 8 pad  (272 B)
#define PE 72    // K=64  + 8 pad

// ---- upd kernel smem ----
#define SA_OFF   0
#define SH_OFF   (128 * PA * 2)                  // 67584 (T/H tile, PB pitch)
#define SB1_OFF  (SH_OFF + 128 * PB * 2)         // 102400
#define SB2_OFF  (SB1_OFF + 512)
#define SB3_OFF  (SB2_OFF + 512)                 // msg b2
#define SDG_OFF  (SB3_OFF + 512)                 // deg[128]
#define DYNB_U   (SDG_OFF + 512)

// ---- embed smem ----
#define EA_OFF   0
#define EH_OFF   (128 * PE * 2)                  // 18432
#define EB1_OFF  (EH_OFF + 128 * PB * 2)         // 53248
#define EB2_OFF  (EB1_OFF + 512)
#define DYNB_EM  (EB2_OFF + 512)

// ---- head smem ----
#define HA_OFF   0
#define HHS_OFF  (128 * PB * 2)                  // 34816
#define HB1_OFF  (HHS_OFF + 128 * PB * 2)        // 69632
#define HB2_OFF  (HB1_OFF + 512)
#define DYNB_H   (HB2_OFF + 512)

__device__ __forceinline__ uint32_t smem_u32(const void* p) {
    uint32_t a;
    asm("{ .reg .u64 t; cvta.to.shared.u64 t, %1; cvt.u32.u64 %0, t; }" : "=r"(a) : "l"(p));
    return a;
}

__device__ __forceinline__ void ldsm_x4(uint32_t r[4], uint32_t addr) {
    asm volatile("ldmatrix.sync.aligned.m8n8.x4.shared.b16 {%0,%1,%2,%3}, [%4];"
                 : "=r"(r[0]), "=r"(r[1]), "=r"(r[2]), "=r"(r[3]) : "r"(addr));
}

__device__ __forceinline__ void mma16816(float c[4], const uint32_t a[4],
                                         uint32_t b0, uint32_t b1) {
    asm volatile(
        "mma.sync.aligned.m16n8k16.row.col.f32.f16.f16.f32 "
        "{%0,%1,%2,%3},{%4,%5,%6,%7},{%8,%9},{%0,%1,%2,%3};"
        : "+f"(c[0]), "+f"(c[1]), "+f"(c[2]), "+f"(c[3])
        : "r"(a[0]), "r"(a[1]), "r"(a[2]), "r"(a[3]), "r"(b0), "r"(b1));
}

__device__ __forceinline__ void red_add_h8(__half* p, uint32_t a, uint32_t b,
                                           uint32_t c, uint32_t d) {
    asm volatile("red.global.add.noftz.v4.f16x2 [%0], {%1, %2, %3, %4};"
                 :: "l"(p), "r"(a), "r"(b), "r"(c), "r"(d) : "memory");
}

__device__ __forceinline__ int load_idx(const void* p, long long i) {
    if (g_is64) return (int)((const long long*)p)[i];
    return ((const int*)p)[i];
}

__global__ void detect_kernel(const int* e) {
    if (threadIdx.x == 0) {
        int is64 = 1;
        for (int i = 1; i < 256; i += 2)
            if (e[i] != 0) { is64 = 0; break; }
        g_is64 = is64;
    }
}

// convert indices to int32 + compute in-degree
__global__ void idx_kernel(const void* __restrict__ eidx) {
    int i = blockIdx.x * blockDim.x + threadIdx.x;
    if (i >= EE) return;
    g_srcA[i] = load_idx(eidx, i);
    int d = load_idx(eidx, (long long)EE + i);
    g_dstA[i] = d;
    atomicAdd(&g_degf[d], 1.0f);
}

// ---------------------------------------------------------------------------
// weight prep: fp32 [k][n] -> fragment-order fp16 image
// grid = (layers, ksteps); 256 threads, one 16B fragment per thread
// ---------------------------------------------------------------------------
__global__ void prep_fragk(const float* __restrict__ src, __half* __restrict__ dst,
                           int Ktrue, int Ntrue, int srcWidth,
                           int srcStride, int dstStride) {
    int l = blockIdx.x, ks = blockIdx.y;
    src += (size_t)l * srcStride;
    dst += (size_t)l * dstStride + (size_t)ks * 2048;
    int tid = threadIdx.x;
    int lane = tid & 31, p = (tid >> 5) & 3, wn = (tid >> 7) & 1;
    uint4 v;
    __half* hv = (__half*)&v;
#pragma unroll
    for (int h = 0; h < 8; h++) {
        int k = ks * 16 + (lane & 3) * 2 + (h & 1) + ((h >> 1) & 1) * 8;
        int n = wn * 64 + p * 16 + (lane >> 2) + (h >> 2) * 8;
        hv[h] = (k < Ktrue && n < Ntrue) ? __float2half(src[k * srcWidth + n]) : __half(0.f);
    }
    ((uint4*)dst)[tid] = v;
}

// ---------------------------------------------------------------------------
// HMMA core: 128 rows per tile, 256 threads (8 warps, warp tile 32x64)
// ---------------------------------------------------------------------------
struct MlpCtx {
    uint32_t sb;
    int lane, wm, wn;
    float acc[2][8][4];
};

__device__ __forceinline__ void gemm_zero(MlpCtx& c) {
#pragma unroll
    for (int mt = 0; mt < 2; mt++)
#pragma unroll
        for (int nt = 0; nt < 8; nt++)
#pragma unroll
            for (int q = 0; q < 4; q++) c.acc[mt][nt][q] = 0.f;
}

__device__ __forceinline__ void gemm_run(MlpCtx& c, uint32_t aoff, uint32_t pbytes,
                                         const uint4* __restrict__ wf, int ksteps) {
    int l = c.lane;
    uint32_t aBase = c.sb + aoff +
        (uint32_t)(c.wm * 32 + (l & 7) + ((l >> 3) & 1) * 8) * pbytes + (l >> 4) * 16;
    const uint4* wb = wf + c.wn * 128 + l;
#pragma unroll
    for (int ks = 0; ks < 16; ks++) {
        if (ks >= ksteps) break;
        uint32_t a0[4], a1[4];
        uint4 q[4];
#pragma unroll
        for (int p = 0; p < 4; p++) q[p] = __ldg(wb + ks * 256 + p * 32);
        ldsm_x4(a0, aBase + ks * 32);
        ldsm_x4(a1, aBase + 16 * pbytes + ks * 32);
#pragma unroll
        for (int p = 0; p < 4; p++) {
            mma16816(c.acc[0][2 * p],     a0, q[p].x, q[p].y);
            mma16816(c.acc[0][2 * p + 1], a0, q[p].z, q[p].w);
            mma16816(c.acc[1][2 * p],     a1, q[p].x, q[p].y);
            mma16816(c.acc[1][2 * p + 1], a1, q[p].z, q[p].w);
        }
    }
}

__device__ __forceinline__ void epi_relu_h(MlpCtx& c, char* sm, int shOff, int b1Off) {
    int g = c.lane >> 2, t = c.lane & 3;
    const float* sb1 = (const float*)(sm + b1Off);
#pragma unroll
    for (int mt = 0; mt < 2; mt++)
#pragma unroll
        for (int nt = 0; nt < 8; nt++) {
            int row = c.wm * 32 + mt * 16 + g;
            int col = c.wn * 64 + nt * 8 + t * 2;
            float v0 = c.acc[mt][nt][0] + sb1[col];
            float v1 = c.acc[mt][nt][1] + sb1[col + 1];
            float v2 = c.acc[mt][nt][2] + sb1[col];
            float v3 = c.acc[mt][nt][3] + sb1[col + 1];
            v0 = v0 > 0.f ? v0 : 0.f; v1 = v1 > 0.f ? v1 : 0.f;
            v2 = v2 > 0.f ? v2 : 0.f; v3 = v3 > 0.f ? v3 : 0.f;
            *(__half2*)(sm + shOff + row * (PB * 2) + col * 2) = __floats2half2_rn(v0, v1);
            *(__half2*)(sm + shOff + (row + 8) * (PB * 2) + col * 2) = __floats2half2_rn(v2, v3);
        }
}

// write x (bias added) to global AND stage fp16 tile (PB pitch) at stageOff
__device__ __forceinline__ void epi_write_x_stage(MlpCtx& c, char* sm, int b2Off,
                                                  __half* __restrict__ xout, int n0,
                                                  int stageOff, bool doStage) {
    int g = c.lane >> 2, t = c.lane & 3;
    const float* sb2 = (const float*)(sm + b2Off);
#pragma unroll
    for (int mt = 0; mt < 2; mt++)
#pragma unroll
        for (int nt = 0; nt < 8; nt++) {
            int row = c.wm * 32 + mt * 16 + g;
            int col = c.wn * 64 + nt * 8 + t * 2;
            float bb0 = sb2[col], bb1 = sb2[col + 1];
            __half2 h0 = __floats2half2_rn(c.acc[mt][nt][0] + bb0, c.acc[mt][nt][1] + bb1);
            __half2 h1 = __floats2half2_rn(c.acc[mt][nt][2] + bb0, c.acc[mt][nt][3] + bb1);
            *(__half2*)(xout + (size_t)(n0 + row) * HH + col) = h0;
            *(__half2*)(xout + (size_t)(n0 + row + 8) * HH + col) = h1;
            if (doStage) {
                *(__half2*)(sm + stageOff + row * (PB * 2) + col * 2) = h0;
                *(__half2*)(sm + stageOff + (row + 8) * (PB * 2) + col * 2) = h1;
            }
        }
}

// fp16 writeout with optional global bias (for pd: + next-layer msg b1)
__device__ __forceinline__ void epi_write_gb(MlpCtx& c, __half* __restrict__ pout, int n0,
                                             const float* __restrict__ bias) {
    int g = c.lane >> 2, t = c.lane & 3;
#pragma unroll
    for (int mt = 0; mt < 2; mt++)
#pragma unroll
        for (int nt = 0; nt < 8; nt++) {
            int row = c.wm * 32 + mt * 16 + g;
            int col = c.wn * 64 + nt * 8 + t * 2;
            float bb0 = 0.f, bb1 = 0.f;
            if (bias) { bb0 = __ldg(bias + col); bb1 = __ldg(bias + col + 1); }
            __half2 h0 = __floats2half2_rn(c.acc[mt][nt][0] + bb0, c.acc[mt][nt][1] + bb1);
            __half2 h1 = __floats2half2_rn(c.acc[mt][nt][2] + bb0, c.acc[mt][nt][3] + bb1);
            *(__half2*)(pout + (size_t)(n0 + row) * HH + col) = h0;
            *(__half2*)(pout + (size_t)(n0 + row + 8) * HH + col) = h1;
        }
}

// compute pd/ps for next layer from fp16 x tile staged at aoff (PB pitch)
__device__ __forceinline__ void pre_from_stage(MlpCtx& c, uint32_t aoff,
                                               const uint4* __restrict__ nW1f,
                                               const float* __restrict__ nb1,
                                               __half* __restrict__ pd,
                                               __half* __restrict__ ps, int n0) {
    gemm_zero(c);
    gemm_run(c, aoff, PB * 2, nW1f, 8);
    epi_write_gb(c, pd, n0, nb1);          // pd gets msg b1 folded in
    gemm_zero(c);
    gemm_run(c, aoff, PB * 2, nW1f + 2048, 8);
    epi_write_gb(c, ps, n0, (const float*)0);
}

// ---------------------------------------------------------------------------
// edge scatter kernel (no MMA): H = relu(pd[dst]+ps[src]); aggH[dst] += H (fp16)
// ---------------------------------------------------------------------------
__global__ void __launch_bounds__(256)
edge_sc(const __half* __restrict__ pd, const __half* __restrict__ ps,
        const int* __restrict__ srcA, const int* __restrict__ dstA,
        __half* __restrict__ aggH) {
    int tid = threadIdx.x;
    int r = tid >> 1, h = tid & 1;
    int e = blockIdx.x * 128 + r;
    int dstn = dstA[e];
    int srcn = srcA[e];
    const uint4* prow = (const uint4*)(pd + (size_t)dstn * HH) + h * 8;
    const uint4* srow = (const uint4*)(ps + (size_t)srcn * HH) + h * 8;
    __half* arow = aggH + (size_t)dstn * HH + h * 64;
    const __half2 z = __half2half2(__ushort_as_half(0));
#pragma unroll
    for (int j = 0; j < 8; j++) {
        uint4 pv = __ldg(prow + j);
        uint4 sv = __ldg(srow + j);
        const __half2* pp = (const __half2*)&pv;
        const __half2* ss = (const __half2*)&sv;
        uint32_t o[4];
#pragma unroll
        for (int q = 0; q < 4; q++) {
            __half2 v = __hmax2(__hadd2(pp[q], ss[q]), z);
            o[q] = *(uint32_t*)&v;
        }
        red_add_h8(arow + j * 8, o[0], o[1], o[2], o[3]);
    }
}

// ---------------------------------------------------------------------------
// upd kernel: agg = aggH@mW2 + deg*mb2 ; x2 = mlp(cat(x,agg)) ; fused pre
// ---------------------------------------------------------------------------
__global__ void __launch_bounds__(256, 2)
upd_tc(const __half* __restrict__ xh, const __half* __restrict__ aggH,
       const uint4* __restrict__ mW2f, const float* __restrict__ mb2,
       const float* __restrict__ degf,
       const uint4* __restrict__ wf1, const uint4* __restrict__ wf2,
       const float* __restrict__ b1, const float* __restrict__ b2,
       __half* __restrict__ xout,
       const uint4* __restrict__ nW1f, const float* __restrict__ nb1,
       __half* __restrict__ pd, __half* __restrict__ ps, int do_pre) {
    extern __shared__ __align__(128) char sm[];
    MlpCtx c;
    c.sb = smem_u32(sm);
    int tid = threadIdx.x;
    c.lane = tid & 31;
    int warp = tid >> 5;
    c.wm = warp >> 1; c.wn = warp & 1;
    int n0 = blockIdx.x * 128;

    if (tid < 128) {
        ((float*)(sm + SB1_OFF))[tid] = b1[tid];
        ((float*)(sm + SB2_OFF))[tid] = b2[tid];
        ((float*)(sm + SB3_OFF))[tid] = mb2[tid];
        ((float*)(sm + SDG_OFF))[tid] = degf[n0 + tid];
    }
    // gather: h=0 -> x row into SA chunks 0-1; h=1 -> aggH row (fp16 copy) into T (SH)
    {
        int r = tid >> 1, h = tid & 1;
        int node = n0 + r;
        if (h == 0) {
            const uint4* row = (const uint4*)xh + (size_t)node * 16;
            uint4* dstp = (uint4*)(sm + SA_OFF + r * (PA * 2));
#pragma unroll
            for (int j = 0; j < 16; j++) dstp[j] = __ldg(row + j);
        } else {
            const uint4* ar = (const uint4*)(aggH + (size_t)node * HH);
            uint4* dstp = (uint4*)(sm + SH_OFF + r * (PB * 2));
#pragma unroll
            for (int j = 0; j < 16; j++) dstp[j] = __ldg(ar + j);
        }
    }
    __syncthreads();

    // GEMM_A: agg = T @ mW2 + deg*mb2 -> fp16 into SA chunks 2-3
    gemm_zero(c);
    gemm_run(c, SH_OFF, PB * 2, mW2f, 8);
    {
        int g = c.lane >> 2, t = c.lane & 3;
        const float* sb3 = (const float*)(sm + SB3_OFF);
        const float* sdg = (const float*)(sm + SDG_OFF);
#pragma unroll
        for (int mt = 0; mt < 2; mt++)
#pragma unroll
            for (int nt = 0; nt < 8; nt++) {
                int row = c.wm * 32 + mt * 16 + g;
                int col = c.wn * 64 + nt * 8 + t * 2;
                float d0 = sdg[row], d1 = sdg[row + 8];
                float bb0 = sb3[col], bb1 = sb3[col + 1];
                __half2 h0 = __floats2half2_rn(c.acc[mt][nt][0] + d0 * bb0,
                                               c.acc[mt][nt][1] + d0 * bb1);
                __half2 h1 = __floats2half2_rn(c.acc[mt][nt][2] + d1 * bb0,
                                               c.acc[mt][nt][3] + d1 * bb1);
                *(__half2*)(sm + SA_OFF + row * (PA * 2) + 256 + col * 2) = h0;
                *(__half2*)(sm + SA_OFF + (row + 8) * (PA * 2) + 256 + col * 2) = h1;
            }
    }
    __syncthreads();

    gemm_zero(c);
    gemm_run(c, SA_OFF, PA * 2, wf1, 16);
    epi_relu_h(c, sm, SH_OFF, SB1_OFF);
    __syncthreads();

    gemm_zero(c);
    gemm_run(c, SH_OFF, PB * 2, wf2, 8);
    epi_write_x_stage(c, sm, SB2_OFF, xout, n0, SA_OFF, do_pre != 0);

    if (do_pre) {
        __syncthreads();
        pre_from_stage(c, SA_OFF, nW1f, nb1, pd, ps, n0);
    }
}

// ---------------------------------------------------------------------------
// embed via HMMA + fused layer-0 pre
// ---------------------------------------------------------------------------
__global__ void __launch_bounds__(256, 2)
embed_tc(const float* __restrict__ loc, const float* __restrict__ vel,
         const uint4* __restrict__ wf1, const uint4* __restrict__ wf2,
         const float* __restrict__ b1, const float* __restrict__ b2,
         __half* __restrict__ xout,
         const uint4* __restrict__ nW1f, const float* __restrict__ nb1,
         __half* __restrict__ pd, __half* __restrict__ ps) {
    extern __shared__ __align__(128) char sm[];
    MlpCtx c;
    c.sb = smem_u32(sm);
    int tid = threadIdx.x;
    c.lane = tid & 31;
    int warp = tid >> 5;
    c.wm = warp >> 1; c.wn = warp & 1;
    int n0 = blockIdx.x * 128;

    if (tid < 128) {
        ((float*)(sm + EB1_OFF))[tid] = b1[tid];
        ((float*)(sm + EB2_OFF))[tid] = b2[tid];
    }
    if (tid < 128) {
        int r = tid;
        const float* lrow = loc + (size_t)(n0 + r) * 30;
        const float* vrow = vel + (size_t)(n0 + r) * 30;
        __half* drow = (__half*)(sm + EA_OFF + r * (PE * 2));
#pragma unroll
        for (int k = 0; k < 64; k++) {
            float v = 0.f;
            if (k < 60) {
                int f = k / 6, c6 = k % 6;
                v = (c6 < 3) ? lrow[f * 3 + c6] : vrow[f * 3 + c6 - 3];
            }
            drow[k] = __float2half(v);
        }
    }
    __syncthreads();

    gemm_zero(c);
    gemm_run(c, EA_OFF, PE * 2, wf1, 4);
    epi_relu_h(c, sm, EH_OFF, EB1_OFF);
    __syncthreads();

    gemm_zero(c);
    gemm_run(c, EH_OFF, PB * 2, wf2, 8);
    __syncthreads();
    epi_write_x_stage(c, sm, EB2_OFF, xout, n0, EH_OFF, true);
    __syncthreads();
    pre_from_stage(c, EH_OFF, nW1f, nb1, pd, ps, n0);
}

// ---------------------------------------------------------------------------
// head via HMMA
// ---------------------------------------------------------------------------
__global__ void __launch_bounds__(256, 2)
head_tc(const __half* __restrict__ xh,
        const uint4* __restrict__ wf1, const uint4* __restrict__ wf2,
        const float* __restrict__ b1, const float* __restrict__ b2,
        float* __restrict__ hout) {
    extern __shared__ __align__(128) char sm[];
    MlpCtx c;
    c.sb = smem_u32(sm);
    int tid = threadIdx.x;
    c.lane = tid & 31;
    int warp = tid >> 5;
    c.wm = warp >> 1; c.wn = warp & 1;
    int n0 = blockIdx.x * 128;

    if (tid < 128) ((float*)(sm + HB1_OFF))[tid] = b1[tid];
    if (tid < 30)  ((float*)(sm + HB2_OFF))[tid] = b2[tid];
    {
        int r = tid >> 1, h = tid & 1;
        const uint4* row = (const uint4*)xh + (size_t)(n0 + r) * 16 + h * 8;
        uint4* dstp = (uint4*)(sm + HA_OFF + r * (PB * 2)) + h * 8;
#pragma unroll
        for (int j = 0; j < 8; j++) dstp[j] = __ldg(row + j);
    }
    __syncthreads();

    gemm_zero(c);
    gemm_run(c, HA_OFF, PB * 2, wf1, 8);
    epi_relu_h(c, sm, HHS_OFF, HB1_OFF);
    __syncthreads();

    gemm_zero(c);
    gemm_run(c, HHS_OFF, PB * 2, wf2, 8);
    {
        int g = c.lane >> 2, t = c.lane & 3;
        const float* sb2 = (const float*)(sm + HB2_OFF);
        if (c.wn == 0) {
#pragma unroll
            for (int mt = 0; mt < 2; mt++)
#pragma unroll
                for (int nt = 0; nt < 4; nt++) {
                    int row = c.wm * 32 + mt * 16 + g;
                    int col = nt * 8 + t * 2;
                    if (col < 30) {
                        hout[(size_t)(n0 + row) * 30 + col] = c.acc[mt][nt][0] + sb2[col];
                        hout[(size_t)(n0 + row + 8) * 30 + col] = c.acc[mt][nt][2] + sb2[col];
                    }
                    if (col + 1 < 30) {
                        hout[(size_t)(n0 + row) * 30 + col + 1] = c.acc[mt][nt][1] + sb2[col + 1];
                        hout[(size_t)(n0 + row + 8) * 30 + col + 1] = c.acc[mt][nt][3] + sb2[col + 1];
                    }
                }
        }
    }
}

// ---------------------------------------------------------------------------
// loss
// ---------------------------------------------------------------------------
__global__ void loss_kernel(const float* __restrict__ hout, const float* __restrict__ loc,
                            const float* __restrict__ y, float* __restrict__ out) {
    int w = (blockIdx.x * blockDim.x + threadIdx.x) >> 5;
    int lane = threadIdx.x & 31;
    if (w >= BB) return;
    float ade = 0.f, fde = 0.f;
    for (int p = lane; p < 160; p += 32) {
        int node = w * 16 + p / NF;
        int f = p % NF;
        int base = node * 30 + f * 3;
        float dx = hout[base] + loc[base] - y[base];
        float dy = hout[base + 1] + loc[base + 1] - y[base + 1];
        float dz = hout[base + 2] + loc[base + 2] - y[base + 2];
        float d = sqrtf(dx * dx + dy * dy + dz * dz);
        ade += d;
        if (f == NF - 1) fde += d;
    }
#pragma unroll
    for (int o = 16; o; o >>= 1) {
        ade += __shfl_down_sync(0xffffffffu, ade, o);
        fde += __shfl_down_sync(0xffffffffu, fde, o);
    }
    if (lane == 0) {
        out[1 + w] = ade / 160.f;
        out[1 + BB + w] = fde / 16.f;
    }
}

__global__ void final_kernel(float* __restrict__ out) {
    __shared__ float s[256];
    float v = 0.f;
    for (int i = threadIdx.x; i < BB; i += 256) v += out[1 + i];
    s[threadIdx.x] = v;
    __syncthreads();
    for (int o = 128; o; o >>= 1) {
        if (threadIdx.x < o) s[threadIdx.x] += s[threadIdx.x + o];
        __syncthreads();
    }
    if (threadIdx.x == 0) out[0] = s[0] / (float)BB;
}

// ---------------------------------------------------------------------------
// host
// ---------------------------------------------------------------------------
extern "C" void kernel_launch(void* const* d_in, const int* in_sizes, int n_in,
                              void* d_out, int out_size) {
    int o = (n_in > 4 && in_sizes[4] == 1) ? 1 : 0;
    const float* loc = (const float*)d_in[0];
    const float* vel = (const float*)d_in[1];
    const float* y   = (const float*)d_in[2];
    const void*  eix = d_in[3];
    const float* embW1 = (const float*)d_in[4 + o];
    const float* embb1 = (const float*)d_in[5 + o];
    const float* embW2 = (const float*)d_in[6 + o];
    const float* embb2 = (const float*)d_in[7 + o];
    const float* msgW1 = (const float*)d_in[8 + o];
    const float* msgb1 = (const float*)d_in[9 + o];
    const float* msgW2 = (const float*)d_in[10 + o];
    const float* msgb2 = (const float*)d_in[11 + o];
    const float* updW1 = (const float*)d_in[12 + o];
    const float* updb1 = (const float*)d_in[13 + o];
    const float* updW2 = (const float*)d_in[14 + o];
    const float* updb2 = (const float*)d_in[15 + o];
    const float* hW1 = (const float*)d_in[16 + o];
    const float* hb1 = (const float*)d_in[17 + o];
    const float* hW2 = (const float*)d_in[18 + o];
    const float* hb2 = (const float*)d_in[19 + o];
    float* out = (float*)d_out;

    cudaFuncSetAttribute(upd_tc, cudaFuncAttributeMaxDynamicSharedMemorySize, DYNB_U);
    cudaFuncSetAttribute(embed_tc, cudaFuncAttributeMaxDynamicSharedMemorySize, DYNB_EM);
    cudaFuncSetAttribute(head_tc, cudaFuncAttributeMaxDynamicSharedMemorySize, DYNB_H);

    __half *xhp, *xh2p, *pdp, *psp, *agghp;
    float *headp, *degp;
    int *srcp, *dstp;
    uint4 *mW1f, *mW2f, *uW1f, *uW2f, *eW1f, *eW2f, *hW1f, *hW2f;
    cudaGetSymbolAddress((void**)&xhp, g_xh);
    cudaGetSymbolAddress((void**)&xh2p, g_xh2);
    cudaGetSymbolAddress((void**)&pdp, g_pd);
    cudaGetSymbolAddress((void**)&psp, g_ps);
    cudaGetSymbolAddress((void**)&agghp, g_aggh);
    cudaGetSymbolAddress((void**)&degp, g_degf);
    cudaGetSymbolAddress((void**)&headp, g_head);
    cudaGetSymbolAddress((void**)&srcp, g_srcA);
    cudaGetSymbolAddress((void**)&dstp, g_dstA);
    cudaGetSymbolAddress((void**)&mW1f, g_mW1f);
    cudaGetSymbolAddress((void**)&mW2f, g_mW2f);
    cudaGetSymbolAddress((void**)&uW1f, g_uW1f);
    cudaGetSymbolAddress((void**)&uW2f, g_uW2f);
    cudaGetSymbolAddress((void**)&eW1f, g_eW1f);
    cudaGetSymbolAddress((void**)&eW2f, g_eW2f);
    cudaGetSymbolAddress((void**)&hW1f, g_hW1f);
    cudaGetSymbolAddress((void**)&hW2f, g_hW2f);

    detect_kernel<<<1, 32>>>((const int*)eix);
    cudaMemsetAsync(degp, 0, NN * sizeof(float));
    idx_kernel<<<EE / 256, 256>>>(eix);
    prep_fragk<<<dim3(LL, 16), 256>>>(msgW1, (__half*)mW1f, 256, 128, 128, 256 * 128, 32768);
    prep_fragk<<<dim3(LL, 16), 256>>>(updW1, (__half*)uW1f, 256, 128, 128, 256 * 128, 32768);
    prep_fragk<<<dim3(LL, 8), 256>>>(msgW2, (__half*)mW2f, 128, 128, 128, 128 * 128, 16384);
    prep_fragk<<<dim3(LL, 8), 256>>>(updW2, (__half*)uW2f, 128, 128, 128, 128 * 128, 16384);
    prep_fragk<<<dim3(1, 4), 256>>>(embW1, (__half*)eW1f, 60, 128, 128, 0, 0);
    prep_fragk<<<dim3(1, 8), 256>>>(embW2, (__half*)eW2f, 128, 128, 128, 0, 0);
    prep_fragk<<<dim3(1, 8), 256>>>(hW1, (__half*)hW1f, 128, 128, 128, 0, 0);
    prep_fragk<<<dim3(1, 8), 256>>>(hW2, (__half*)hW2f, 128, 30, 30, 0, 0);

    embed_tc<<<NN / 128, 256, DYNB_EM>>>(loc, vel, eW1f, eW2f, embb1, embb2, xhp,
                                         mW1f, msgb1, pdp, psp);

    __half* xa = xhp;
    __half* xb = xh2p;
    for (int i = 0; i < LL; i++) {
        cudaMemsetAsync(agghp, 0, (size_t)NN * HH * sizeof(__half));
        edge_sc<<<EE / 128, 256>>>(pdp, psp, srcp, dstp, agghp);
        upd_tc<<<NN / 128, 256, DYNB_U>>>(
            xa, agghp,
            mW2f + (size_t)i * 2048, msgb2 + (size_t)i * HH, degp,
            uW1f + (size_t)i * 4096, uW2f + (size_t)i * 2048,
            updb1 + (size_t)i * HH, updb2 + (size_t)i * HH, xb,
            mW1f + (size_t)(i + 1 < LL ? i + 1 : 0) * 4096,
            msgb1 + (size_t)(i + 1 < LL ? i + 1 : 0) * HH, pdp, psp,
            i + 1 < LL ? 1 : 0);
        __half* t = xa; xa = xb; xb = t;
    }
    head_tc<<<NN / 128, 256, DYNB_H>>>(xa, hW1f, hW2f, hb1, hb2, headp);
    loss_kernel<<<(BB * 32 + 127) / 128, 128>>>(headp, loc, y, out);
    final_kernel<<<1, 256>>>(out);
}

// round 13
// speedup vs baseline: 26.6089x; 2.0985x over previous
#include <cuda_runtime.h>
#include <cuda_fp16.h>
#include <math.h>
#include <stdint.h>

#define NN 32768
#define EE 524288
#define HH 128
#define BB 2048
#define LL 7
#define NF 10

// ---------------------------------------------------------------------------
// device scratch
// ---------------------------------------------------------------------------
__device__ int    g_is64;
__device__ __half g_xh[NN * HH];
__device__ __half g_xh2[NN * HH];
__device__ __half g_pd[NN * HH];       // x @ W1_top + b1 (indexed by dst)
__device__ __half g_ps[NN * HH];       // x @ W1_bot      (indexed by src)
__device__ __half g_aggh[NN * HH];     // per-node aggregated H (fp16)
__device__ int    g_degi[NN];
__device__ float  g_head[NN * 30];
__device__ int    g_srcA[EE];
__device__ int    g_dstA[EE];
__device__ int    g_csrs[EE];          // src per CSR slot (grouped by dst)
__device__ int    g_rowp[NN + 1];
__device__ int    g_cursor[NN];
// fragment-order fp16 weight images (uint4 = one lane's 16B B-fragment)
__device__ uint4 g_mW1f[LL * 4096];
__device__ uint4 g_mW2f[LL * 2048];
__device__ uint4 g_uW1f[LL * 4096];
__device__ uint4 g_uW2f[LL * 2048];
__device__ uint4 g_eW1f[1024];         // K=64 (4 ks)
__device__ uint4 g_eW2f[2048];         // K=128 (8 ks)
__device__ uint4 g_hW1f[2048];         // head W1, K=128
__device__ uint4 g_hW2f[2048];         // head W2, K=128, N=30 (padded)

// pitches in halfs
#define PA 264   // K=256 + 8 pad
#define PB 136   // K=128 + 8 pad  (272 B)
#define PE 72    // K=64  + 8 pad

// ---- upd kernel smem ----
#define SA_OFF   0
#define SH_OFF   (128 * PA * 2)                  // 67584 (T/H tile, PB pitch)
#define SB1_OFF  (SH_OFF + 128 * PB * 2)         // 102400
#define SB2_OFF  (SB1_OFF + 512)
#define SB3_OFF  (SB2_OFF + 512)                 // msg b2
#define SDG_OFF  (SB3_OFF + 512)                 // deg[128]
#define DYNB_U   (SDG_OFF + 512)

// ---- embed smem ----
#define EA_OFF   0
#define EH_OFF   (128 * PE * 2)                  // 18432
#define EB1_OFF  (EH_OFF + 128 * PB * 2)         // 53248
#define EB2_OFF  (EB1_OFF + 512)
#define DYNB_EM  (EB2_OFF + 512)

// ---- head smem ----
#define HA_OFF   0
#define HHS_OFF  (128 * PB * 2)                  // 34816
#define HB1_OFF  (HHS_OFF + 128 * PB * 2)        // 69632
#define HB2_OFF  (HB1_OFF + 512)
#define DYNB_H   (HB2_OFF + 512)

__device__ __forceinline__ uint32_t smem_u32(const void* p) {
    uint32_t a;
    asm("{ .reg .u64 t; cvta.to.shared.u64 t, %1; cvt.u32.u64 %0, t; }" : "=r"(a) : "l"(p));
    return a;
}

__device__ __forceinline__ void ldsm_x4(uint32_t r[4], uint32_t addr) {
    asm volatile("ldmatrix.sync.aligned.m8n8.x4.shared.b16 {%0,%1,%2,%3}, [%4];"
                 : "=r"(r[0]), "=r"(r[1]), "=r"(r[2]), "=r"(r[3]) : "r"(addr));
}

__device__ __forceinline__ void mma16816(float c[4], const uint32_t a[4],
                                         uint32_t b0, uint32_t b1) {
    asm volatile(
        "mma.sync.aligned.m16n8k16.row.col.f32.f16.f16.f32 "
        "{%0,%1,%2,%3},{%4,%5,%6,%7},{%8,%9},{%0,%1,%2,%3};"
        : "+f"(c[0]), "+f"(c[1]), "+f"(c[2]), "+f"(c[3])
        : "r"(a[0]), "r"(a[1]), "r"(a[2]), "r"(a[3]), "r"(b0), "r"(b1));
}

__device__ __forceinline__ int load_idx(const void* p, long long i) {
    if (g_is64) return (int)((const long long*)p)[i];
    return ((const int*)p)[i];
}

__global__ void detect_kernel(const int* e) {
    if (threadIdx.x == 0) {
        int is64 = 1;
        for (int i = 1; i < 256; i += 2)
            if (e[i] != 0) { is64 = 0; break; }
        g_is64 = is64;
    }
}

// convert indices to int32 + integer in-degree
__global__ void idx_kernel(const void* __restrict__ eidx) {
    int i = blockIdx.x * blockDim.x + threadIdx.x;
    if (i >= EE) return;
    g_srcA[i] = load_idx(eidx, i);
    int d = load_idx(eidx, (long long)EE + i);
    g_dstA[i] = d;
    atomicAdd(&g_degi[d], 1);
}

// single-block scan: rowp = exclusive prefix of degi; cursor = rowp
__global__ void scan_kernel() {
    __shared__ int s[1024];
    __shared__ int srun;
    int tid = threadIdx.x;
    if (tid == 0) srun = 0;
    __syncthreads();
    for (int c = 0; c < NN; c += 1024) {
        int v = g_degi[c + tid];
        s[tid] = v;
        __syncthreads();
        for (int off = 1; off < 1024; off <<= 1) {
            int t = (tid >= off) ? s[tid - off] : 0;
            __syncthreads();
            s[tid] += t;
            __syncthreads();
        }
        int excl = srun + s[tid] - v;
        g_rowp[c + tid] = excl;
        g_cursor[c + tid] = excl;
        __syncthreads();
        if (tid == 0) srun += s[1023];
        __syncthreads();
    }
    if (tid == 0) g_rowp[NN] = srun;
}

__global__ void fill_kernel() {
    int i = blockIdx.x * blockDim.x + threadIdx.x;
    if (i >= EE) return;
    int pos = atomicAdd(&g_cursor[g_dstA[i]], 1);
    g_csrs[pos] = g_srcA[i];
}

// ---------------------------------------------------------------------------
// weight prep: fp32 [k][n] -> fragment-order fp16 image
// ---------------------------------------------------------------------------
__global__ void prep_fragk(const float* __restrict__ src, __half* __restrict__ dst,
                           int Ktrue, int Ntrue, int srcWidth,
                           int srcStride, int dstStride) {
    int l = blockIdx.x, ks = blockIdx.y;
    src += (size_t)l * srcStride;
    dst += (size_t)l * dstStride + (size_t)ks * 2048;
    int tid = threadIdx.x;
    int lane = tid & 31, p = (tid >> 5) & 3, wn = (tid >> 7) & 1;
    uint4 v;
    __half* hv = (__half*)&v;
#pragma unroll
    for (int h = 0; h < 8; h++) {
        int k = ks * 16 + (lane & 3) * 2 + (h & 1) + ((h >> 1) & 1) * 8;
        int n = wn * 64 + p * 16 + (lane >> 2) + (h >> 2) * 8;
        hv[h] = (k < Ktrue && n < Ntrue) ? __float2half(src[k * srcWidth + n]) : __half(0.f);
    }
    ((uint4*)dst)[tid] = v;
}

// ---------------------------------------------------------------------------
// HMMA core: 128 rows per tile, 256 threads (8 warps, warp tile 32x64)
// ---------------------------------------------------------------------------
struct MlpCtx {
    uint32_t sb;
    int lane, wm, wn;
    float acc[2][8][4];
};

__device__ __forceinline__ void gemm_zero(MlpCtx& c) {
#pragma unroll
    for (int mt = 0; mt < 2; mt++)
#pragma unroll
        for (int nt = 0; nt < 8; nt++)
#pragma unroll
            for (int q = 0; q < 4; q++) c.acc[mt][nt][q] = 0.f;
}

__device__ __forceinline__ void gemm_run(MlpCtx& c, uint32_t aoff, uint32_t pbytes,
                                         const uint4* __restrict__ wf, int ksteps) {
    int l = c.lane;
    uint32_t aBase = c.sb + aoff +
        (uint32_t)(c.wm * 32 + (l & 7) + ((l >> 3) & 1) * 8) * pbytes + (l >> 4) * 16;
    const uint4* wb = wf + c.wn * 128 + l;
#pragma unroll
    for (int ks = 0; ks < 16; ks++) {
        if (ks >= ksteps) break;
        uint32_t a0[4], a1[4];
        uint4 q[4];
#pragma unroll
        for (int p = 0; p < 4; p++) q[p] = __ldg(wb + ks * 256 + p * 32);
        ldsm_x4(a0, aBase + ks * 32);
        ldsm_x4(a1, aBase + 16 * pbytes + ks * 32);
#pragma unroll
        for (int p = 0; p < 4; p++) {
            mma16816(c.acc[0][2 * p],     a0, q[p].x, q[p].y);
            mma16816(c.acc[0][2 * p + 1], a0, q[p].z, q[p].w);
            mma16816(c.acc[1][2 * p],     a1, q[p].x, q[p].y);
            mma16816(c.acc[1][2 * p + 1], a1, q[p].z, q[p].w);
        }
    }
}

__device__ __forceinline__ void epi_relu_h(MlpCtx& c, char* sm, int shOff, int b1Off) {
    int g = c.lane >> 2, t = c.lane & 3;
    const float* sb1 = (const float*)(sm + b1Off);
#pragma unroll
    for (int mt = 0; mt < 2; mt++)
#pragma unroll
        for (int nt = 0; nt < 8; nt++) {
            int row = c.wm * 32 + mt * 16 + g;
            int col = c.wn * 64 + nt * 8 + t * 2;
            float v0 = c.acc[mt][nt][0] + sb1[col];
            float v1 = c.acc[mt][nt][1] + sb1[col + 1];
            float v2 = c.acc[mt][nt][2] + sb1[col];
            float v3 = c.acc[mt][nt][3] + sb1[col + 1];
            v0 = v0 > 0.f ? v0 : 0.f; v1 = v1 > 0.f ? v1 : 0.f;
            v2 = v2 > 0.f ? v2 : 0.f; v3 = v3 > 0.f ? v3 : 0.f;
            *(__half2*)(sm + shOff + row * (PB * 2) + col * 2) = __floats2half2_rn(v0, v1);
            *(__half2*)(sm + shOff + (row + 8) * (PB * 2) + col * 2) = __floats2half2_rn(v2, v3);
        }
}

__device__ __forceinline__ void epi_write_x_stage(MlpCtx& c, char* sm, int b2Off,
                                                  __half* __restrict__ xout, int n0,
                                                  int stageOff, bool doStage) {
    int g = c.lane >> 2, t = c.lane & 3;
    const float* sb2 = (const float*)(sm + b2Off);
#pragma unroll
    for (int mt = 0; mt < 2; mt++)
#pragma unroll
        for (int nt = 0; nt < 8; nt++) {
            int row = c.wm * 32 + mt * 16 + g;
            int col = c.wn * 64 + nt * 8 + t * 2;
            float bb0 = sb2[col], bb1 = sb2[col + 1];
            __half2 h0 = __floats2half2_rn(c.acc[mt][nt][0] + bb0, c.acc[mt][nt][1] + bb1);
            __half2 h1 = __floats2half2_rn(c.acc[mt][nt][2] + bb0, c.acc[mt][nt][3] + bb1);
            *(__half2*)(xout + (size_t)(n0 + row) * HH + col) = h0;
            *(__half2*)(xout + (size_t)(n0 + row + 8) * HH + col) = h1;
            if (doStage) {
                *(__half2*)(sm + stageOff + row * (PB * 2) + col * 2) = h0;
                *(__half2*)(sm + stageOff + (row + 8) * (PB * 2) + col * 2) = h1;
            }
        }
}

__device__ __forceinline__ void epi_write_gb(MlpCtx& c, __half* __restrict__ pout, int n0,
                                             const float* __restrict__ bias) {
    int g = c.lane >> 2, t = c.lane & 3;
#pragma unroll
    for (int mt = 0; mt < 2; mt++)
#pragma unroll
        for (int nt = 0; nt < 8; nt++) {
            int row = c.wm * 32 + mt * 16 + g;
            int col = c.wn * 64 + nt * 8 + t * 2;
            float bb0 = 0.f, bb1 = 0.f;
            if (bias) { bb0 = __ldg(bias + col); bb1 = __ldg(bias + col + 1); }
            __half2 h0 = __floats2half2_rn(c.acc[mt][nt][0] + bb0, c.acc[mt][nt][1] + bb1);
            __half2 h1 = __floats2half2_rn(c.acc[mt][nt][2] + bb0, c.acc[mt][nt][3] + bb1);
            *(__half2*)(pout + (size_t)(n0 + row) * HH + col) = h0;
            *(__half2*)(pout + (size_t)(n0 + row + 8) * HH + col) = h1;
        }
}

__device__ __forceinline__ void pre_from_stage(MlpCtx& c, uint32_t aoff,
                                               const uint4* __restrict__ nW1f,
                                               const float* __restrict__ nb1,
                                               __half* __restrict__ pd,
                                               __half* __restrict__ ps, int n0) {
    gemm_zero(c);
    gemm_run(c, aoff, PB * 2, nW1f, 8);
    epi_write_gb(c, pd, n0, nb1);
    gemm_zero(c);
    gemm_run(c, aoff, PB * 2, nW1f + 2048, 8);
    epi_write_gb(c, ps, n0, (const float*)0);
}

// ---------------------------------------------------------------------------
// CSR aggregation: one warp per node; aggH[n] = sum_e relu(pd[n]+ps[src_e])
// fp32 register accumulation; lane owns 8B (4 halfs) of the 256B row
// ---------------------------------------------------------------------------
__global__ void __launch_bounds__(256)
agg_csr(const __half* __restrict__ pd, const __half* __restrict__ ps,
        const int* __restrict__ csrs, const int* __restrict__ rowp,
        __half* __restrict__ aggH) {
    int w = (blockIdx.x * 256 + threadIdx.x) >> 5;
    int lane = threadIdx.x & 31;
    if (w >= NN) return;
    int beg = __ldg(rowp + w), end = __ldg(rowp + w + 1);

    uint2 pdu = ((const uint2*)(pd + (size_t)w * HH))[lane];
    __half2 pd0 = *(__half2*)&pdu.x, pd1 = *(__half2*)&pdu.y;
    float2 p0 = __half22float2(pd0), p1 = __half22float2(pd1);
    float a0 = 0.f, a1 = 0.f, a2 = 0.f, a3 = 0.f;

    int i = beg;
    for (; i + 1 < end; i += 2) {
        int s0 = __ldg(csrs + i), s1 = __ldg(csrs + i + 1);
        uint2 v0 = __ldg((const uint2*)(ps + (size_t)s0 * HH) + lane);
        uint2 v1 = __ldg((const uint2*)(ps + (size_t)s1 * HH) + lane);
        float2 q0 = __half22float2(*(__half2*)&v0.x);
        float2 q1 = __half22float2(*(__half2*)&v0.y);
        float2 r0 = __half22float2(*(__half2*)&v1.x);
        float2 r1 = __half22float2(*(__half2*)&v1.y);
        a0 += fmaxf(p0.x + q0.x, 0.f) + fmaxf(p0.x + r0.x, 0.f);
        a1 += fmaxf(p0.y + q0.y, 0.f) + fmaxf(p0.y + r0.y, 0.f);
        a2 += fmaxf(p1.x + q1.x, 0.f) + fmaxf(p1.x + r1.x, 0.f);
        a3 += fmaxf(p1.y + q1.y, 0.f) + fmaxf(p1.y + r1.y, 0.f);
    }
    if (i < end) {
        int s0 = __ldg(csrs + i);
        uint2 v0 = __ldg((const uint2*)(ps + (size_t)s0 * HH) + lane);
        float2 q0 = __half22float2(*(__half2*)&v0.x);
        float2 q1 = __half22float2(*(__half2*)&v0.y);
        a0 += fmaxf(p0.x + q0.x, 0.f);
        a1 += fmaxf(p0.y + q0.y, 0.f);
        a2 += fmaxf(p1.x + q1.x, 0.f);
        a3 += fmaxf(p1.y + q1.y, 0.f);
    }
    __half2 o0 = __floats2half2_rn(a0, a1);
    __half2 o1 = __floats2half2_rn(a2, a3);
    uint2 ov;
    ov.x = *(uint32_t*)&o0; ov.y = *(uint32_t*)&o1;
    ((uint2*)(aggH + (size_t)w * HH))[lane] = ov;
}

// ---------------------------------------------------------------------------
// upd kernel: agg = aggH@mW2 + deg*mb2 ; x2 = mlp(cat(x,agg)) ; fused pre
// ---------------------------------------------------------------------------
__global__ void __launch_bounds__(256, 2)
upd_tc(const __half* __restrict__ xh, const __half* __restrict__ aggH,
       const uint4* __restrict__ mW2f, const float* __restrict__ mb2,
       const int* __restrict__ degi,
       const uint4* __restrict__ wf1, const uint4* __restrict__ wf2,
       const float* __restrict__ b1, const float* __restrict__ b2,
       __half* __restrict__ xout,
       const uint4* __restrict__ nW1f, const float* __restrict__ nb1,
       __half* __restrict__ pd, __half* __restrict__ ps, int do_pre) {
    extern __shared__ __align__(128) char sm[];
    MlpCtx c;
    c.sb = smem_u32(sm);
    int tid = threadIdx.x;
    c.lane = tid & 31;
    int warp = tid >> 5;
    c.wm = warp >> 1; c.wn = warp & 1;
    int n0 = blockIdx.x * 128;

    if (tid < 128) {
        ((float*)(sm + SB1_OFF))[tid] = b1[tid];
        ((float*)(sm + SB2_OFF))[tid] = b2[tid];
        ((float*)(sm + SB3_OFF))[tid] = mb2[tid];
        ((float*)(sm + SDG_OFF))[tid] = (float)degi[n0 + tid];
    }
    {
        int r = tid >> 1, h = tid & 1;
        int node = n0 + r;
        if (h == 0) {
            const uint4* row = (const uint4*)xh + (size_t)node * 16;
            uint4* dstp = (uint4*)(sm + SA_OFF + r * (PA * 2));
#pragma unroll
            for (int j = 0; j < 16; j++) dstp[j] = __ldg(row + j);
        } else {
            const uint4* ar = (const uint4*)(aggH + (size_t)node * HH);
            uint4* dstp = (uint4*)(sm + SH_OFF + r * (PB * 2));
#pragma unroll
            for (int j = 0; j < 16; j++) dstp[j] = __ldg(ar + j);
        }
    }
    __syncthreads();

    // GEMM_A: agg = T @ mW2 + deg*mb2 -> fp16 into SA chunks 2-3
    gemm_zero(c);
    gemm_run(c, SH_OFF, PB * 2, mW2f, 8);
    {
        int g = c.lane >> 2, t = c.lane & 3;
        const float* sb3 = (const float*)(sm + SB3_OFF);
        const float* sdg = (const float*)(sm + SDG_OFF);
#pragma unroll
        for (int mt = 0; mt < 2; mt++)
#pragma unroll
            for (int nt = 0; nt < 8; nt++) {
                int row = c.wm * 32 + mt * 16 + g;
                int col = c.wn * 64 + nt * 8 + t * 2;
                float d0 = sdg[row], d1 = sdg[row + 8];
                float bb0 = sb3[col], bb1 = sb3[col + 1];
                __half2 h0 = __floats2half2_rn(c.acc[mt][nt][0] + d0 * bb0,
                                               c.acc[mt][nt][1] + d0 * bb1);
                __half2 h1 = __floats2half2_rn(c.acc[mt][nt][2] + d1 * bb0,
                                               c.acc[mt][nt][3] + d1 * bb1);
                *(__half2*)(sm + SA_OFF + row * (PA * 2) + 256 + col * 2) = h0;
                *(__half2*)(sm + SA_OFF + (row + 8) * (PA * 2) + 256 + col * 2) = h1;
            }
    }
    __syncthreads();

    gemm_zero(c);
    gemm_run(c, SA_OFF, PA * 2, wf1, 16);
    epi_relu_h(c, sm, SH_OFF, SB1_OFF);
    __syncthreads();

    gemm_zero(c);
    gemm_run(c, SH_OFF, PB * 2, wf2, 8);
    epi_write_x_stage(c, sm, SB2_OFF, xout, n0, SA_OFF, do_pre != 0);

    if (do_pre) {
        __syncthreads();
        pre_from_stage(c, SA_OFF, nW1f, nb1, pd, ps, n0);
    }
}

// ---------------------------------------------------------------------------
// embed via HMMA + fused layer-0 pre
// ---------------------------------------------------------------------------
__global__ void __launch_bounds__(256, 2)
embed_tc(const float* __restrict__ loc, const float* __restrict__ vel,
         const uint4* __restrict__ wf1, const uint4* __restrict__ wf2,
         const float* __restrict__ b1, const float* __restrict__ b2,
         __half* __restrict__ xout,
         const uint4* __restrict__ nW1f, const float* __restrict__ nb1,
         __half* __restrict__ pd, __half* __restrict__ ps) {
    extern __shared__ __align__(128) char sm[];
    MlpCtx c;
    c.sb = smem_u32(sm);
    int tid = threadIdx.x;
    c.lane = tid & 31;
    int warp = tid >> 5;
    c.wm = warp >> 1; c.wn = warp & 1;
    int n0 = blockIdx.x * 128;

    if (tid < 128) {
        ((float*)(sm + EB1_OFF))[tid] = b1[tid];
        ((float*)(sm + EB2_OFF))[tid] = b2[tid];
    }
    if (tid < 128) {
        int r = tid;
        const float* lrow = loc + (size_t)(n0 + r) * 30;
        const float* vrow = vel + (size_t)(n0 + r) * 30;
        __half* drow = (__half*)(sm + EA_OFF + r * (PE * 2));
#pragma unroll
        for (int k = 0; k < 64; k++) {
            float v = 0.f;
            if (k < 60) {
                int f = k / 6, c6 = k % 6;
                v = (c6 < 3) ? lrow[f * 3 + c6] : vrow[f * 3 + c6 - 3];
            }
            drow[k] = __float2half(v);
        }
    }
    __syncthreads();

    gemm_zero(c);
    gemm_run(c, EA_OFF, PE * 2, wf1, 4);
    epi_relu_h(c, sm, EH_OFF, EB1_OFF);
    __syncthreads();

    gemm_zero(c);
    gemm_run(c, EH_OFF, PB * 2, wf2, 8);
    __syncthreads();
    epi_write_x_stage(c, sm, EB2_OFF, xout, n0, EH_OFF, true);
    __syncthreads();
    pre_from_stage(c, EH_OFF, nW1f, nb1, pd, ps, n0);
}

// ---------------------------------------------------------------------------
// head via HMMA
// ---------------------------------------------------------------------------
__global__ void __launch_bounds__(256, 2)
head_tc(const __half* __restrict__ xh,
        const uint4* __restrict__ wf1, const uint4* __restrict__ wf2,
        const float* __restrict__ b1, const float* __restrict__ b2,
        float* __restrict__ hout) {
    extern __shared__ __align__(128) char sm[];
    MlpCtx c;
    c.sb = smem_u32(sm);
    int tid = threadIdx.x;
    c.lane = tid & 31;
    int warp = tid >> 5;
    c.wm = warp >> 1; c.wn = warp & 1;
    int n0 = blockIdx.x * 128;

    if (tid < 128) ((float*)(sm + HB1_OFF))[tid] = b1[tid];
    if (tid < 30)  ((float*)(sm + HB2_OFF))[tid] = b2[tid];
    {
        int r = tid >> 1, h = tid & 1;
        const uint4* row = (const uint4*)xh + (size_t)(n0 + r) * 16 + h * 8;
        uint4* dstp = (uint4*)(sm + HA_OFF + r * (PB * 2)) + h * 8;
#pragma unroll
        for (int j = 0; j < 8; j++) dstp[j] = __ldg(row + j);
    }
    __syncthreads();

    gemm_zero(c);
    gemm_run(c, HA_OFF, PB * 2, wf1, 8);
    epi_relu_h(c, sm, HHS_OFF, HB1_OFF);
    __syncthreads();

    gemm_zero(c);
    gemm_run(c, HHS_OFF, PB * 2, wf2, 8);
    {
        int g = c.lane >> 2, t = c.lane & 3;
        const float* sb2 = (const float*)(sm + HB2_OFF);
        if (c.wn == 0) {
#pragma unroll
            for (int mt = 0; mt < 2; mt++)
#pragma unroll
                for (int nt = 0; nt < 4; nt++) {
                    int row = c.wm * 32 + mt * 16 + g;
                    int col = nt * 8 + t * 2;
                    if (col < 30) {
                        hout[(size_t)(n0 + row) * 30 + col] = c.acc[mt][nt][0] + sb2[col];
                        hout[(size_t)(n0 + row + 8) * 30 + col] = c.acc[mt][nt][2] + sb2[col];
                    }
                    if (col + 1 < 30) {
                        hout[(size_t)(n0 + row) * 30 + col + 1] = c.acc[mt][nt][1] + sb2[col + 1];
                        hout[(size_t)(n0 + row + 8) * 30 + col + 1] = c.acc[mt][nt][3] + sb2[col + 1];
                    }
                }
        }
    }
}

// ---------------------------------------------------------------------------
// loss
// ---------------------------------------------------------------------------
__global__ void loss_kernel(const float* __restrict__ hout, const float* __restrict__ loc,
                            const float* __restrict__ y, float* __restrict__ out) {
    int w = (blockIdx.x * blockDim.x + threadIdx.x) >> 5;
    int lane = threadIdx.x & 31;
    if (w >= BB) return;
    float ade = 0.f, fde = 0.f;
    for (int p = lane; p < 160; p += 32) {
        int node = w * 16 + p / NF;
        int f = p % NF;
        int base = node * 30 + f * 3;
        float dx = hout[base] + loc[base] - y[base];
        float dy = hout[base + 1] + loc[base + 1] - y[base + 1];
        float dz = hout[base + 2] + loc[base + 2] - y[base + 2];
        float d = sqrtf(dx * dx + dy * dy + dz * dz);
        ade += d;
        if (f == NF - 1) fde += d;
    }
#pragma unroll
    for (int o = 16; o; o >>= 1) {
        ade += __shfl_down_sync(0xffffffffu, ade, o);
        fde += __shfl_down_sync(0xffffffffu, fde, o);
    }
    if (lane == 0) {
        out[1 + w] = ade / 160.f;
        out[1 + BB + w] = fde / 16.f;
    }
}

__global__ void final_kernel(float* __restrict__ out) {
    __shared__ float s[256];
    float v = 0.f;
    for (int i = threadIdx.x; i < BB; i += 256) v += out[1 + i];
    s[threadIdx.x] = v;
    __syncthreads();
    for (int o = 128; o; o >>= 1) {
        if (threadIdx.x < o) s[threadIdx.x] += s[threadIdx.x + o];
        __syncthreads();
    }
    if (threadIdx.x == 0) out[0] = s[0] / (float)BB;
}

// ---------------------------------------------------------------------------
// host
// ---------------------------------------------------------------------------
extern "C" void kernel_launch(void* const* d_in, const int* in_sizes, int n_in,
                              void* d_out, int out_size) {
    int o = (n_in > 4 && in_sizes[4] == 1) ? 1 : 0;
    const float* loc = (const float*)d_in[0];
    const float* vel = (const float*)d_in[1];
    const float* y   = (const float*)d_in[2];
    const void*  eix = d_in[3];
    const float* embW1 = (const float*)d_in[4 + o];
    const float* embb1 = (const float*)d_in[5 + o];
    const float* embW2 = (const float*)d_in[6 + o];
    const float* embb2 = (const float*)d_in[7 + o];
    const float* msgW1 = (const float*)d_in[8 + o];
    const float* msgb1 = (const float*)d_in[9 + o];
    const float* msgW2 = (const float*)d_in[10 + o];
    const float* msgb2 = (const float*)d_in[11 + o];
    const float* updW1 = (const float*)d_in[12 + o];
    const float* updb1 = (const float*)d_in[13 + o];
    const float* updW2 = (const float*)d_in[14 + o];
    const float* updb2 = (const float*)d_in[15 + o];
    const float* hW1 = (const float*)d_in[16 + o];
    const float* hb1 = (const float*)d_in[17 + o];
    const float* hW2 = (const float*)d_in[18 + o];
    const float* hb2 = (const float*)d_in[19 + o];
    float* out = (float*)d_out;

    cudaFuncSetAttribute(upd_tc, cudaFuncAttributeMaxDynamicSharedMemorySize, DYNB_U);
    cudaFuncSetAttribute(embed_tc, cudaFuncAttributeMaxDynamicSharedMemorySize, DYNB_EM);
    cudaFuncSetAttribute(head_tc, cudaFuncAttributeMaxDynamicSharedMemorySize, DYNB_H);

    __half *xhp, *xh2p, *pdp, *psp, *agghp;
    float *headp;
    int *degip, *csrsp, *rowpp;
    uint4 *mW1f, *mW2f, *uW1f, *uW2f, *eW1f, *eW2f, *hW1f, *hW2f;
    cudaGetSymbolAddress((void**)&xhp, g_xh);
    cudaGetSymbolAddress((void**)&xh2p, g_xh2);
    cudaGetSymbolAddress((void**)&pdp, g_pd);
    cudaGetSymbolAddress((void**)&psp, g_ps);
    cudaGetSymbolAddress((void**)&agghp, g_aggh);
    cudaGetSymbolAddress((void**)&degip, g_degi);
    cudaGetSymbolAddress((void**)&headp, g_head);
    cudaGetSymbolAddress((void**)&csrsp, g_csrs);
    cudaGetSymbolAddress((void**)&rowpp, g_rowp);
    cudaGetSymbolAddress((void**)&mW1f, g_mW1f);
    cudaGetSymbolAddress((void**)&mW2f, g_mW2f);
    cudaGetSymbolAddress((void**)&uW1f, g_uW1f);
    cudaGetSymbolAddress((void**)&uW2f, g_uW2f);
    cudaGetSymbolAddress((void**)&eW1f, g_eW1f);
    cudaGetSymbolAddress((void**)&eW2f, g_eW2f);
    cudaGetSymbolAddress((void**)&hW1f, g_hW1f);
    cudaGetSymbolAddress((void**)&hW2f, g_hW2f);

    detect_kernel<<<1, 32>>>((const int*)eix);
    cudaMemsetAsync(degip, 0, NN * sizeof(int));
    idx_kernel<<<EE / 256, 256>>>(eix);
    scan_kernel<<<1, 1024>>>();
    fill_kernel<<<EE / 256, 256>>>();
    prep_fragk<<<dim3(LL, 16), 256>>>(msgW1, (__half*)mW1f, 256, 128, 128, 256 * 128, 32768);
    prep_fragk<<<dim3(LL, 16), 256>>>(updW1, (__half*)uW1f, 256, 128, 128, 256 * 128, 32768);
    prep_fragk<<<dim3(LL, 8), 256>>>(msgW2, (__half*)mW2f, 128, 128, 128, 128 * 128, 16384);
    prep_fragk<<<dim3(LL, 8), 256>>>(updW2, (__half*)uW2f, 128, 128, 128, 128 * 128, 16384);
    prep_fragk<<<dim3(1, 4), 256>>>(embW1, (__half*)eW1f, 60, 128, 128, 0, 0);
    prep_fragk<<<dim3(1, 8), 256>>>(embW2, (__half*)eW2f, 128, 128, 128, 0, 0);
    prep_fragk<<<dim3(1, 8), 256>>>(hW1, (__half*)hW1f, 128, 128, 128, 0, 0);
    prep_fragk<<<dim3(1, 8), 256>>>(hW2, (__half*)hW2f, 128, 30, 30, 0, 0);

    embed_tc<<<NN / 128, 256, DYNB_EM>>>(loc, vel, eW1f, eW2f, embb1, embb2, xhp,
                                         mW1f, msgb1, pdp, psp);

    __half* xa = xhp;
    __half* xb = xh2p;
    for (int i = 0; i < LL; i++) {
        agg_csr<<<NN * 32 / 256, 256>>>(pdp, psp, csrsp, rowpp, agghp);
        upd_tc<<<NN / 128, 256, DYNB_U>>>(
            xa, agghp,
            mW2f + (size_t)i * 2048, msgb2 + (size_t)i * HH, degip,
            uW1f + (size_t)i * 4096, uW2f + (size_t)i * 2048,
            updb1 + (size_t)i * HH, updb2 + (size_t)i * HH, xb,
            mW1f + (size_t)(i + 1 < LL ? i + 1 : 0) * 4096,
            msgb1 + (size_t)(i + 1 < LL ? i + 1 : 0) * HH, pdp, psp,
            i + 1 < LL ? 1 : 0);
        __half* t = xa; xa = xb; xb = t;
    }
    head_tc<<<NN / 128, 256, DYNB_H>>>(xa, hW1f, hW2f, hb1, hb2, headp);
    loss_kernel<<<(BB * 32 + 127) / 128, 128>>>(headp, loc, y, out);
    final_kernel<<<1, 256>>>(out);
}